// round 11
// baseline (speedup 1.0000x reference)
#include <cuda_runtime.h>
#include <math.h>
#include <stdint.h>

#define EN 300000
#define NN 50000
#define GN 1024
#define H  256
#define NCONV 4
#define PA 136      // A smem row stride: 136 mod 32 == 8 -> conflict-free frag loads
#define PB1 136     // B smem row stride (128-wide tiles)

// ---------------- scratch (device globals) ---------------------------------
static __device__ float g_bond[(size_t)EN * H];   // bond_attr [E,H] (edge order)
static __device__ float g_h1[(size_t)EN * H];     // out-MLP hidden1
static __device__ float g_h[NN * H];
static __device__ float g_aggr[NN * H];
static __device__ float g_tmp[NN * H];
static __device__ float g_temb[GN];
static __device__ float g_invstd[GN];
static __device__ float g_einv[EN];
// sort machinery
static __device__ int g_cnt[NN];      // zero-init; scan re-zeroes each call
static __device__ int g_rp[NN + 1];
static __device__ int g_woff[NN];
static __device__ int g_srcp[EN];
static __device__ int g_eid[EN];

// ---------------- helpers ---------------------------------------------------
__device__ __forceinline__ float totf(float x) {
    uint32_t u; asm("cvt.rna.tf32.f32 %0, %1;" : "=r"(u) : "f"(x));
    return __uint_as_float(u);
}

__device__ __forceinline__ void mma1(float acc[4],
                                     float a0, float a1, float a2, float a3,
                                     float b0, float b1) {
    asm volatile(
        "mma.sync.aligned.m16n8k8.row.col.f32.tf32.tf32.f32 "
        "{%0,%1,%2,%3}, {%4,%5,%6,%7}, {%8,%9}, {%0,%1,%2,%3};\n"
        : "+f"(acc[0]), "+f"(acc[1]), "+f"(acc[2]), "+f"(acc[3])
        : "r"(__float_as_uint(a0)), "r"(__float_as_uint(a1)),
          "r"(__float_as_uint(a2)), "r"(__float_as_uint(a3)),
          "r"(__float_as_uint(b0)), "r"(__float_as_uint(b1)));
}

// warp 64x64 via smem A + smem B (N-tile = 8, B 128-wide, 4 warps 2x2)
__device__ __forceinline__ void mma_k8w(float acc[4][8][4],
                                        const float* As, const float* Bs,
                                        int kk, int wy, int wx, int lane) {
    int g = lane >> 2, t4 = lane & 3;
    float a[4][4];
#pragma unroll
    for (int mt = 0; mt < 4; mt++) {
        int rm = wy * 64 + mt * 16 + g;
        a[mt][0] = As[(kk + t4) * PA + rm];
        a[mt][1] = As[(kk + t4) * PA + rm + 8];
        a[mt][2] = As[(kk + t4 + 4) * PA + rm];
        a[mt][3] = As[(kk + t4 + 4) * PA + rm + 8];
    }
#pragma unroll
    for (int nt = 0; nt < 8; nt++) {
        int cn = wx * 64 + nt * 8 + g;
        float b0 = Bs[(kk + t4) * PB1 + cn];
        float b1 = Bs[(kk + t4 + 4) * PB1 + cn];
#pragma unroll
        for (int mt = 0; mt < 4; mt++)
            mma1(acc[mt][nt], a[mt][0], a[mt][1], a[mt][2], a[mt][3], b0, b1);
    }
}

// B tile 16x128, 128 threads: thread owns COLUMN tid (conflict-free stores)
__device__ __forceinline__ void load_w128(float v[16], const float* __restrict__ W,
                                          int ldw, int k0, int n0, int tid) {
    const float* p = &W[(size_t)k0 * ldw + n0 + tid];
#pragma unroll
    for (int k = 0; k < 16; k++) v[k] = p[(size_t)k * ldw];
}
__device__ __forceinline__ void store_w128(float* Bs, const float v[16], int tid) {
#pragma unroll
    for (int k = 0; k < 16; k++) Bs[k * PB1 + tid] = totf(v[k]);
}
// A: 128 threads, thread owns row tid, 16 k's (conflict-free stores)
__device__ __forceinline__ void store_a16(float* As, int r, const float v[16]) {
#pragma unroll
    for (int k = 0; k < 16; k++) As[k * PA + r] = totf(v[k]);
}

// ---------------- temb (comb fused) -----------------------------------------
__global__ void __launch_bounds__(128)
temb_fused(const float* __restrict__ t, const float* __restrict__ fw,
           const float* __restrict__ tW, const float* __restrict__ tb,
           const float* __restrict__ d1W, const float* __restrict__ d1b) {
    __shared__ float d1S[H], combS[H + 1], red[128];
    int tid = threadIdx.x, lane = tid & 31, warp = tid >> 5;
    d1S[tid] = d1W[tid]; d1S[tid + 128] = d1W[tid + 128];
    __syncthreads();
    for (int row = warp; row < H + 1; row += 4) {
        const float* p = (row < H) ? &tW[(size_t)row * H] : tb;
        float s = 0.f;
        for (int k = lane; k < H; k += 32) s += p[k] * d1S[k];
#pragma unroll
        for (int o = 16; o; o >>= 1) s += __shfl_down_sync(0xffffffffu, s, o);
        if (lane == 0) combS[row] = (row == H) ? s + d1b[0] : s;
    }
    __syncthreads();
    int g = blockIdx.x;
    float tt = t[g];
    float xp = tt * fw[tid] * 6.283185307179586f;
    red[tid] = sinf(xp) * combS[tid] + cosf(xp) * combS[128 + tid];
    __syncthreads();
    for (int s = 64; s > 0; s >>= 1) {
        if (tid < s) red[tid] += red[tid + s];
        __syncthreads();
    }
    if (tid == 0) {
        g_temb[g] = red[0] + combS[H];
        const float LS = 3.2188758248682006f;   // ln(25)
        float var = (expf(2.f * tt * LS) - 1.f) / (2.f * LS);
        g_invstd[g] = rsqrtf(var);
    }
}

// ---------------- sort machinery ---------------------------------------------
__global__ void __launch_bounds__(256) hist(const int* __restrict__ dst) {
    int e = blockIdx.x * blockDim.x + threadIdx.x;
    if (e < EN) atomicAdd(&g_cnt[dst[e]], 1);
}

__global__ void __launch_bounds__(1024) scan_kernel() {
    __shared__ int part[1024];
    const int CH = 49;
    int t = threadIdx.x;
    int beg = t * CH, end = min(beg + CH, NN);
    int s = 0;
    for (int i = beg; i < end; i++) s += g_cnt[i];
    part[t] = s;
    __syncthreads();
    for (int off = 1; off < 1024; off <<= 1) {
        int v = (t >= off) ? part[t - off] : 0;
        __syncthreads();
        part[t] += v;
        __syncthreads();
    }
    int run = (t == 0) ? 0 : part[t - 1];
    for (int i = beg; i < end; i++) {
        g_rp[i] = run; g_woff[i] = run; run += g_cnt[i];
        g_cnt[i] = 0;
    }
    if (t == 1023) g_rp[NN] = part[1023];
}

__global__ void __launch_bounds__(256) place(const int* __restrict__ src,
                                             const int* __restrict__ dst) {
    int e = blockIdx.x * blockDim.x + threadIdx.x;
    if (e >= EN) return;
    int p = atomicAdd(&g_woff[dst[e]], 1);
    g_srcp[p] = src[e];
    g_eid[p] = e;
}

__global__ void __launch_bounds__(256) init_h(const int* __restrict__ nt,
                                              const float* __restrict__ atom_emb) {
    int idx = blockIdx.x * blockDim.x + threadIdx.x;
    if (idx >= NN * 64) return;
    int n = idx >> 6, q = idx & 63;
    ((float4*)g_h)[idx] = ((const float4*)atom_emb)[nt[n] * 64 + q];
}

// ---------------- gather: aggr[n] = sum relu(h[src]+bond) -------------------
__global__ void __launch_bounds__(256) gather() {
    int warp = threadIdx.x >> 5, lane = threadIdx.x & 31;
    int n = blockIdx.x * 8 + warp;
    if (n >= NN) return;
    int q = lane * 8;
    float4 a0 = make_float4(0.f, 0.f, 0.f, 0.f), a1 = a0;
    int beg = g_rp[n], end = g_rp[n + 1];
    for (int p = beg; p < end; p++) {
        int s = g_srcp[p];
        int e = g_eid[p];
        const float4* hp = (const float4*)&g_h[s * H + q];
        const float4* bp = (const float4*)&g_bond[(size_t)e * H + q];
        float4 h0 = hp[0], h1v = hp[1], b0 = bp[0], b1v = bp[1];
        a0.x += fmaxf(h0.x + b0.x, 0.f);  a0.y += fmaxf(h0.y + b0.y, 0.f);
        a0.z += fmaxf(h0.z + b0.z, 0.f);  a0.w += fmaxf(h0.w + b0.w, 0.f);
        a1.x += fmaxf(h1v.x + b1v.x, 0.f); a1.y += fmaxf(h1v.y + b1v.y, 0.f);
        a1.z += fmaxf(h1v.z + b1v.z, 0.f); a1.w += fmaxf(h1v.w + b1v.w, 0.f);
    }
    float4* ap = (float4*)&g_aggr[n * H + q];
    ap[0] = a0; ap[1] = a1;
}

// ---------------- edge_bond: 128 thr, 4 warps, grid(2, EB) ------------------
#define ASZ (16 * PA)
#define BSZ1 (16 * PB1)
#define EB_SMEM ((2 * BSZ1 + 128 + 128 + 128 + 2 * H) * 4)

__global__ void __launch_bounds__(128, 2)
edge_bond(const float* __restrict__ elen, const int* __restrict__ src,
          const int* __restrict__ batch, const int* __restrict__ etype,
          const float* __restrict__ W1, const float* __restrict__ b1,
          const float* __restrict__ W2, const float* __restrict__ b2,
          const float* __restrict__ bond_emb) {
    extern __shared__ float sm[];
    float* Bs = sm;                       // 2*BSZ1
    float* xS = Bs + 2 * BSZ1;            // 128
    float* tS = xS + 128;                 // 128
    int*   eS = (int*)(tS + 128);         // 128
    float* w1S = (float*)(eS + 128);      // 256
    float* b1S = w1S + H;                 // 256

    int tid = threadIdx.x, lane = tid & 31, warp = tid >> 5;
    int wy = warp >> 1, wx = warp & 1;
    int g = lane >> 2, t4 = lane & 3;
    int m0 = blockIdx.y * 128, n0 = blockIdx.x * 128;

    {
        int e = m0 + tid;
        float x = 0.f, tb = 0.f; int et = 0;
        if (e < EN) {
            x = elen[e];
            int gph = batch[src[e]];
            tb = g_temb[gph];
            if (n0 == 0) g_einv[e] = g_invstd[gph];
            et = etype[e];
        }
        xS[tid] = x; tS[tid] = tb; eS[tid] = et;
    }
    w1S[tid] = W1[tid];         w1S[tid + 128] = W1[tid + 128];
    b1S[tid] = b1[tid];         b1S[tid + 128] = b1[tid + 128];
    __syncthreads();

    // preload this thread's 8 A-rows' x values
    float xr[4][2];
#pragma unroll
    for (int mt = 0; mt < 4; mt++) {
        xr[mt][0] = xS[wy * 64 + mt * 16 + g];
        xr[mt][1] = xS[wy * 64 + mt * 16 + g + 8];
    }

    float breg[16];
    load_w128(breg, W2, H, 0, n0, tid);
    store_w128(Bs, breg, tid);
    __syncthreads();

    float acc[4][8][4] = {};
    for (int s = 0; s < 16; s++) {
        int cur = s & 1, nxt = cur ^ 1;
        if (s < 15) load_w128(breg, W2, H, (s + 1) * 16, n0, tid);
        const float* B = Bs + cur * BSZ1;
#pragma unroll
        for (int kh = 0; kh < 16; kh += 8) {
            int kA = s * 16 + kh;
            float w0 = w1S[kA + t4], w4 = w1S[kA + t4 + 4];
            float c0 = b1S[kA + t4], c4 = b1S[kA + t4 + 4];
            float a[4][4];
#pragma unroll
            for (int mt = 0; mt < 4; mt++) {
                a[mt][0] = totf(fmaxf(fmaf(xr[mt][0], w0, c0), 0.f));
                a[mt][1] = totf(fmaxf(fmaf(xr[mt][1], w0, c0), 0.f));
                a[mt][2] = totf(fmaxf(fmaf(xr[mt][0], w4, c4), 0.f));
                a[mt][3] = totf(fmaxf(fmaf(xr[mt][1], w4, c4), 0.f));
            }
#pragma unroll
            for (int nt = 0; nt < 8; nt++) {
                int cn = wx * 64 + nt * 8 + g;
                float b0 = B[(kh + t4) * PB1 + cn];
                float b1v = B[(kh + t4 + 4) * PB1 + cn];
#pragma unroll
                for (int mt = 0; mt < 4; mt++)
                    mma1(acc[mt][nt], a[mt][0], a[mt][1], a[mt][2], a[mt][3], b0, b1v);
            }
        }
        if (s < 15) {
            store_w128(Bs + nxt * BSZ1, breg, tid);
            __syncthreads();
        }
    }

#pragma unroll
    for (int mt = 0; mt < 4; mt++)
#pragma unroll
        for (int half = 0; half < 2; half++) {
            int rl = wy * 64 + mt * 16 + g + half * 8;
            int row = m0 + rl;
            if (row >= EN) continue;
            float tb = tS[rl];
            const float* bep = &bond_emb[eS[rl] * H];
            size_t obase = (size_t)row * H;
#pragma unroll
            for (int nt = 0; nt < 8; nt++) {
                int col = n0 + wx * 64 + nt * 8 + 2 * t4;
                float v0 = (acc[mt][nt][half * 2 + 0] + b2[col] + tb) * bep[col];
                float v1 = (acc[mt][nt][half * 2 + 1] + b2[col + 1] + tb) * bep[col + 1];
                *(float2*)&g_bond[obase + col] = make_float2(v0, v1);
            }
        }
}

// ---------------- GIN GEMMs: 128 thr, grid(2, NB) ---------------------------
#define GIN_SMEM ((2 * ASZ + 2 * BSZ1) * 4)
template <int MODE>
__global__ void __launch_bounds__(128, 2)
gin_mma(const float* __restrict__ W, const float* __restrict__ bias, int reluOut) {
    extern __shared__ float sm[];
    float* As = sm;
    float* Bs = sm + 2 * ASZ;
    int tid = threadIdx.x, lane = tid & 31, warp = tid >> 5;
    int wy = warp >> 1, wx = warp & 1;
    int m0 = blockIdx.y * 128, n0 = blockIdx.x * 128;
    int arow = m0 + tid;
    bool valid = (arow < NN);
    const float* A1 = (MODE == 0) ? g_h : g_tmp;

    float areg[16], breg[16];
    auto loadA = [&](int k0) {
        if (valid) {
            const float* p = &A1[arow * H + k0];
#pragma unroll
            for (int j = 0; j < 4; j++) {
                float4 v = *(const float4*)(p + 4 * j);
                areg[4 * j] = v.x; areg[4 * j + 1] = v.y;
                areg[4 * j + 2] = v.z; areg[4 * j + 3] = v.w;
            }
            if (MODE == 0) {
                const float* q = &g_aggr[arow * H + k0];
#pragma unroll
                for (int j = 0; j < 4; j++) {
                    float4 v = *(const float4*)(q + 4 * j);
                    areg[4 * j] += v.x; areg[4 * j + 1] += v.y;
                    areg[4 * j + 2] += v.z; areg[4 * j + 3] += v.w;
                }
            }
        } else {
#pragma unroll
            for (int i = 0; i < 16; i++) areg[i] = 0.f;
        }
    };

    loadA(0);
    load_w128(breg, W, H, 0, n0, tid);
    store_a16(As, tid, areg);
    store_w128(Bs, breg, tid);
    __syncthreads();

    float acc[4][8][4] = {};
    for (int s = 0; s < 16; s++) {
        int cur = s & 1, nxt = cur ^ 1;
        if (s < 15) { loadA((s + 1) * 16); load_w128(breg, W, H, (s + 1) * 16, n0, tid); }
        mma_k8w(acc, As + cur * ASZ, Bs + cur * BSZ1, 0, wy, wx, lane);
        mma_k8w(acc, As + cur * ASZ, Bs + cur * BSZ1, 8, wy, wx, lane);
        if (s < 15) {
            store_a16(As + nxt * ASZ, tid, areg);
            store_w128(Bs + nxt * BSZ1, breg, tid);
            __syncthreads();
        }
    }

    int g = lane >> 2, t4 = lane & 3;
#pragma unroll
    for (int mt = 0; mt < 4; mt++)
#pragma unroll
        for (int half = 0; half < 2; half++) {
            int row = m0 + wy * 64 + mt * 16 + g + half * 8;
            if (row >= NN) continue;
#pragma unroll
            for (int nt = 0; nt < 8; nt++) {
                int col = n0 + wx * 64 + nt * 8 + 2 * t4;
                float v0 = acc[mt][nt][half * 2 + 0] + bias[col];
                float v1 = acc[mt][nt][half * 2 + 1] + bias[col + 1];
                if (reluOut) { v0 = fmaxf(v0, 0.f); v1 = fmaxf(v1, 0.f); }
                if (MODE == 0) {
                    *(float2*)&g_tmp[row * H + col] = make_float2(v0, v1);
                } else {
                    float2 rh = *(const float2*)&g_h[row * H + col];
                    *(float2*)&g_h[row * H + col] = make_float2(v0 + rh.x, v1 + rh.y);
                }
            }
        }
}

// ---------------- out1: K=512, 128 thr, grid(2, EB) -------------------------
#define OUT1_SMEM ((2 * ASZ + 2 * BSZ1 + 256) * 4)
__global__ void __launch_bounds__(128, 2)
out1(const int* __restrict__ src, const int* __restrict__ dst,
     const float* __restrict__ W1, const float* __restrict__ b1) {
    extern __shared__ float sm[];
    float* As = sm;
    float* Bs = sm + 2 * ASZ;
    int* srcS = (int*)(Bs + 2 * BSZ1);   // 128
    int* dstS = srcS + 128;              // 128
    int tid = threadIdx.x, lane = tid & 31, warp = tid >> 5;
    int wy = warp >> 1, wx = warp & 1;
    int m0 = blockIdx.y * 128, n0 = blockIdx.x * 128;

    {
        int e = m0 + tid;
        int s = 0, d = 0;
        if (e < EN) { s = src[e]; d = dst[e]; }
        srcS[tid] = s; dstS[tid] = d;
    }
    __syncthreads();

    int e = m0 + tid;
    bool valid = (e < EN);
    float areg[16], breg[16];

    auto loadA = [&](int k0) {
        if (k0 < 256) {
            const float* hs = &g_h[srcS[tid] * H + k0];
            const float* hd = &g_h[dstS[tid] * H + k0];
#pragma unroll
            for (int j = 0; j < 4; j++) {
                float4 a = *(const float4*)(hs + 4 * j);
                float4 c = *(const float4*)(hd + 4 * j);
                areg[4 * j] = a.x * c.x; areg[4 * j + 1] = a.y * c.y;
                areg[4 * j + 2] = a.z * c.z; areg[4 * j + 3] = a.w * c.w;
            }
        } else if (valid) {
            const float* bp = &g_bond[(size_t)e * H + (k0 - 256)];
#pragma unroll
            for (int j = 0; j < 4; j++) {
                float4 v = *(const float4*)(bp + 4 * j);
                areg[4 * j] = v.x; areg[4 * j + 1] = v.y;
                areg[4 * j + 2] = v.z; areg[4 * j + 3] = v.w;
            }
        } else {
#pragma unroll
            for (int i = 0; i < 16; i++) areg[i] = 0.f;
        }
    };

    loadA(0);
    load_w128(breg, W1, H, 0, n0, tid);
    store_a16(As, tid, areg);
    store_w128(Bs, breg, tid);
    __syncthreads();

    float acc[4][8][4] = {};
    for (int s = 0; s < 32; s++) {
        int cur = s & 1, nxt = cur ^ 1;
        if (s < 31) { loadA((s + 1) * 16); load_w128(breg, W1, H, (s + 1) * 16, n0, tid); }
        mma_k8w(acc, As + cur * ASZ, Bs + cur * BSZ1, 0, wy, wx, lane);
        mma_k8w(acc, As + cur * ASZ, Bs + cur * BSZ1, 8, wy, wx, lane);
        if (s < 31) {
            store_a16(As + nxt * ASZ, tid, areg);
            store_w128(Bs + nxt * BSZ1, breg, tid);
            __syncthreads();
        }
    }

    int g = lane >> 2, t4 = lane & 3;
#pragma unroll
    for (int mt = 0; mt < 4; mt++)
#pragma unroll
        for (int half = 0; half < 2; half++) {
            int row = m0 + wy * 64 + mt * 16 + g + half * 8;
            if (row >= EN) continue;
#pragma unroll
            for (int nt = 0; nt < 8; nt++) {
                int col = n0 + wx * 64 + nt * 8 + 2 * t4;
                float v0 = fmaxf(acc[mt][nt][half * 2 + 0] + b1[col], 0.f);
                float v1 = fmaxf(acc[mt][nt][half * 2 + 1] + b1[col + 1], 0.f);
                *(float2*)&g_h1[(size_t)row * H + col] = make_float2(v0, v1);
            }
        }
}

// ---------------- out23 fused: 128x128 tile (static smem, unchanged) --------
__global__ void __launch_bounds__(128, 2)
out23(const float* __restrict__ W2, const float* __restrict__ b2,
      const float* __restrict__ W3, const float* __restrict__ b3,
      float* __restrict__ out) {
    __shared__ float As[2 * ASZ], Bs[2 * BSZ1];
    __shared__ float red[128 * 8];
    __shared__ float b2S[128], w3S[128];
    int tid = threadIdx.x, lane = tid & 31, warp = tid >> 5;
    int wy = warp >> 1, wx = warp & 1;
    int m0 = blockIdx.x * 128;

    b2S[tid] = b2[tid]; w3S[tid] = W3[tid];

    int e = m0 + tid;
    bool valid = (e < EN);
    float areg[16], breg[16];
    auto loadA = [&](int k0) {
        if (valid) {
            const float* p = &g_h1[(size_t)e * H + k0];
#pragma unroll
            for (int j = 0; j < 4; j++) {
                float4 v = *(const float4*)(p + 4 * j);
                areg[4 * j] = v.x; areg[4 * j + 1] = v.y;
                areg[4 * j + 2] = v.z; areg[4 * j + 3] = v.w;
            }
        } else {
#pragma unroll
            for (int i = 0; i < 16; i++) areg[i] = 0.f;
        }
    };

    loadA(0);
    load_w128(breg, W2, 128, 0, 0, tid);
    store_a16(As, tid, areg);
    store_w128(Bs, breg, tid);
    __syncthreads();

    float acc[4][8][4] = {};
    for (int s = 0; s < 16; s++) {
        int cur = s & 1, nxt = cur ^ 1;
        if (s < 15) { loadA((s + 1) * 16); load_w128(breg, W2, 128, (s + 1) * 16, 0, tid); }
        mma_k8w(acc, As + cur * ASZ, Bs + cur * BSZ1, 0, wy, wx, lane);
        mma_k8w(acc, As + cur * ASZ, Bs + cur * BSZ1, 8, wy, wx, lane);
        if (s < 15) {
            store_a16(As + nxt * ASZ, tid, areg);
            store_w128(Bs + nxt * BSZ1, breg, tid);
            __syncthreads();
        }
    }

    int g = lane >> 2, t4 = lane & 3;
#pragma unroll
    for (int mt = 0; mt < 4; mt++)
#pragma unroll
        for (int half = 0; half < 2; half++) {
            int rl = wy * 64 + mt * 16 + g + half * 8;
            float partial = 0.f;
#pragma unroll
            for (int nt = 0; nt < 8; nt++) {
                int col = wx * 64 + nt * 8 + 2 * t4;
                float h0 = fmaxf(acc[mt][nt][half * 2 + 0] + b2S[col], 0.f);
                float h1 = fmaxf(acc[mt][nt][half * 2 + 1] + b2S[col + 1], 0.f);
                partial += h0 * w3S[col] + h1 * w3S[col + 1];
            }
            red[rl * 8 + wx * 4 + t4] = partial;
        }
    __syncthreads();

    if (valid) {
        float s = 0.f;
#pragma unroll
        for (int i = 0; i < 8; i++) s += red[tid * 8 + i];
        out[e] = (s + b3[0]) * g_einv[e];
    }
}

// ---------------- launch ----------------------------------------------------
extern "C" void kernel_launch(void* const* d_in, const int* in_sizes, int n_in,
                              void* d_out, int out_size) {
    const int*   node_type = (const int*)d_in[0];
    const int*   edge_type = (const int*)d_in[1];
    const int*   edge_index = (const int*)d_in[2];
    const int*   batch = (const int*)d_in[3];
    const float* elen = (const float*)d_in[4];
    const float* t = (const float*)d_in[5];
    const float* atom_emb = (const float*)d_in[6];
    const float* bond_emb = (const float*)d_in[7];
    const float* in_W1 = (const float*)d_in[8];
    const float* in_b1 = (const float*)d_in[9];
    const float* in_W2 = (const float*)d_in[10];
    const float* in_b2 = (const float*)d_in[11];
    const float* fourier_W = (const float*)d_in[12];
    const float* temb_W = (const float*)d_in[13];
    const float* temb_b = (const float*)d_in[14];
    const float* d1W = (const float*)d_in[15];
    const float* d1b = (const float*)d_in[16];
    const float* gin_W1 = (const float*)d_in[17];
    const float* gin_b1 = (const float*)d_in[18];
    const float* gin_W2 = (const float*)d_in[19];
    const float* gin_b2 = (const float*)d_in[20];
    const float* out_W1 = (const float*)d_in[21];
    const float* out_b1 = (const float*)d_in[22];
    const float* out_W2 = (const float*)d_in[23];
    const float* out_b2 = (const float*)d_in[24];
    const float* out_W3 = (const float*)d_in[25];
    const float* out_b3 = (const float*)d_in[26];
    const int* src = edge_index;
    const int* dst = edge_index + EN;
    float* out = (float*)d_out;

    const int EB = (EN + 127) / 128;   // 2344
    const int NB = (NN + 127) / 128;   // 391

    static int attr_done = 0;
    if (!attr_done) {
        cudaFuncSetAttribute(edge_bond, cudaFuncAttributeMaxDynamicSharedMemorySize, EB_SMEM);
        cudaFuncSetAttribute(gin_mma<0>, cudaFuncAttributeMaxDynamicSharedMemorySize, GIN_SMEM);
        cudaFuncSetAttribute(gin_mma<1>, cudaFuncAttributeMaxDynamicSharedMemorySize, GIN_SMEM);
        cudaFuncSetAttribute(out1, cudaFuncAttributeMaxDynamicSharedMemorySize, OUT1_SMEM);
        attr_done = 1;
    }

    // launch order chosen so ncu (launch index 3) profiles edge_bond
    temb_fused<<<GN, 128>>>(t, fourier_W, temb_W, temb_b, d1W, d1b);      // 0
    hist<<<(EN + 255) / 256, 256>>>(dst);                                 // 1
    scan_kernel<<<1, 1024>>>();                                           // 2
    edge_bond<<<dim3(2, EB), 128, EB_SMEM>>>(elen, src, batch, edge_type, // 3
                                             in_W1, in_b1, in_W2, in_b2, bond_emb);
    place<<<(EN + 255) / 256, 256>>>(src, dst);                           // 4
    init_h<<<(NN * 64 + 255) / 256, 256>>>(node_type, atom_emb);          // 5

    for (int c = 0; c < NCONV; c++) {
        gather<<<(NN + 7) / 8, 256>>>();
        gin_mma<0><<<dim3(2, NB), 128, GIN_SMEM>>>(gin_W1 + c * H * H, gin_b1 + c * H, 1);
        gin_mma<1><<<dim3(2, NB), 128, GIN_SMEM>>>(gin_W2 + c * H * H, gin_b2 + c * H,
                                                   (c < NCONV - 1) ? 1 : 0);
    }

    out1<<<dim3(2, EB), 128, OUT1_SMEM>>>(src, dst, out_W1, out_b1);
    out23<<<EB, 128>>>(out_W2, out_b2, out_W3, out_b3, out);
}

// round 12
// speedup vs baseline: 1.0373x; 1.0373x over previous
#include <cuda_runtime.h>
#include <math.h>
#include <stdint.h>

#define EN 300000
#define NN 50000
#define GN 1024
#define H  256
#define NCONV 4
#define PA 136      // A smem row stride: 136 mod 32 == 8 -> conflict-free frag loads
#define PB 264      // B smem row stride (256-wide tiles)
#define PB1 136     // B smem row stride (128-wide tiles)

// ---------------- scratch (device globals) ---------------------------------
static __device__ float g_bond[(size_t)EN * H];   // bond_attr [E,H] (edge order)
static __device__ float g_h1[(size_t)EN * H];     // out-MLP hidden1
static __device__ float g_h[NN * H];
static __device__ float g_aggr[NN * H];
static __device__ float g_tmp[NN * H];
static __device__ float g_temb[GN];
static __device__ float g_invstd[GN];
static __device__ float g_einv[EN];
// sort machinery
static __device__ int g_cnt[NN];      // zero-init; scan re-zeroes each call
static __device__ int g_rp[NN + 1];
static __device__ int g_woff[NN];
static __device__ int g_srcp[EN];
static __device__ int g_eid[EN];

// ---------------- helpers ---------------------------------------------------
__device__ __forceinline__ float totf(float x) {
    uint32_t u; asm("cvt.rna.tf32.f32 %0, %1;" : "=r"(u) : "f"(x));
    return __uint_as_float(u);
}

__device__ __forceinline__ void mma1(float acc[4],
                                     float a0, float a1, float a2, float a3,
                                     float b0, float b1) {
    asm volatile(
        "mma.sync.aligned.m16n8k8.row.col.f32.tf32.tf32.f32 "
        "{%0,%1,%2,%3}, {%4,%5,%6,%7}, {%8,%9}, {%0,%1,%2,%3};\n"
        : "+f"(acc[0]), "+f"(acc[1]), "+f"(acc[2]), "+f"(acc[3])
        : "r"(__float_as_uint(a0)), "r"(__float_as_uint(a1)),
          "r"(__float_as_uint(a2)), "r"(__float_as_uint(a3)),
          "r"(__float_as_uint(b0)), "r"(__float_as_uint(b1)));
}

// warp 64x64 via smem A + smem B (N-tile = 8); BS = B row stride
template <int BS>
__device__ __forceinline__ void mma_k8w(float acc[4][8][4],
                                        const float* As, const float* Bs,
                                        int kk, int wy, int wx, int lane) {
    int g = lane >> 2, t4 = lane & 3;
    float a[4][4];
#pragma unroll
    for (int mt = 0; mt < 4; mt++) {
        int rm = wy * 64 + mt * 16 + g;
        a[mt][0] = As[(kk + t4) * PA + rm];
        a[mt][1] = As[(kk + t4) * PA + rm + 8];
        a[mt][2] = As[(kk + t4 + 4) * PA + rm];
        a[mt][3] = As[(kk + t4 + 4) * PA + rm + 8];
    }
#pragma unroll
    for (int nt = 0; nt < 8; nt++) {
        int cn = wx * 64 + nt * 8 + g;
        float b0 = Bs[(kk + t4) * BS + cn];
        float b1 = Bs[(kk + t4 + 4) * BS + cn];
#pragma unroll
        for (int mt = 0; mt < 4; mt++)
            mma1(acc[mt][nt], a[mt][0], a[mt][1], a[mt][2], a[mt][3], b0, b1);
    }
}

// B tile 16x256, 256 threads: thread owns COLUMN tid (conflict-free stores)
__device__ __forceinline__ void load_w256(float v[16], const float* __restrict__ W,
                                          int ldw, int k0, int tid) {
    const float* p = &W[(size_t)k0 * ldw + tid];
#pragma unroll
    for (int k = 0; k < 16; k++) v[k] = p[(size_t)k * ldw];
}
__device__ __forceinline__ void store_w256(float* Bs, const float v[16], int tid) {
#pragma unroll
    for (int k = 0; k < 16; k++) Bs[k * PB + tid] = totf(v[k]);
}
// B tile 16x128, 128 threads: thread owns column tid
__device__ __forceinline__ void load_w128(float v[16], const float* __restrict__ W,
                                          int ldw, int k0, int n0, int tid) {
    const float* p = &W[(size_t)k0 * ldw + n0 + tid];
#pragma unroll
    for (int k = 0; k < 16; k++) v[k] = p[(size_t)k * ldw];
}
__device__ __forceinline__ void store_w128(float* Bs, const float v[16], int tid) {
#pragma unroll
    for (int k = 0; k < 16; k++) Bs[k * PB1 + tid] = totf(v[k]);
}
// A: 256 threads, r = tid&127, kh = (tid>>7)*8 (conflict-free stores)
__device__ __forceinline__ void store_a8(float* As, int kh, int r, const float v[8]) {
#pragma unroll
    for (int i = 0; i < 8; i++) As[(kh + i) * PA + r] = totf(v[i]);
}
// A: 128 threads, thread owns row tid, 16 k's (conflict-free stores)
__device__ __forceinline__ void store_a16(float* As, int r, const float v[16]) {
#pragma unroll
    for (int k = 0; k < 16; k++) As[k * PA + r] = totf(v[k]);
}

// ---------------- temb (comb fused) -----------------------------------------
__global__ void __launch_bounds__(128)
temb_fused(const float* __restrict__ t, const float* __restrict__ fw,
           const float* __restrict__ tW, const float* __restrict__ tb,
           const float* __restrict__ d1W, const float* __restrict__ d1b) {
    __shared__ float d1S[H], combS[H + 1], red[128];
    int tid = threadIdx.x, lane = tid & 31, warp = tid >> 5;
    d1S[tid] = d1W[tid]; d1S[tid + 128] = d1W[tid + 128];
    __syncthreads();
    for (int row = warp; row < H + 1; row += 4) {
        const float* p = (row < H) ? &tW[(size_t)row * H] : tb;
        float s = 0.f;
        for (int k = lane; k < H; k += 32) s += p[k] * d1S[k];
#pragma unroll
        for (int o = 16; o; o >>= 1) s += __shfl_down_sync(0xffffffffu, s, o);
        if (lane == 0) combS[row] = (row == H) ? s + d1b[0] : s;
    }
    __syncthreads();
    int g = blockIdx.x;
    float tt = t[g];
    float xp = tt * fw[tid] * 6.283185307179586f;
    red[tid] = sinf(xp) * combS[tid] + cosf(xp) * combS[128 + tid];
    __syncthreads();
    for (int s = 64; s > 0; s >>= 1) {
        if (tid < s) red[tid] += red[tid + s];
        __syncthreads();
    }
    if (tid == 0) {
        g_temb[g] = red[0] + combS[H];
        const float LS = 3.2188758248682006f;   // ln(25)
        float var = (expf(2.f * tt * LS) - 1.f) / (2.f * LS);
        g_invstd[g] = rsqrtf(var);
    }
}

// ---------------- sort machinery ---------------------------------------------
__global__ void __launch_bounds__(256) hist(const int* __restrict__ dst) {
    int e = blockIdx.x * blockDim.x + threadIdx.x;
    if (e < EN) atomicAdd(&g_cnt[dst[e]], 1);
}

__global__ void __launch_bounds__(1024) scan_kernel() {
    __shared__ int part[1024];
    const int CH = 49;
    int t = threadIdx.x;
    int beg = t * CH, end = min(beg + CH, NN);
    int s = 0;
    for (int i = beg; i < end; i++) s += g_cnt[i];
    part[t] = s;
    __syncthreads();
    for (int off = 1; off < 1024; off <<= 1) {
        int v = (t >= off) ? part[t - off] : 0;
        __syncthreads();
        part[t] += v;
        __syncthreads();
    }
    int run = (t == 0) ? 0 : part[t - 1];
    for (int i = beg; i < end; i++) {
        g_rp[i] = run; g_woff[i] = run; run += g_cnt[i];
        g_cnt[i] = 0;
    }
    if (t == 1023) g_rp[NN] = part[1023];
}

__global__ void __launch_bounds__(256) place(const int* __restrict__ src,
                                             const int* __restrict__ dst) {
    int e = blockIdx.x * blockDim.x + threadIdx.x;
    if (e >= EN) return;
    int p = atomicAdd(&g_woff[dst[e]], 1);
    g_srcp[p] = src[e];
    g_eid[p] = e;
}

__global__ void __launch_bounds__(256) init_h(const int* __restrict__ nt,
                                              const float* __restrict__ atom_emb) {
    int idx = blockIdx.x * blockDim.x + threadIdx.x;
    if (idx >= NN * 64) return;
    int n = idx >> 6, q = idx & 63;
    ((float4*)g_h)[idx] = ((const float4*)atom_emb)[nt[n] * 64 + q];
}

// ---------------- gather: aggr[n] = sum relu(h[src]+bond) -------------------
__global__ void __launch_bounds__(256) gather() {
    int warp = threadIdx.x >> 5, lane = threadIdx.x & 31;
    int n = blockIdx.x * 8 + warp;
    if (n >= NN) return;
    int q = lane * 8;
    float4 a0 = make_float4(0.f, 0.f, 0.f, 0.f), a1 = a0;
    int beg = g_rp[n], end = g_rp[n + 1];
    for (int p = beg; p < end; p++) {
        int s = g_srcp[p];
        int e = g_eid[p];
        const float4* hp = (const float4*)&g_h[s * H + q];
        const float4* bp = (const float4*)&g_bond[(size_t)e * H + q];
        float4 h0 = hp[0], h1v = hp[1], b0 = bp[0], b1v = bp[1];
        a0.x += fmaxf(h0.x + b0.x, 0.f);  a0.y += fmaxf(h0.y + b0.y, 0.f);
        a0.z += fmaxf(h0.z + b0.z, 0.f);  a0.w += fmaxf(h0.w + b0.w, 0.f);
        a1.x += fmaxf(h1v.x + b1v.x, 0.f); a1.y += fmaxf(h1v.y + b1v.y, 0.f);
        a1.z += fmaxf(h1v.z + b1v.z, 0.f); a1.w += fmaxf(h1v.w + b1v.w, 0.f);
    }
    float4* ap = (float4*)&g_aggr[n * H + q];
    ap[0] = a0; ap[1] = a1;
}

// ---------------- edge_bond: 128 thr, 4 warps, grid(2, EB) ------------------
#define ASZ (16 * PA)
#define BSZ (16 * PB)
#define BSZ1 (16 * PB1)
#define EB_SMEM ((2 * BSZ1 + 128 + 128 + 128 + 2 * H) * 4)

__global__ void __launch_bounds__(128, 2)
edge_bond(const float* __restrict__ elen, const int* __restrict__ src,
          const int* __restrict__ batch, const int* __restrict__ etype,
          const float* __restrict__ W1, const float* __restrict__ b1,
          const float* __restrict__ W2, const float* __restrict__ b2,
          const float* __restrict__ bond_emb) {
    extern __shared__ float sm[];
    float* Bs = sm;                       // 2*BSZ1
    float* xS = Bs + 2 * BSZ1;            // 128
    float* tS = xS + 128;                 // 128
    int*   eS = (int*)(tS + 128);         // 128
    float* w1S = (float*)(eS + 128);      // 256
    float* b1S = w1S + H;                 // 256

    int tid = threadIdx.x, lane = tid & 31, warp = tid >> 5;
    int wy = warp >> 1, wx = warp & 1;
    int g = lane >> 2, t4 = lane & 3;
    int m0 = blockIdx.y * 128, n0 = blockIdx.x * 128;

    {
        int e = m0 + tid;
        float x = 0.f, tb = 0.f; int et = 0;
        if (e < EN) {
            x = elen[e];
            int gph = batch[src[e]];
            tb = g_temb[gph];
            if (n0 == 0) g_einv[e] = g_invstd[gph];
            et = etype[e];
        }
        xS[tid] = x; tS[tid] = tb; eS[tid] = et;
    }
    w1S[tid] = W1[tid];         w1S[tid + 128] = W1[tid + 128];
    b1S[tid] = b1[tid];         b1S[tid + 128] = b1[tid + 128];
    __syncthreads();

    // preload this thread's 8 A-rows' x values
    float xr[4][2];
#pragma unroll
    for (int mt = 0; mt < 4; mt++) {
        xr[mt][0] = xS[wy * 64 + mt * 16 + g];
        xr[mt][1] = xS[wy * 64 + mt * 16 + g + 8];
    }

    float breg[16];
    load_w128(breg, W2, H, 0, n0, tid);
    store_w128(Bs, breg, tid);
    __syncthreads();

    float acc[4][8][4] = {};
    for (int s = 0; s < 16; s++) {
        int cur = s & 1, nxt = cur ^ 1;
        if (s < 15) load_w128(breg, W2, H, (s + 1) * 16, n0, tid);
        const float* B = Bs + cur * BSZ1;
#pragma unroll
        for (int kh = 0; kh < 16; kh += 8) {
            int kA = s * 16 + kh;
            float w0 = w1S[kA + t4], w4 = w1S[kA + t4 + 4];
            float c0 = b1S[kA + t4], c4 = b1S[kA + t4 + 4];
            float a[4][4];
#pragma unroll
            for (int mt = 0; mt < 4; mt++) {
                a[mt][0] = totf(fmaxf(fmaf(xr[mt][0], w0, c0), 0.f));
                a[mt][1] = totf(fmaxf(fmaf(xr[mt][1], w0, c0), 0.f));
                a[mt][2] = totf(fmaxf(fmaf(xr[mt][0], w4, c4), 0.f));
                a[mt][3] = totf(fmaxf(fmaf(xr[mt][1], w4, c4), 0.f));
            }
#pragma unroll
            for (int nt = 0; nt < 8; nt++) {
                int cn = wx * 64 + nt * 8 + g;
                float b0 = B[(kh + t4) * PB1 + cn];
                float b1v = B[(kh + t4 + 4) * PB1 + cn];
#pragma unroll
                for (int mt = 0; mt < 4; mt++)
                    mma1(acc[mt][nt], a[mt][0], a[mt][1], a[mt][2], a[mt][3], b0, b1v);
            }
        }
        if (s < 15) {
            store_w128(Bs + nxt * BSZ1, breg, tid);
            __syncthreads();
        }
    }

#pragma unroll
    for (int mt = 0; mt < 4; mt++)
#pragma unroll
        for (int half = 0; half < 2; half++) {
            int rl = wy * 64 + mt * 16 + g + half * 8;
            int row = m0 + rl;
            if (row >= EN) continue;
            float tb = tS[rl];
            const float* bep = &bond_emb[eS[rl] * H];
            size_t obase = (size_t)row * H;
#pragma unroll
            for (int nt = 0; nt < 8; nt++) {
                int col = n0 + wx * 64 + nt * 8 + 2 * t4;
                float v0 = (acc[mt][nt][half * 2 + 0] + b2[col] + tb) * bep[col];
                float v1 = (acc[mt][nt][half * 2 + 1] + b2[col + 1] + tb) * bep[col + 1];
                *(float2*)&g_bond[obase + col] = make_float2(v0, v1);
            }
        }
}

// ---------------- GIN GEMMs: 256 thr, 128x256 tile, pipelined (R10) ---------
#define GIN_SMEM ((2 * ASZ + 2 * BSZ) * 4)
template <int MODE>
__global__ void __launch_bounds__(256, 1)
gin_mma(const float* __restrict__ W, const float* __restrict__ bias, int reluOut) {
    extern __shared__ float sm[];
    float* As = sm;
    float* Bs = sm + 2 * ASZ;
    int tid = threadIdx.x, lane = tid & 31, warp = tid >> 5;
    int wy = warp >> 2, wx = warp & 3;
    int m0 = blockIdx.x * 128;
    int r = tid & 127, kh = (tid >> 7) * 8;
    int arow = m0 + r;
    bool valid = (arow < NN);
    const float* A1 = (MODE == 0) ? g_h : g_tmp;

    float areg[8], breg[16];
    auto loadA = [&](int k0) {
        if (valid) {
            const float* p = &A1[arow * H + k0 + kh];
            float4 v0 = *(const float4*)p, v1 = *(const float4*)(p + 4);
            areg[0] = v0.x; areg[1] = v0.y; areg[2] = v0.z; areg[3] = v0.w;
            areg[4] = v1.x; areg[5] = v1.y; areg[6] = v1.z; areg[7] = v1.w;
            if (MODE == 0) {
                const float* q = &g_aggr[arow * H + k0 + kh];
                float4 w0 = *(const float4*)q, w1 = *(const float4*)(q + 4);
                areg[0] += w0.x; areg[1] += w0.y; areg[2] += w0.z; areg[3] += w0.w;
                areg[4] += w1.x; areg[5] += w1.y; areg[6] += w1.z; areg[7] += w1.w;
            }
        } else {
#pragma unroll
            for (int i = 0; i < 8; i++) areg[i] = 0.f;
        }
    };

    loadA(0);
    load_w256(breg, W, H, 0, tid);
    store_a8(As, kh, r, areg);
    store_w256(Bs, breg, tid);
    __syncthreads();

    float acc[4][8][4] = {};
    for (int s = 0; s < 16; s++) {
        int cur = s & 1, nxt = cur ^ 1;
        if (s < 15) { loadA((s + 1) * 16); load_w256(breg, W, H, (s + 1) * 16, tid); }
        mma_k8w<PB>(acc, As + cur * ASZ, Bs + cur * BSZ, 0, wy, wx, lane);
        mma_k8w<PB>(acc, As + cur * ASZ, Bs + cur * BSZ, 8, wy, wx, lane);
        if (s < 15) {
            store_a8(As + nxt * ASZ, kh, r, areg);
            store_w256(Bs + nxt * BSZ, breg, tid);
            __syncthreads();
        }
    }

    int g = lane >> 2, t4 = lane & 3;
#pragma unroll
    for (int mt = 0; mt < 4; mt++)
#pragma unroll
        for (int half = 0; half < 2; half++) {
            int row = m0 + wy * 64 + mt * 16 + g + half * 8;
            if (row >= NN) continue;
#pragma unroll
            for (int nt = 0; nt < 8; nt++) {
                int col = wx * 64 + nt * 8 + 2 * t4;
                float v0 = acc[mt][nt][half * 2 + 0] + bias[col];
                float v1 = acc[mt][nt][half * 2 + 1] + bias[col + 1];
                if (reluOut) { v0 = fmaxf(v0, 0.f); v1 = fmaxf(v1, 0.f); }
                if (MODE == 0) {
                    *(float2*)&g_tmp[row * H + col] = make_float2(v0, v1);
                } else {
                    float2 rh = *(const float2*)&g_h[row * H + col];
                    *(float2*)&g_h[row * H + col] = make_float2(v0 + rh.x, v1 + rh.y);
                }
            }
        }
}

// ---------------- out1: K=512, 256 thr, 128x256 tile, pipelined (R10) -------
#define OUT1_SMEM ((2 * ASZ + 2 * BSZ + 256) * 4)
__global__ void __launch_bounds__(256, 1)
out1(const int* __restrict__ src, const int* __restrict__ dst,
     const float* __restrict__ W1, const float* __restrict__ b1) {
    extern __shared__ float sm[];
    float* As = sm;
    float* Bs = sm + 2 * ASZ;
    int* srcS = (int*)(Bs + 2 * BSZ);   // 128
    int* dstS = srcS + 128;             // 128
    int tid = threadIdx.x, lane = tid & 31, warp = tid >> 5;
    int wy = warp >> 2, wx = warp & 3;
    int m0 = blockIdx.x * 128;

    if (tid < 128) {
        int e = m0 + tid;
        int s = 0, d = 0;
        if (e < EN) { s = src[e]; d = dst[e]; }
        srcS[tid] = s; dstS[tid] = d;
    }
    __syncthreads();

    int r = tid & 127, kh = (tid >> 7) * 8;
    int e = m0 + r;
    bool valid = (e < EN);
    float areg[8], breg[16];

    auto loadA = [&](int k0) {
        if (k0 < 256) {
            const float* hs = &g_h[srcS[r] * H + k0 + kh];
            const float* hd = &g_h[dstS[r] * H + k0 + kh];
            float4 a0 = *(const float4*)hs, a1 = *(const float4*)(hs + 4);
            float4 c0 = *(const float4*)hd, c1 = *(const float4*)(hd + 4);
            areg[0] = a0.x * c0.x; areg[1] = a0.y * c0.y;
            areg[2] = a0.z * c0.z; areg[3] = a0.w * c0.w;
            areg[4] = a1.x * c1.x; areg[5] = a1.y * c1.y;
            areg[6] = a1.z * c1.z; areg[7] = a1.w * c1.w;
        } else if (valid) {
            const float* bp = &g_bond[(size_t)e * H + (k0 - 256) + kh];
            float4 v0 = *(const float4*)bp, v1 = *(const float4*)(bp + 4);
            areg[0] = v0.x; areg[1] = v0.y; areg[2] = v0.z; areg[3] = v0.w;
            areg[4] = v1.x; areg[5] = v1.y; areg[6] = v1.z; areg[7] = v1.w;
        } else {
#pragma unroll
            for (int i = 0; i < 8; i++) areg[i] = 0.f;
        }
    };

    loadA(0);
    load_w256(breg, W1, H, 0, tid);
    store_a8(As, kh, r, areg);
    store_w256(Bs, breg, tid);
    __syncthreads();

    float acc[4][8][4] = {};
    for (int s = 0; s < 32; s++) {
        int cur = s & 1, nxt = cur ^ 1;
        if (s < 31) { loadA((s + 1) * 16); load_w256(breg, W1, H, (s + 1) * 16, tid); }
        mma_k8w<PB>(acc, As + cur * ASZ, Bs + cur * BSZ, 0, wy, wx, lane);
        mma_k8w<PB>(acc, As + cur * ASZ, Bs + cur * BSZ, 8, wy, wx, lane);
        if (s < 31) {
            store_a8(As + nxt * ASZ, kh, r, areg);
            store_w256(Bs + nxt * BSZ, breg, tid);
            __syncthreads();
        }
    }

    int g = lane >> 2, t4 = lane & 3;
#pragma unroll
    for (int mt = 0; mt < 4; mt++)
#pragma unroll
        for (int half = 0; half < 2; half++) {
            int row = m0 + wy * 64 + mt * 16 + g + half * 8;
            if (row >= EN) continue;
#pragma unroll
            for (int nt = 0; nt < 8; nt++) {
                int col = wx * 64 + nt * 8 + 2 * t4;
                float v0 = fmaxf(acc[mt][nt][half * 2 + 0] + b1[col], 0.f);
                float v1 = fmaxf(acc[mt][nt][half * 2 + 1] + b1[col + 1], 0.f);
                *(float2*)&g_h1[(size_t)row * H + col] = make_float2(v0, v1);
            }
        }
}

// ---------------- out23 fused: 128x128 tile (static smem) -------------------
__global__ void __launch_bounds__(128, 2)
out23(const float* __restrict__ W2, const float* __restrict__ b2,
      const float* __restrict__ W3, const float* __restrict__ b3,
      float* __restrict__ out) {
    __shared__ float As[2 * ASZ], Bs[2 * BSZ1];
    __shared__ float red[128 * 8];
    __shared__ float b2S[128], w3S[128];
    int tid = threadIdx.x, lane = tid & 31, warp = tid >> 5;
    int wy = warp >> 1, wx = warp & 1;
    int m0 = blockIdx.x * 128;

    b2S[tid] = b2[tid]; w3S[tid] = W3[tid];

    int e = m0 + tid;
    bool valid = (e < EN);
    float areg[16], breg[16];
    auto loadA = [&](int k0) {
        if (valid) {
            const float* p = &g_h1[(size_t)e * H + k0];
#pragma unroll
            for (int j = 0; j < 4; j++) {
                float4 v = *(const float4*)(p + 4 * j);
                areg[4 * j] = v.x; areg[4 * j + 1] = v.y;
                areg[4 * j + 2] = v.z; areg[4 * j + 3] = v.w;
            }
        } else {
#pragma unroll
            for (int i = 0; i < 16; i++) areg[i] = 0.f;
        }
    };

    loadA(0);
    load_w128(breg, W2, 128, 0, 0, tid);
    store_a16(As, tid, areg);
    store_w128(Bs, breg, tid);
    __syncthreads();

    float acc[4][8][4] = {};
    for (int s = 0; s < 16; s++) {
        int cur = s & 1, nxt = cur ^ 1;
        if (s < 15) { loadA((s + 1) * 16); load_w128(breg, W2, 128, (s + 1) * 16, 0, tid); }
        mma_k8w<PB1>(acc, As + cur * ASZ, Bs + cur * BSZ1, 0, wy, wx, lane);
        mma_k8w<PB1>(acc, As + cur * ASZ, Bs + cur * BSZ1, 8, wy, wx, lane);
        if (s < 15) {
            store_a16(As + nxt * ASZ, tid, areg);
            store_w128(Bs + nxt * BSZ1, breg, tid);
            __syncthreads();
        }
    }

    int g = lane >> 2, t4 = lane & 3;
#pragma unroll
    for (int mt = 0; mt < 4; mt++)
#pragma unroll
        for (int half = 0; half < 2; half++) {
            int rl = wy * 64 + mt * 16 + g + half * 8;
            float partial = 0.f;
#pragma unroll
            for (int nt = 0; nt < 8; nt++) {
                int col = wx * 64 + nt * 8 + 2 * t4;
                float h0 = fmaxf(acc[mt][nt][half * 2 + 0] + b2S[col], 0.f);
                float h1 = fmaxf(acc[mt][nt][half * 2 + 1] + b2S[col + 1], 0.f);
                partial += h0 * w3S[col] + h1 * w3S[col + 1];
            }
            red[rl * 8 + wx * 4 + t4] = partial;
        }
    __syncthreads();

    if (valid) {
        float s = 0.f;
#pragma unroll
        for (int i = 0; i < 8; i++) s += red[tid * 8 + i];
        out[e] = (s + b3[0]) * g_einv[e];
    }
}

// ---------------- launch ----------------------------------------------------
extern "C" void kernel_launch(void* const* d_in, const int* in_sizes, int n_in,
                              void* d_out, int out_size) {
    const int*   node_type = (const int*)d_in[0];
    const int*   edge_type = (const int*)d_in[1];
    const int*   edge_index = (const int*)d_in[2];
    const int*   batch = (const int*)d_in[3];
    const float* elen = (const float*)d_in[4];
    const float* t = (const float*)d_in[5];
    const float* atom_emb = (const float*)d_in[6];
    const float* bond_emb = (const float*)d_in[7];
    const float* in_W1 = (const float*)d_in[8];
    const float* in_b1 = (const float*)d_in[9];
    const float* in_W2 = (const float*)d_in[10];
    const float* in_b2 = (const float*)d_in[11];
    const float* fourier_W = (const float*)d_in[12];
    const float* temb_W = (const float*)d_in[13];
    const float* temb_b = (const float*)d_in[14];
    const float* d1W = (const float*)d_in[15];
    const float* d1b = (const float*)d_in[16];
    const float* gin_W1 = (const float*)d_in[17];
    const float* gin_b1 = (const float*)d_in[18];
    const float* gin_W2 = (const float*)d_in[19];
    const float* gin_b2 = (const float*)d_in[20];
    const float* out_W1 = (const float*)d_in[21];
    const float* out_b1 = (const float*)d_in[22];
    const float* out_W2 = (const float*)d_in[23];
    const float* out_b2 = (const float*)d_in[24];
    const float* out_W3 = (const float*)d_in[25];
    const float* out_b3 = (const float*)d_in[26];
    const int* src = edge_index;
    const int* dst = edge_index + EN;
    float* out = (float*)d_out;

    const int EB = (EN + 127) / 128;   // 2344
    const int NB = (NN + 127) / 128;   // 391

    static int attr_done = 0;
    if (!attr_done) {
        cudaFuncSetAttribute(edge_bond, cudaFuncAttributeMaxDynamicSharedMemorySize, EB_SMEM);
        cudaFuncSetAttribute(gin_mma<0>, cudaFuncAttributeMaxDynamicSharedMemorySize, GIN_SMEM);
        cudaFuncSetAttribute(gin_mma<1>, cudaFuncAttributeMaxDynamicSharedMemorySize, GIN_SMEM);
        cudaFuncSetAttribute(out1, cudaFuncAttributeMaxDynamicSharedMemorySize, OUT1_SMEM);
        attr_done = 1;
    }

    // launch order chosen so ncu (launch index 3) profiles edge_bond
    temb_fused<<<GN, 128>>>(t, fourier_W, temb_W, temb_b, d1W, d1b);      // 0
    hist<<<(EN + 255) / 256, 256>>>(dst);                                 // 1
    scan_kernel<<<1, 1024>>>();                                           // 2
    edge_bond<<<dim3(2, EB), 128, EB_SMEM>>>(elen, src, batch, edge_type, // 3
                                             in_W1, in_b1, in_W2, in_b2, bond_emb);
    place<<<(EN + 255) / 256, 256>>>(src, dst);                           // 4
    init_h<<<(NN * 64 + 255) / 256, 256>>>(node_type, atom_emb);          // 5

    for (int c = 0; c < NCONV; c++) {
        gather<<<(NN + 7) / 8, 256>>>();
        gin_mma<0><<<NB, 256, GIN_SMEM>>>(gin_W1 + c * H * H, gin_b1 + c * H, 1);
        gin_mma<1><<<NB, 256, GIN_SMEM>>>(gin_W2 + c * H * H, gin_b2 + c * H,
                                          (c < NCONV - 1) ? 1 : 0);
    }

    out1<<<EB, 256, OUT1_SMEM>>>(src, dst, out_W1, out_b1);
    out23<<<EB, 128>>>(out_W2, out_b2, out_W3, out_b3, out);
}

// round 13
// speedup vs baseline: 1.0708x; 1.0322x over previous
#include <cuda_runtime.h>
#include <math.h>
#include <stdint.h>

#define EN 300000
#define NN 50000
#define GN 1024
#define H  256
#define NCONV 4
#define PA 136      // A stride, 128-row tiles (mod 32 == 8)
#define PA64 72     // A stride, 64-row tiles (mod 32 == 8)
#define PB 264      // B stride, 256-wide tiles (mod 32 == 8)
#define PB1 136     // B stride, 128-wide tiles

// ---------------- scratch (device globals) ---------------------------------
static __device__ float g_bond[(size_t)EN * H];
static __device__ float g_h1[(size_t)EN * H];
static __device__ float g_h[NN * H];
static __device__ float g_aggr[NN * H];
static __device__ float g_tmp[NN * H];
static __device__ float g_temb[GN];
static __device__ float g_invstd[GN];
static __device__ float g_einv[EN];
static __device__ int g_cnt[NN];
static __device__ int g_rp[NN + 1];
static __device__ int g_woff[NN];
static __device__ int g_srcp[EN];
static __device__ int g_eid[EN];

// ---------------- helpers ---------------------------------------------------
__device__ __forceinline__ float totf(float x) {
    uint32_t u; asm("cvt.rna.tf32.f32 %0, %1;" : "=r"(u) : "f"(x));
    return __uint_as_float(u);
}

__device__ __forceinline__ void mma1(float acc[4],
                                     float a0, float a1, float a2, float a3,
                                     float b0, float b1) {
    asm volatile(
        "mma.sync.aligned.m16n8k8.row.col.f32.tf32.tf32.f32 "
        "{%0,%1,%2,%3}, {%4,%5,%6,%7}, {%8,%9}, {%0,%1,%2,%3};\n"
        : "+f"(acc[0]), "+f"(acc[1]), "+f"(acc[2]), "+f"(acc[3])
        : "r"(__float_as_uint(a0)), "r"(__float_as_uint(a1)),
          "r"(__float_as_uint(a2)), "r"(__float_as_uint(a3)),
          "r"(__float_as_uint(b0)), "r"(__float_as_uint(b1)));
}

// warp 64x64 from 128-row A tile (stride PA), B stride BS
template <int BS>
__device__ __forceinline__ void mma_k8w(float acc[4][8][4],
                                        const float* As, const float* Bs,
                                        int kk, int wy, int wx, int lane) {
    int g = lane >> 2, t4 = lane & 3;
    float a[4][4];
#pragma unroll
    for (int mt = 0; mt < 4; mt++) {
        int rm = wy * 64 + mt * 16 + g;
        a[mt][0] = As[(kk + t4) * PA + rm];
        a[mt][1] = As[(kk + t4) * PA + rm + 8];
        a[mt][2] = As[(kk + t4 + 4) * PA + rm];
        a[mt][3] = As[(kk + t4 + 4) * PA + rm + 8];
    }
#pragma unroll
    for (int nt = 0; nt < 8; nt++) {
        int cn = wx * 64 + nt * 8 + g;
        float b0 = Bs[(kk + t4) * BS + cn];
        float b1 = Bs[(kk + t4 + 4) * BS + cn];
#pragma unroll
        for (int mt = 0; mt < 4; mt++)
            mma1(acc[mt][nt], a[mt][0], a[mt][1], a[mt][2], a[mt][3], b0, b1);
    }
}

// warp 64x64 from 64-row A tile (stride PA64); warp covers all 64 rows (wy=0)
__device__ __forceinline__ void mma_k8w64(float acc[4][8][4],
                                          const float* As, const float* Bs,
                                          int kk, int wx, int lane) {
    int g = lane >> 2, t4 = lane & 3;
    float a[4][4];
#pragma unroll
    for (int mt = 0; mt < 4; mt++) {
        int rm = mt * 16 + g;
        a[mt][0] = As[(kk + t4) * PA64 + rm];
        a[mt][1] = As[(kk + t4) * PA64 + rm + 8];
        a[mt][2] = As[(kk + t4 + 4) * PA64 + rm];
        a[mt][3] = As[(kk + t4 + 4) * PA64 + rm + 8];
    }
#pragma unroll
    for (int nt = 0; nt < 8; nt++) {
        int cn = wx * 64 + nt * 8 + g;
        float b0 = Bs[(kk + t4) * PB + cn];
        float b1 = Bs[(kk + t4 + 4) * PB + cn];
#pragma unroll
        for (int mt = 0; mt < 4; mt++)
            mma1(acc[mt][nt], a[mt][0], a[mt][1], a[mt][2], a[mt][3], b0, b1);
    }
}

// B tile 16x256, 256 threads: thread owns COLUMN tid
__device__ __forceinline__ void load_w256(float v[16], const float* __restrict__ W,
                                          int ldw, int k0, int tid) {
    const float* p = &W[(size_t)k0 * ldw + tid];
#pragma unroll
    for (int k = 0; k < 16; k++) v[k] = p[(size_t)k * ldw];
}
__device__ __forceinline__ void store_w256(float* Bs, const float v[16], int tid) {
#pragma unroll
    for (int k = 0; k < 16; k++) Bs[k * PB + tid] = totf(v[k]);
}
// B tile 16x256, 128 threads: thread owns columns tid and tid+128
__device__ __forceinline__ void load_w256h(float v[32], const float* __restrict__ W,
                                           int ldw, int k0, int tid) {
    const float* p = &W[(size_t)k0 * ldw + tid];
#pragma unroll
    for (int k = 0; k < 16; k++) {
        v[k] = p[(size_t)k * ldw];
        v[16 + k] = p[(size_t)k * ldw + 128];
    }
}
__device__ __forceinline__ void store_w256h(float* Bs, const float v[32], int tid) {
#pragma unroll
    for (int k = 0; k < 16; k++) {
        Bs[k * PB + tid] = totf(v[k]);
        Bs[k * PB + tid + 128] = totf(v[16 + k]);
    }
}
// B tile 16x128, 128 threads
__device__ __forceinline__ void load_w128(float v[16], const float* __restrict__ W,
                                          int ldw, int k0, int n0, int tid) {
    const float* p = &W[(size_t)k0 * ldw + n0 + tid];
#pragma unroll
    for (int k = 0; k < 16; k++) v[k] = p[(size_t)k * ldw];
}
__device__ __forceinline__ void store_w128(float* Bs, const float v[16], int tid) {
#pragma unroll
    for (int k = 0; k < 16; k++) Bs[k * PB1 + tid] = totf(v[k]);
}
// A 128-row tile, 256 threads: r = tid&127, kh = (tid>>7)*8
__device__ __forceinline__ void store_a8(float* As, int kh, int r, const float v[8]) {
#pragma unroll
    for (int i = 0; i < 8; i++) As[(kh + i) * PA + r] = totf(v[i]);
}
// A 64-row tile, 128 threads: r = tid&63, kh = (tid>>6)*8
__device__ __forceinline__ void store_a8_64(float* As, int kh, int r, const float v[8]) {
#pragma unroll
    for (int i = 0; i < 8; i++) As[(kh + i) * PA64 + r] = totf(v[i]);
}
// A 128-row tile, 128 threads, 16 k's per thread
__device__ __forceinline__ void store_a16(float* As, int r, const float v[16]) {
#pragma unroll
    for (int k = 0; k < 16; k++) As[k * PA + r] = totf(v[k]);
}

// ---------------- temb (comb fused) -----------------------------------------
__global__ void __launch_bounds__(128)
temb_fused(const float* __restrict__ t, const float* __restrict__ fw,
           const float* __restrict__ tW, const float* __restrict__ tb,
           const float* __restrict__ d1W, const float* __restrict__ d1b) {
    __shared__ float d1S[H], combS[H + 1], red[128];
    int tid = threadIdx.x, lane = tid & 31, warp = tid >> 5;
    d1S[tid] = d1W[tid]; d1S[tid + 128] = d1W[tid + 128];
    __syncthreads();
    for (int row = warp; row < H + 1; row += 4) {
        const float* p = (row < H) ? &tW[(size_t)row * H] : tb;
        float s = 0.f;
        for (int k = lane; k < H; k += 32) s += p[k] * d1S[k];
#pragma unroll
        for (int o = 16; o; o >>= 1) s += __shfl_down_sync(0xffffffffu, s, o);
        if (lane == 0) combS[row] = (row == H) ? s + d1b[0] : s;
    }
    __syncthreads();
    int g = blockIdx.x;
    float tt = t[g];
    float xp = tt * fw[tid] * 6.283185307179586f;
    red[tid] = sinf(xp) * combS[tid] + cosf(xp) * combS[128 + tid];
    __syncthreads();
    for (int s = 64; s > 0; s >>= 1) {
        if (tid < s) red[tid] += red[tid + s];
        __syncthreads();
    }
    if (tid == 0) {
        g_temb[g] = red[0] + combS[H];
        const float LS = 3.2188758248682006f;   // ln(25)
        float var = (expf(2.f * tt * LS) - 1.f) / (2.f * LS);
        g_invstd[g] = rsqrtf(var);
    }
}

// ---------------- sort machinery ---------------------------------------------
__global__ void __launch_bounds__(256) hist(const int* __restrict__ dst) {
    int e = blockIdx.x * blockDim.x + threadIdx.x;
    if (e < EN) atomicAdd(&g_cnt[dst[e]], 1);
}

__global__ void __launch_bounds__(1024) scan_kernel() {
    __shared__ int part[1024];
    const int CH = 49;
    int t = threadIdx.x;
    int beg = t * CH, end = min(beg + CH, NN);
    int s = 0;
    for (int i = beg; i < end; i++) s += g_cnt[i];
    part[t] = s;
    __syncthreads();
    for (int off = 1; off < 1024; off <<= 1) {
        int v = (t >= off) ? part[t - off] : 0;
        __syncthreads();
        part[t] += v;
        __syncthreads();
    }
    int run = (t == 0) ? 0 : part[t - 1];
    for (int i = beg; i < end; i++) {
        g_rp[i] = run; g_woff[i] = run; run += g_cnt[i];
        g_cnt[i] = 0;
    }
    if (t == 1023) g_rp[NN] = part[1023];
}

__global__ void __launch_bounds__(256) place(const int* __restrict__ src,
                                             const int* __restrict__ dst) {
    int e = blockIdx.x * blockDim.x + threadIdx.x;
    if (e >= EN) return;
    int p = atomicAdd(&g_woff[dst[e]], 1);
    g_srcp[p] = src[e];
    g_eid[p] = e;
}

__global__ void __launch_bounds__(256) init_h(const int* __restrict__ nt,
                                              const float* __restrict__ atom_emb) {
    int idx = blockIdx.x * blockDim.x + threadIdx.x;
    if (idx >= NN * 64) return;
    int n = idx >> 6, q = idx & 63;
    ((float4*)g_h)[idx] = ((const float4*)atom_emb)[nt[n] * 64 + q];
}

// ---------------- gather ----------------------------------------------------
__global__ void __launch_bounds__(256) gather() {
    int warp = threadIdx.x >> 5, lane = threadIdx.x & 31;
    int n = blockIdx.x * 8 + warp;
    if (n >= NN) return;
    int q = lane * 8;
    float4 a0 = make_float4(0.f, 0.f, 0.f, 0.f), a1 = a0;
    int beg = g_rp[n], end = g_rp[n + 1];
    for (int p = beg; p < end; p++) {
        int s = g_srcp[p];
        int e = g_eid[p];
        const float4* hp = (const float4*)&g_h[s * H + q];
        const float4* bp = (const float4*)&g_bond[(size_t)e * H + q];
        float4 h0 = hp[0], h1v = hp[1], b0 = bp[0], b1v = bp[1];
        a0.x += fmaxf(h0.x + b0.x, 0.f);  a0.y += fmaxf(h0.y + b0.y, 0.f);
        a0.z += fmaxf(h0.z + b0.z, 0.f);  a0.w += fmaxf(h0.w + b0.w, 0.f);
        a1.x += fmaxf(h1v.x + b1v.x, 0.f); a1.y += fmaxf(h1v.y + b1v.y, 0.f);
        a1.z += fmaxf(h1v.z + b1v.z, 0.f); a1.w += fmaxf(h1v.w + b1v.w, 0.f);
    }
    float4* ap = (float4*)&g_aggr[n * H + q];
    ap[0] = a0; ap[1] = a1;
}

// ---------------- edge_bond: 128 thr, grid(2, EB) (R12-verified) ------------
#define ASZ (16 * PA)
#define ASZ64 (16 * PA64)
#define BSZ (16 * PB)
#define BSZ1 (16 * PB1)
#define EB_SMEM ((2 * BSZ1 + 128 + 128 + 128 + 2 * H) * 4)

__global__ void __launch_bounds__(128, 2)
edge_bond(const float* __restrict__ elen, const int* __restrict__ src,
          const int* __restrict__ batch, const int* __restrict__ etype,
          const float* __restrict__ W1, const float* __restrict__ b1,
          const float* __restrict__ W2, const float* __restrict__ b2,
          const float* __restrict__ bond_emb) {
    extern __shared__ float sm[];
    float* Bs = sm;
    float* xS = Bs + 2 * BSZ1;
    float* tS = xS + 128;
    int*   eS = (int*)(tS + 128);
    float* w1S = (float*)(eS + 128);
    float* b1S = w1S + H;

    int tid = threadIdx.x, lane = tid & 31, warp = tid >> 5;
    int wy = warp >> 1, wx = warp & 1;
    int g = lane >> 2, t4 = lane & 3;
    int m0 = blockIdx.y * 128, n0 = blockIdx.x * 128;

    {
        int e = m0 + tid;
        float x = 0.f, tb = 0.f; int et = 0;
        if (e < EN) {
            x = elen[e];
            int gph = batch[src[e]];
            tb = g_temb[gph];
            if (n0 == 0) g_einv[e] = g_invstd[gph];
            et = etype[e];
        }
        xS[tid] = x; tS[tid] = tb; eS[tid] = et;
    }
    w1S[tid] = W1[tid];         w1S[tid + 128] = W1[tid + 128];
    b1S[tid] = b1[tid];         b1S[tid + 128] = b1[tid + 128];
    __syncthreads();

    float xr[4][2];
#pragma unroll
    for (int mt = 0; mt < 4; mt++) {
        xr[mt][0] = xS[wy * 64 + mt * 16 + g];
        xr[mt][1] = xS[wy * 64 + mt * 16 + g + 8];
    }

    float breg[16];
    load_w128(breg, W2, H, 0, n0, tid);
    store_w128(Bs, breg, tid);
    __syncthreads();

    float acc[4][8][4] = {};
    for (int s = 0; s < 16; s++) {
        int cur = s & 1, nxt = cur ^ 1;
        if (s < 15) load_w128(breg, W2, H, (s + 1) * 16, n0, tid);
        const float* B = Bs + cur * BSZ1;
#pragma unroll
        for (int kh = 0; kh < 16; kh += 8) {
            int kA = s * 16 + kh;
            float w0 = w1S[kA + t4], w4 = w1S[kA + t4 + 4];
            float c0 = b1S[kA + t4], c4 = b1S[kA + t4 + 4];
            float a[4][4];
#pragma unroll
            for (int mt = 0; mt < 4; mt++) {
                a[mt][0] = totf(fmaxf(fmaf(xr[mt][0], w0, c0), 0.f));
                a[mt][1] = totf(fmaxf(fmaf(xr[mt][1], w0, c0), 0.f));
                a[mt][2] = totf(fmaxf(fmaf(xr[mt][0], w4, c4), 0.f));
                a[mt][3] = totf(fmaxf(fmaf(xr[mt][1], w4, c4), 0.f));
            }
#pragma unroll
            for (int nt = 0; nt < 8; nt++) {
                int cn = wx * 64 + nt * 8 + g;
                float b0 = B[(kh + t4) * PB1 + cn];
                float b1v = B[(kh + t4 + 4) * PB1 + cn];
#pragma unroll
                for (int mt = 0; mt < 4; mt++)
                    mma1(acc[mt][nt], a[mt][0], a[mt][1], a[mt][2], a[mt][3], b0, b1v);
            }
        }
        if (s < 15) {
            store_w128(Bs + nxt * BSZ1, breg, tid);
            __syncthreads();
        }
    }

#pragma unroll
    for (int mt = 0; mt < 4; mt++)
#pragma unroll
        for (int half = 0; half < 2; half++) {
            int rl = wy * 64 + mt * 16 + g + half * 8;
            int row = m0 + rl;
            if (row >= EN) continue;
            float tb = tS[rl];
            const float* bep = &bond_emb[eS[rl] * H];
            size_t obase = (size_t)row * H;
#pragma unroll
            for (int nt = 0; nt < 8; nt++) {
                int col = n0 + wx * 64 + nt * 8 + 2 * t4;
                float v0 = (acc[mt][nt][half * 2 + 0] + b2[col] + tb) * bep[col];
                float v1 = (acc[mt][nt][half * 2 + 1] + b2[col + 1] + tb) * bep[col + 1];
                *(float2*)&g_bond[obase + col] = make_float2(v0, v1);
            }
        }
}

// ---------------- GIN GEMMs: 64x256 tile, 128 thr, 2 CTA/SM -----------------
#define GIN_SMEM ((2 * ASZ64 + 2 * BSZ) * 4)
template <int MODE>
__global__ void __launch_bounds__(128, 2)
gin_mma(const float* __restrict__ W, const float* __restrict__ bias, int reluOut) {
    extern __shared__ float sm[];
    float* As = sm;                 // 2*ASZ64
    float* Bs = sm + 2 * ASZ64;     // 2*BSZ
    int tid = threadIdx.x, lane = tid & 31, warp = tid >> 5;
    int wx = warp;                  // 4 warps side by side over N=256
    int m0 = blockIdx.x * 64;
    int r = tid & 63, kh = (tid >> 6) * 8;
    int arow = m0 + r;
    bool valid = (arow < NN);
    const float* A1 = (MODE == 0) ? g_h : g_tmp;

    float areg[8], breg[32];
    auto loadA = [&](int k0) {
        if (valid) {
            const float* p = &A1[arow * H + k0 + kh];
            float4 v0 = *(const float4*)p, v1 = *(const float4*)(p + 4);
            areg[0] = v0.x; areg[1] = v0.y; areg[2] = v0.z; areg[3] = v0.w;
            areg[4] = v1.x; areg[5] = v1.y; areg[6] = v1.z; areg[7] = v1.w;
            if (MODE == 0) {
                const float* q = &g_aggr[arow * H + k0 + kh];
                float4 w0 = *(const float4*)q, w1 = *(const float4*)(q + 4);
                areg[0] += w0.x; areg[1] += w0.y; areg[2] += w0.z; areg[3] += w0.w;
                areg[4] += w1.x; areg[5] += w1.y; areg[6] += w1.z; areg[7] += w1.w;
            }
        } else {
#pragma unroll
            for (int i = 0; i < 8; i++) areg[i] = 0.f;
        }
    };

    loadA(0);
    load_w256h(breg, W, H, 0, tid);
    store_a8_64(As, kh, r, areg);
    store_w256h(Bs, breg, tid);
    __syncthreads();

    float acc[4][8][4] = {};
    for (int s = 0; s < 16; s++) {
        int cur = s & 1, nxt = cur ^ 1;
        if (s < 15) { loadA((s + 1) * 16); load_w256h(breg, W, H, (s + 1) * 16, tid); }
        mma_k8w64(acc, As + cur * ASZ64, Bs + cur * BSZ, 0, wx, lane);
        mma_k8w64(acc, As + cur * ASZ64, Bs + cur * BSZ, 8, wx, lane);
        if (s < 15) {
            store_a8_64(As + nxt * ASZ64, kh, r, areg);
            store_w256h(Bs + nxt * BSZ, breg, tid);
            __syncthreads();
        }
    }

    int g = lane >> 2, t4 = lane & 3;
#pragma unroll
    for (int mt = 0; mt < 4; mt++)
#pragma unroll
        for (int half = 0; half < 2; half++) {
            int row = m0 + mt * 16 + g + half * 8;
            if (row >= NN) continue;
#pragma unroll
            for (int nt = 0; nt < 8; nt++) {
                int col = wx * 64 + nt * 8 + 2 * t4;
                float v0 = acc[mt][nt][half * 2 + 0] + bias[col];
                float v1 = acc[mt][nt][half * 2 + 1] + bias[col + 1];
                if (reluOut) { v0 = fmaxf(v0, 0.f); v1 = fmaxf(v1, 0.f); }
                if (MODE == 0) {
                    *(float2*)&g_tmp[row * H + col] = make_float2(v0, v1);
                } else {
                    float2 rh = *(const float2*)&g_h[row * H + col];
                    *(float2*)&g_h[row * H + col] = make_float2(v0 + rh.x, v1 + rh.y);
                }
            }
        }
}

// ---------------- out1: K=512, 64x256 tile, 128 thr, 2 CTA/SM ---------------
#define OUT1_SMEM ((2 * ASZ64 + 2 * BSZ + 128) * 4)
__global__ void __launch_bounds__(128, 2)
out1(const int* __restrict__ src, const int* __restrict__ dst,
     const float* __restrict__ W1, const float* __restrict__ b1) {
    extern __shared__ float sm[];
    float* As = sm;                    // 2*ASZ64
    float* Bs = sm + 2 * ASZ64;        // 2*BSZ
    int* srcS = (int*)(Bs + 2 * BSZ);  // 64
    int* dstS = srcS + 64;             // 64
    int tid = threadIdx.x, lane = tid & 31, warp = tid >> 5;
    int wx = warp;
    int m0 = blockIdx.x * 64;

    if (tid < 64) {
        int e = m0 + tid;
        int s = 0, d = 0;
        if (e < EN) { s = src[e]; d = dst[e]; }
        srcS[tid] = s; dstS[tid] = d;
    }
    __syncthreads();

    int r = tid & 63, kh = (tid >> 6) * 8;
    int e = m0 + r;
    bool valid = (e < EN);
    float areg[8], breg[32];

    auto loadA = [&](int k0) {
        if (k0 < 256) {
            const float* hs = &g_h[srcS[r] * H + k0 + kh];
            const float* hd = &g_h[dstS[r] * H + k0 + kh];
            float4 a0 = *(const float4*)hs, a1 = *(const float4*)(hs + 4);
            float4 c0 = *(const float4*)hd, c1 = *(const float4*)(hd + 4);
            areg[0] = a0.x * c0.x; areg[1] = a0.y * c0.y;
            areg[2] = a0.z * c0.z; areg[3] = a0.w * c0.w;
            areg[4] = a1.x * c1.x; areg[5] = a1.y * c1.y;
            areg[6] = a1.z * c1.z; areg[7] = a1.w * c1.w;
        } else if (valid) {
            const float* bp = &g_bond[(size_t)e * H + (k0 - 256) + kh];
            float4 v0 = *(const float4*)bp, v1 = *(const float4*)(bp + 4);
            areg[0] = v0.x; areg[1] = v0.y; areg[2] = v0.z; areg[3] = v0.w;
            areg[4] = v1.x; areg[5] = v1.y; areg[6] = v1.z; areg[7] = v1.w;
        } else {
#pragma unroll
            for (int i = 0; i < 8; i++) areg[i] = 0.f;
        }
    };

    loadA(0);
    load_w256h(breg, W1, H, 0, tid);
    store_a8_64(As, kh, r, areg);
    store_w256h(Bs, breg, tid);
    __syncthreads();

    float acc[4][8][4] = {};
    for (int s = 0; s < 32; s++) {
        int cur = s & 1, nxt = cur ^ 1;
        if (s < 31) { loadA((s + 1) * 16); load_w256h(breg, W1, H, (s + 1) * 16, tid); }
        mma_k8w64(acc, As + cur * ASZ64, Bs + cur * BSZ, 0, wx, lane);
        mma_k8w64(acc, As + cur * ASZ64, Bs + cur * BSZ, 8, wx, lane);
        if (s < 31) {
            store_a8_64(As + nxt * ASZ64, kh, r, areg);
            store_w256h(Bs + nxt * BSZ, breg, tid);
            __syncthreads();
        }
    }

    int g = lane >> 2, t4 = lane & 3;
#pragma unroll
    for (int mt = 0; mt < 4; mt++)
#pragma unroll
        for (int half = 0; half < 2; half++) {
            int row = m0 + mt * 16 + g + half * 8;
            if (row >= EN) continue;
#pragma unroll
            for (int nt = 0; nt < 8; nt++) {
                int col = wx * 64 + nt * 8 + 2 * t4;
                float v0 = fmaxf(acc[mt][nt][half * 2 + 0] + b1[col], 0.f);
                float v1 = fmaxf(acc[mt][nt][half * 2 + 1] + b1[col + 1], 0.f);
                *(float2*)&g_h1[(size_t)row * H + col] = make_float2(v0, v1);
            }
        }
}

// ---------------- out23 fused: 128x128 tile (static smem, unchanged) --------
__global__ void __launch_bounds__(128, 2)
out23(const float* __restrict__ W2, const float* __restrict__ b2,
      const float* __restrict__ W3, const float* __restrict__ b3,
      float* __restrict__ out) {
    __shared__ float As[2 * ASZ], Bs[2 * BSZ1];
    __shared__ float red[128 * 8];
    __shared__ float b2S[128], w3S[128];
    int tid = threadIdx.x, lane = tid & 31, warp = tid >> 5;
    int wy = warp >> 1, wx = warp & 1;
    int m0 = blockIdx.x * 128;

    b2S[tid] = b2[tid]; w3S[tid] = W3[tid];

    int e = m0 + tid;
    bool valid = (e < EN);
    float areg[16], breg[16];
    auto loadA = [&](int k0) {
        if (valid) {
            const float* p = &g_h1[(size_t)e * H + k0];
#pragma unroll
            for (int j = 0; j < 4; j++) {
                float4 v = *(const float4*)(p + 4 * j);
                areg[4 * j] = v.x; areg[4 * j + 1] = v.y;
                areg[4 * j + 2] = v.z; areg[4 * j + 3] = v.w;
            }
        } else {
#pragma unroll
            for (int i = 0; i < 16; i++) areg[i] = 0.f;
        }
    };

    loadA(0);
    load_w128(breg, W2, 128, 0, 0, tid);
    store_a16(As, tid, areg);
    store_w128(Bs, breg, tid);
    __syncthreads();

    float acc[4][8][4] = {};
    for (int s = 0; s < 16; s++) {
        int cur = s & 1, nxt = cur ^ 1;
        if (s < 15) { loadA((s + 1) * 16); load_w128(breg, W2, 128, (s + 1) * 16, 0, tid); }
        mma_k8w<PB1>(acc, As + cur * ASZ, Bs + cur * BSZ1, 0, wy, wx, lane);
        mma_k8w<PB1>(acc, As + cur * ASZ, Bs + cur * BSZ1, 8, wy, wx, lane);
        if (s < 15) {
            store_a16(As + nxt * ASZ, tid, areg);
            store_w128(Bs + nxt * BSZ1, breg, tid);
            __syncthreads();
        }
    }

    int g = lane >> 2, t4 = lane & 3;
#pragma unroll
    for (int mt = 0; mt < 4; mt++)
#pragma unroll
        for (int half = 0; half < 2; half++) {
            int rl = wy * 64 + mt * 16 + g + half * 8;
            float partial = 0.f;
#pragma unroll
            for (int nt = 0; nt < 8; nt++) {
                int col = wx * 64 + nt * 8 + 2 * t4;
                float h0 = fmaxf(acc[mt][nt][half * 2 + 0] + b2S[col], 0.f);
                float h1 = fmaxf(acc[mt][nt][half * 2 + 1] + b2S[col + 1], 0.f);
                partial += h0 * w3S[col] + h1 * w3S[col + 1];
            }
            red[rl * 8 + wx * 4 + t4] = partial;
        }
    __syncthreads();

    if (valid) {
        float s = 0.f;
#pragma unroll
        for (int i = 0; i < 8; i++) s += red[tid * 8 + i];
        out[e] = (s + b3[0]) * g_einv[e];
    }
}

// ---------------- launch ----------------------------------------------------
extern "C" void kernel_launch(void* const* d_in, const int* in_sizes, int n_in,
                              void* d_out, int out_size) {
    const int*   node_type = (const int*)d_in[0];
    const int*   edge_type = (const int*)d_in[1];
    const int*   edge_index = (const int*)d_in[2];
    const int*   batch = (const int*)d_in[3];
    const float* elen = (const float*)d_in[4];
    const float* t = (const float*)d_in[5];
    const float* atom_emb = (const float*)d_in[6];
    const float* bond_emb = (const float*)d_in[7];
    const float* in_W1 = (const float*)d_in[8];
    const float* in_b1 = (const float*)d_in[9];
    const float* in_W2 = (const float*)d_in[10];
    const float* in_b2 = (const float*)d_in[11];
    const float* fourier_W = (const float*)d_in[12];
    const float* temb_W = (const float*)d_in[13];
    const float* temb_b = (const float*)d_in[14];
    const float* d1W = (const float*)d_in[15];
    const float* d1b = (const float*)d_in[16];
    const float* gin_W1 = (const float*)d_in[17];
    const float* gin_b1 = (const float*)d_in[18];
    const float* gin_W2 = (const float*)d_in[19];
    const float* gin_b2 = (const float*)d_in[20];
    const float* out_W1 = (const float*)d_in[21];
    const float* out_b1 = (const float*)d_in[22];
    const float* out_W2 = (const float*)d_in[23];
    const float* out_b2 = (const float*)d_in[24];
    const float* out_W3 = (const float*)d_in[25];
    const float* out_b3 = (const float*)d_in[26];
    const int* src = edge_index;
    const int* dst = edge_index + EN;
    float* out = (float*)d_out;

    const int EB = (EN + 127) / 128;      // 2344
    const int EB64 = (EN + 63) / 64;      // 4688
    const int NB64 = (NN + 63) / 64;      // 782

    static int attr_done = 0;
    if (!attr_done) {
        cudaFuncSetAttribute(edge_bond, cudaFuncAttributeMaxDynamicSharedMemorySize, EB_SMEM);
        cudaFuncSetAttribute(gin_mma<0>, cudaFuncAttributeMaxDynamicSharedMemorySize, GIN_SMEM);
        cudaFuncSetAttribute(gin_mma<1>, cudaFuncAttributeMaxDynamicSharedMemorySize, GIN_SMEM);
        cudaFuncSetAttribute(out1, cudaFuncAttributeMaxDynamicSharedMemorySize, OUT1_SMEM);
        attr_done = 1;
    }

    // launch order chosen so ncu (launch index 3) profiles edge_bond
    temb_fused<<<GN, 128>>>(t, fourier_W, temb_W, temb_b, d1W, d1b);      // 0
    hist<<<(EN + 255) / 256, 256>>>(dst);                                 // 1
    scan_kernel<<<1, 1024>>>();                                           // 2
    edge_bond<<<dim3(2, EB), 128, EB_SMEM>>>(elen, src, batch, edge_type, // 3
                                             in_W1, in_b1, in_W2, in_b2, bond_emb);
    place<<<(EN + 255) / 256, 256>>>(src, dst);                           // 4
    init_h<<<(NN * 64 + 255) / 256, 256>>>(node_type, atom_emb);          // 5

    for (int c = 0; c < NCONV; c++) {
        gather<<<(NN + 7) / 8, 256>>>();
        gin_mma<0><<<NB64, 128, GIN_SMEM>>>(gin_W1 + c * H * H, gin_b1 + c * H, 1);
        gin_mma<1><<<NB64, 128, GIN_SMEM>>>(gin_W2 + c * H * H, gin_b2 + c * H,
                                            (c < NCONV - 1) ? 1 : 0);
    }

    out1<<<EB64, 128, OUT1_SMEM>>>(src, dst, out_W1, out_b1);
    out23<<<EB, 128>>>(out_W2, out_b2, out_W3, out_b3, out);
}

// round 14
// speedup vs baseline: 1.1108x; 1.0374x over previous
#include <cuda_runtime.h>
#include <math.h>
#include <stdint.h>

#define EN 300000
#define NN 50000
#define GN 1024
#define H  256
#define NCONV 4
// old-style strides (kept for out23)
#define PA 136
#define PB1 136
#define ASZ (16 * PA)
#define BSZ1 (16 * PB1)
// paired-fragment layout constants
#define A64P 136            // A 64-row paired: k*136 + rpos   (136 mod 32 == 8)
#define A64SZ (16 * A64P)   // 2176 floats
#define B256P 520           // B 256-wide paired: slot*520 + n*2 + half (520 mod 32 == 8)
#define B256SZ (8 * B256P)  // 4160 floats
#define B128P 264           // B 128-wide paired (264 mod 32 == 8)
#define B128SZ (8 * B128P)  // 2112 floats

// ---------------- scratch (device globals) ---------------------------------
static __device__ float g_bond[(size_t)EN * H];
static __device__ float g_h1[(size_t)EN * H];
static __device__ float g_h[NN * H];
static __device__ float g_aggr[NN * H];
static __device__ float g_tmp[NN * H];
static __device__ float g_temb[GN];
static __device__ float g_invstd[GN];
static __device__ float g_einv[EN];
static __device__ int g_cnt[NN];
static __device__ int g_rp[NN + 1];
static __device__ int g_woff[NN];
static __device__ int g_srcp[EN];
static __device__ int g_eid[EN];

// ---------------- helpers ---------------------------------------------------
__device__ __forceinline__ float totf(float x) {
    uint32_t u; asm("cvt.rna.tf32.f32 %0, %1;" : "=r"(u) : "f"(x));
    return __uint_as_float(u);
}

__device__ __forceinline__ void mma1(float acc[4],
                                     float a0, float a1, float a2, float a3,
                                     float b0, float b1) {
    asm volatile(
        "mma.sync.aligned.m16n8k8.row.col.f32.tf32.tf32.f32 "
        "{%0,%1,%2,%3}, {%4,%5,%6,%7}, {%8,%9}, {%0,%1,%2,%3};\n"
        : "+f"(acc[0]), "+f"(acc[1]), "+f"(acc[2]), "+f"(acc[3])
        : "r"(__float_as_uint(a0)), "r"(__float_as_uint(a1)),
          "r"(__float_as_uint(a2)), "r"(__float_as_uint(a3)),
          "r"(__float_as_uint(b0)), "r"(__float_as_uint(b1)));
}

// ---- old-style warp 64x64 (kept for out23; A 128-row, B stride BS) ----
template <int BS>
__device__ __forceinline__ void mma_k8w(float acc[4][8][4],
                                        const float* As, const float* Bs,
                                        int kk, int wy, int wx, int lane) {
    int g = lane >> 2, t4 = lane & 3;
    float a[4][4];
#pragma unroll
    for (int mt = 0; mt < 4; mt++) {
        int rm = wy * 64 + mt * 16 + g;
        a[mt][0] = As[(kk + t4) * PA + rm];
        a[mt][1] = As[(kk + t4) * PA + rm + 8];
        a[mt][2] = As[(kk + t4 + 4) * PA + rm];
        a[mt][3] = As[(kk + t4 + 4) * PA + rm + 8];
    }
#pragma unroll
    for (int nt = 0; nt < 8; nt++) {
        int cn = wx * 64 + nt * 8 + g;
        float b0 = Bs[(kk + t4) * BS + cn];
        float b1 = Bs[(kk + t4 + 4) * BS + cn];
#pragma unroll
        for (int mt = 0; mt < 4; mt++)
            mma1(acc[mt][nt], a[mt][0], a[mt][1], a[mt][2], a[mt][3], b0, b1);
    }
}

// ---- paired-fragment warp 64x64: A 64-row paired, B 256-wide paired ----
__device__ __forceinline__ void mma_k8p64(float acc[4][8][4],
                                          const float* As, const float* Bs,
                                          int kk, int wx, int lane) {
    int g = lane >> 2, t4 = lane & 3;
    int ks = (kk >> 3) * 4 + t4;
    float2 a01[4], a23[4];
#pragma unroll
    for (int mt = 0; mt < 4; mt++) {
        a01[mt] = *(const float2*)&As[(kk + t4) * A64P + (mt * 8 + g) * 2];
        a23[mt] = *(const float2*)&As[(kk + t4 + 4) * A64P + (mt * 8 + g) * 2];
    }
#pragma unroll
    for (int nt = 0; nt < 8; nt++) {
        int cn = wx * 64 + nt * 8 + g;
        float2 b = *(const float2*)&Bs[ks * B256P + cn * 2];
#pragma unroll
        for (int mt = 0; mt < 4; mt++)
            mma1(acc[mt][nt], a01[mt].x, a01[mt].y, a23[mt].x, a23[mt].y, b.x, b.y);
    }
}

// ---- loaders / storers ----
// B 16x256 from global, 128 threads own cols tid and tid+128
__device__ __forceinline__ void load_w256h(float v[32], const float* __restrict__ W,
                                           int ldw, int k0, int tid) {
    const float* p = &W[(size_t)k0 * ldw + tid];
#pragma unroll
    for (int k = 0; k < 16; k++) {
        v[k] = p[(size_t)k * ldw];
        v[16 + k] = p[(size_t)k * ldw + 128];
    }
}
// store paired: 16 STS.64, conflict-free
__device__ __forceinline__ void store_w256p(float* Bs, const float v[32], int tid) {
#pragma unroll
    for (int s8 = 0; s8 < 2; s8++)
#pragma unroll
        for (int t4 = 0; t4 < 4; t4++) {
            int slot = s8 * 4 + t4;
            *(float2*)&Bs[slot * B256P + tid * 2] =
                make_float2(totf(v[s8 * 8 + t4]), totf(v[s8 * 8 + t4 + 4]));
            *(float2*)&Bs[slot * B256P + (tid + 128) * 2] =
                make_float2(totf(v[16 + s8 * 8 + t4]), totf(v[16 + s8 * 8 + t4 + 4]));
        }
}
// B 16x128 from global, 128 threads own col n0+tid
__device__ __forceinline__ void load_w128(float v[16], const float* __restrict__ W,
                                          int ldw, int k0, int n0, int tid) {
    const float* p = &W[(size_t)k0 * ldw + n0 + tid];
#pragma unroll
    for (int k = 0; k < 16; k++) v[k] = p[(size_t)k * ldw];
}
// paired store for 128-wide B: 8 STS.64
__device__ __forceinline__ void store_w128p(float* Bs, const float v[16], int tid) {
#pragma unroll
    for (int s8 = 0; s8 < 2; s8++)
#pragma unroll
        for (int t4 = 0; t4 < 4; t4++)
            *(float2*)&Bs[(s8 * 4 + t4) * B128P + tid * 2] =
                make_float2(totf(v[s8 * 8 + t4]), totf(v[s8 * 8 + t4 + 4]));
}
// old-style 128-wide B store (out23)
__device__ __forceinline__ void store_w128(float* Bs, const float v[16], int tid) {
#pragma unroll
    for (int k = 0; k < 16; k++) Bs[k * PB1 + tid] = totf(v[k]);
}
// A 64-row paired store: thread owns row r, 8 k's from kh
__device__ __forceinline__ void store_a8p(float* As, int kh, int r, const float v[8]) {
    int rpos = ((r >> 4) * 8 + (r & 7)) * 2 + ((r >> 3) & 1);
#pragma unroll
    for (int i = 0; i < 8; i++) As[(kh + i) * A64P + rpos] = totf(v[i]);
}
// old-style A 128-row store (out23)
__device__ __forceinline__ void store_a16(float* As, int r, const float v[16]) {
#pragma unroll
    for (int k = 0; k < 16; k++) As[k * PA + r] = totf(v[k]);
}

// ---------------- temb (comb fused) -----------------------------------------
__global__ void __launch_bounds__(128)
temb_fused(const float* __restrict__ t, const float* __restrict__ fw,
           const float* __restrict__ tW, const float* __restrict__ tb,
           const float* __restrict__ d1W, const float* __restrict__ d1b) {
    __shared__ float d1S[H], combS[H + 1], red[128];
    int tid = threadIdx.x, lane = tid & 31, warp = tid >> 5;
    d1S[tid] = d1W[tid]; d1S[tid + 128] = d1W[tid + 128];
    __syncthreads();
    for (int row = warp; row < H + 1; row += 4) {
        const float* p = (row < H) ? &tW[(size_t)row * H] : tb;
        float s = 0.f;
        for (int k = lane; k < H; k += 32) s += p[k] * d1S[k];
#pragma unroll
        for (int o = 16; o; o >>= 1) s += __shfl_down_sync(0xffffffffu, s, o);
        if (lane == 0) combS[row] = (row == H) ? s + d1b[0] : s;
    }
    __syncthreads();
    int g = blockIdx.x;
    float tt = t[g];
    float xp = tt * fw[tid] * 6.283185307179586f;
    red[tid] = sinf(xp) * combS[tid] + cosf(xp) * combS[128 + tid];
    __syncthreads();
    for (int s = 64; s > 0; s >>= 1) {
        if (tid < s) red[tid] += red[tid + s];
        __syncthreads();
    }
    if (tid == 0) {
        g_temb[g] = red[0] + combS[H];
        const float LS = 3.2188758248682006f;   // ln(25)
        float var = (expf(2.f * tt * LS) - 1.f) / (2.f * LS);
        g_invstd[g] = rsqrtf(var);
    }
}

// ---------------- sort machinery ---------------------------------------------
__global__ void __launch_bounds__(256) hist(const int* __restrict__ dst) {
    int e = blockIdx.x * blockDim.x + threadIdx.x;
    if (e < EN) atomicAdd(&g_cnt[dst[e]], 1);
}

__global__ void __launch_bounds__(1024) scan_kernel() {
    __shared__ int part[1024];
    const int CH = 49;
    int t = threadIdx.x;
    int beg = t * CH, end = min(beg + CH, NN);
    int s = 0;
    for (int i = beg; i < end; i++) s += g_cnt[i];
    part[t] = s;
    __syncthreads();
    for (int off = 1; off < 1024; off <<= 1) {
        int v = (t >= off) ? part[t - off] : 0;
        __syncthreads();
        part[t] += v;
        __syncthreads();
    }
    int run = (t == 0) ? 0 : part[t - 1];
    for (int i = beg; i < end; i++) {
        g_rp[i] = run; g_woff[i] = run; run += g_cnt[i];
        g_cnt[i] = 0;
    }
    if (t == 1023) g_rp[NN] = part[1023];
}

__global__ void __launch_bounds__(256) place(const int* __restrict__ src,
                                             const int* __restrict__ dst) {
    int e = blockIdx.x * blockDim.x + threadIdx.x;
    if (e >= EN) return;
    int p = atomicAdd(&g_woff[dst[e]], 1);
    g_srcp[p] = src[e];
    g_eid[p] = e;
}

__global__ void __launch_bounds__(256) init_h(const int* __restrict__ nt,
                                              const float* __restrict__ atom_emb) {
    int idx = blockIdx.x * blockDim.x + threadIdx.x;
    if (idx >= NN * 64) return;
    int n = idx >> 6, q = idx & 63;
    ((float4*)g_h)[idx] = ((const float4*)atom_emb)[nt[n] * 64 + q];
}

// ---------------- gather ----------------------------------------------------
__global__ void __launch_bounds__(256) gather() {
    int warp = threadIdx.x >> 5, lane = threadIdx.x & 31;
    int n = blockIdx.x * 8 + warp;
    if (n >= NN) return;
    int q = lane * 8;
    float4 a0 = make_float4(0.f, 0.f, 0.f, 0.f), a1 = a0;
    int beg = g_rp[n], end = g_rp[n + 1];
    for (int p = beg; p < end; p++) {
        int s = g_srcp[p];
        int e = g_eid[p];
        const float4* hp = (const float4*)&g_h[s * H + q];
        const float4* bp = (const float4*)&g_bond[(size_t)e * H + q];
        float4 h0 = hp[0], h1v = hp[1], b0 = bp[0], b1v = bp[1];
        a0.x += fmaxf(h0.x + b0.x, 0.f);  a0.y += fmaxf(h0.y + b0.y, 0.f);
        a0.z += fmaxf(h0.z + b0.z, 0.f);  a0.w += fmaxf(h0.w + b0.w, 0.f);
        a1.x += fmaxf(h1v.x + b1v.x, 0.f); a1.y += fmaxf(h1v.y + b1v.y, 0.f);
        a1.z += fmaxf(h1v.z + b1v.z, 0.f); a1.w += fmaxf(h1v.w + b1v.w, 0.f);
    }
    float4* ap = (float4*)&g_aggr[n * H + q];
    ap[0] = a0; ap[1] = a1;
}

// ---------------- edge_bond: reg-A + paired B, 128 thr, grid(2, EB) ---------
#define EB_SMEM ((2 * B128SZ + 128 + 128 + 128 + 2 * H) * 4)

__global__ void __launch_bounds__(128, 2)
edge_bond(const float* __restrict__ elen, const int* __restrict__ src,
          const int* __restrict__ batch, const int* __restrict__ etype,
          const float* __restrict__ W1, const float* __restrict__ b1,
          const float* __restrict__ W2, const float* __restrict__ b2,
          const float* __restrict__ bond_emb) {
    extern __shared__ float sm[];
    float* Bs = sm;                       // 2*B128SZ
    float* xS = Bs + 2 * B128SZ;
    float* tS = xS + 128;
    int*   eS = (int*)(tS + 128);
    float* w1S = (float*)(eS + 128);
    float* b1S = w1S + H;

    int tid = threadIdx.x, lane = tid & 31, warp = tid >> 5;
    int wy = warp >> 1, wx = warp & 1;
    int g = lane >> 2, t4 = lane & 3;
    int m0 = blockIdx.y * 128, n0 = blockIdx.x * 128;

    {
        int e = m0 + tid;
        float x = 0.f, tb = 0.f; int et = 0;
        if (e < EN) {
            x = elen[e];
            int gph = batch[src[e]];
            tb = g_temb[gph];
            if (n0 == 0) g_einv[e] = g_invstd[gph];
            et = etype[e];
        }
        xS[tid] = x; tS[tid] = tb; eS[tid] = et;
    }
    w1S[tid] = W1[tid];         w1S[tid + 128] = W1[tid + 128];
    b1S[tid] = b1[tid];         b1S[tid + 128] = b1[tid + 128];
    __syncthreads();

    float xr[4][2];
#pragma unroll
    for (int mt = 0; mt < 4; mt++) {
        xr[mt][0] = xS[wy * 64 + mt * 16 + g];
        xr[mt][1] = xS[wy * 64 + mt * 16 + g + 8];
    }

    float breg[16];
    load_w128(breg, W2, H, 0, n0, tid);
    store_w128p(Bs, breg, tid);
    __syncthreads();

    float acc[4][8][4] = {};
    for (int s = 0; s < 16; s++) {
        int cur = s & 1, nxt = cur ^ 1;
        if (s < 15) load_w128(breg, W2, H, (s + 1) * 16, n0, tid);
        const float* B = Bs + cur * B128SZ;
#pragma unroll
        for (int kh = 0; kh < 16; kh += 8) {
            int kA = s * 16 + kh;
            float w0 = w1S[kA + t4], w4 = w1S[kA + t4 + 4];
            float c0 = b1S[kA + t4], c4 = b1S[kA + t4 + 4];
            float a[4][4];
#pragma unroll
            for (int mt = 0; mt < 4; mt++) {
                a[mt][0] = totf(fmaxf(fmaf(xr[mt][0], w0, c0), 0.f));
                a[mt][1] = totf(fmaxf(fmaf(xr[mt][1], w0, c0), 0.f));
                a[mt][2] = totf(fmaxf(fmaf(xr[mt][0], w4, c4), 0.f));
                a[mt][3] = totf(fmaxf(fmaf(xr[mt][1], w4, c4), 0.f));
            }
            int ks = (kh >> 3) * 4 + t4;
#pragma unroll
            for (int nt = 0; nt < 8; nt++) {
                int cn = wx * 64 + nt * 8 + g;
                float2 b = *(const float2*)&B[ks * B128P + cn * 2];
#pragma unroll
                for (int mt = 0; mt < 4; mt++)
                    mma1(acc[mt][nt], a[mt][0], a[mt][1], a[mt][2], a[mt][3], b.x, b.y);
            }
        }
        if (s < 15) {
            store_w128p(Bs + nxt * B128SZ, breg, tid);
            __syncthreads();
        }
    }

#pragma unroll
    for (int mt = 0; mt < 4; mt++)
#pragma unroll
        for (int half = 0; half < 2; half++) {
            int rl = wy * 64 + mt * 16 + g + half * 8;
            int row = m0 + rl;
            if (row >= EN) continue;
            float tb = tS[rl];
            const float* bep = &bond_emb[eS[rl] * H];
            size_t obase = (size_t)row * H;
#pragma unroll
            for (int nt = 0; nt < 8; nt++) {
                int col = n0 + wx * 64 + nt * 8 + 2 * t4;
                float v0 = (acc[mt][nt][half * 2 + 0] + b2[col] + tb) * bep[col];
                float v1 = (acc[mt][nt][half * 2 + 1] + b2[col + 1] + tb) * bep[col + 1];
                *(float2*)&g_bond[obase + col] = make_float2(v0, v1);
            }
        }
}

// ---------------- GIN GEMMs: 64x256 paired, 128 thr, 2 CTA/SM ---------------
#define GIN_SMEM ((2 * A64SZ + 2 * B256SZ) * 4)
template <int MODE>
__global__ void __launch_bounds__(128, 2)
gin_mma(const float* __restrict__ W, const float* __restrict__ bias, int reluOut) {
    extern __shared__ float sm[];
    float* As = sm;                 // 2*A64SZ
    float* Bs = sm + 2 * A64SZ;     // 2*B256SZ
    int tid = threadIdx.x, lane = tid & 31, warp = tid >> 5;
    int wx = warp;
    int m0 = blockIdx.x * 64;
    int r = tid & 63, kh = (tid >> 6) * 8;
    int arow = m0 + r;
    bool valid = (arow < NN);
    const float* A1 = (MODE == 0) ? g_h : g_tmp;

    float areg[8], breg[32];
    auto loadA = [&](int k0) {
        if (valid) {
            const float* p = &A1[arow * H + k0 + kh];
            float4 v0 = *(const float4*)p, v1 = *(const float4*)(p + 4);
            areg[0] = v0.x; areg[1] = v0.y; areg[2] = v0.z; areg[3] = v0.w;
            areg[4] = v1.x; areg[5] = v1.y; areg[6] = v1.z; areg[7] = v1.w;
            if (MODE == 0) {
                const float* q = &g_aggr[arow * H + k0 + kh];
                float4 w0 = *(const float4*)q, w1 = *(const float4*)(q + 4);
                areg[0] += w0.x; areg[1] += w0.y; areg[2] += w0.z; areg[3] += w0.w;
                areg[4] += w1.x; areg[5] += w1.y; areg[6] += w1.z; areg[7] += w1.w;
            }
        } else {
#pragma unroll
            for (int i = 0; i < 8; i++) areg[i] = 0.f;
        }
    };

    loadA(0);
    load_w256h(breg, W, H, 0, tid);
    store_a8p(As, kh, r, areg);
    store_w256p(Bs, breg, tid);
    __syncthreads();

    float acc[4][8][4] = {};
    for (int s = 0; s < 16; s++) {
        int cur = s & 1, nxt = cur ^ 1;
        if (s < 15) { loadA((s + 1) * 16); load_w256h(breg, W, H, (s + 1) * 16, tid); }
        mma_k8p64(acc, As + cur * A64SZ, Bs + cur * B256SZ, 0, wx, lane);
        mma_k8p64(acc, As + cur * A64SZ, Bs + cur * B256SZ, 8, wx, lane);
        if (s < 15) {
            store_a8p(As + nxt * A64SZ, kh, r, areg);
            store_w256p(Bs + nxt * B256SZ, breg, tid);
            __syncthreads();
        }
    }

    int g = lane >> 2, t4 = lane & 3;
#pragma unroll
    for (int mt = 0; mt < 4; mt++)
#pragma unroll
        for (int half = 0; half < 2; half++) {
            int row = m0 + mt * 16 + g + half * 8;
            if (row >= NN) continue;
#pragma unroll
            for (int nt = 0; nt < 8; nt++) {
                int col = wx * 64 + nt * 8 + 2 * t4;
                float v0 = acc[mt][nt][half * 2 + 0] + bias[col];
                float v1 = acc[mt][nt][half * 2 + 1] + bias[col + 1];
                if (reluOut) { v0 = fmaxf(v0, 0.f); v1 = fmaxf(v1, 0.f); }
                if (MODE == 0) {
                    *(float2*)&g_tmp[row * H + col] = make_float2(v0, v1);
                } else {
                    float2 rh = *(const float2*)&g_h[row * H + col];
                    *(float2*)&g_h[row * H + col] = make_float2(v0 + rh.x, v1 + rh.y);
                }
            }
        }
}

// ---------------- out1: K=512, 64x256 paired, 128 thr, 2 CTA/SM -------------
#define OUT1_SMEM ((2 * A64SZ + 2 * B256SZ + 128) * 4)
__global__ void __launch_bounds__(128, 2)
out1(const int* __restrict__ src, const int* __restrict__ dst,
     const float* __restrict__ W1, const float* __restrict__ b1) {
    extern __shared__ float sm[];
    float* As = sm;
    float* Bs = sm + 2 * A64SZ;
    int* srcS = (int*)(Bs + 2 * B256SZ);  // 64
    int* dstS = srcS + 64;                // 64
    int tid = threadIdx.x, lane = tid & 31, warp = tid >> 5;
    int wx = warp;
    int m0 = blockIdx.x * 64;

    if (tid < 64) {
        int e = m0 + tid;
        int s = 0, d = 0;
        if (e < EN) { s = src[e]; d = dst[e]; }
        srcS[tid] = s; dstS[tid] = d;
    }
    __syncthreads();

    int r = tid & 63, kh = (tid >> 6) * 8;
    int e = m0 + r;
    bool valid = (e < EN);
    float areg[8], breg[32];

    auto loadA = [&](int k0) {
        if (k0 < 256) {
            const float* hs = &g_h[srcS[r] * H + k0 + kh];
            const float* hd = &g_h[dstS[r] * H + k0 + kh];
            float4 a0 = *(const float4*)hs, a1 = *(const float4*)(hs + 4);
            float4 c0 = *(const float4*)hd, c1 = *(const float4*)(hd + 4);
            areg[0] = a0.x * c0.x; areg[1] = a0.y * c0.y;
            areg[2] = a0.z * c0.z; areg[3] = a0.w * c0.w;
            areg[4] = a1.x * c1.x; areg[5] = a1.y * c1.y;
            areg[6] = a1.z * c1.z; areg[7] = a1.w * c1.w;
        } else if (valid) {
            const float* bp = &g_bond[(size_t)e * H + (k0 - 256) + kh];
            float4 v0 = *(const float4*)bp, v1 = *(const float4*)(bp + 4);
            areg[0] = v0.x; areg[1] = v0.y; areg[2] = v0.z; areg[3] = v0.w;
            areg[4] = v1.x; areg[5] = v1.y; areg[6] = v1.z; areg[7] = v1.w;
        } else {
#pragma unroll
            for (int i = 0; i < 8; i++) areg[i] = 0.f;
        }
    };

    loadA(0);
    load_w256h(breg, W1, H, 0, tid);
    store_a8p(As, kh, r, areg);
    store_w256p(Bs, breg, tid);
    __syncthreads();

    float acc[4][8][4] = {};
    for (int s = 0; s < 32; s++) {
        int cur = s & 1, nxt = cur ^ 1;
        if (s < 31) { loadA((s + 1) * 16); load_w256h(breg, W1, H, (s + 1) * 16, tid); }
        mma_k8p64(acc, As + cur * A64SZ, Bs + cur * B256SZ, 0, wx, lane);
        mma_k8p64(acc, As + cur * A64SZ, Bs + cur * B256SZ, 8, wx, lane);
        if (s < 31) {
            store_a8p(As + nxt * A64SZ, kh, r, areg);
            store_w256p(Bs + nxt * B256SZ, breg, tid);
            __syncthreads();
        }
    }

    int g = lane >> 2, t4 = lane & 3;
#pragma unroll
    for (int mt = 0; mt < 4; mt++)
#pragma unroll
        for (int half = 0; half < 2; half++) {
            int row = m0 + mt * 16 + g + half * 8;
            if (row >= EN) continue;
#pragma unroll
            for (int nt = 0; nt < 8; nt++) {
                int col = wx * 64 + nt * 8 + 2 * t4;
                float v0 = fmaxf(acc[mt][nt][half * 2 + 0] + b1[col], 0.f);
                float v1 = fmaxf(acc[mt][nt][half * 2 + 1] + b1[col + 1], 0.f);
                *(float2*)&g_h1[(size_t)row * H + col] = make_float2(v0, v1);
            }
        }
}

// ---------------- out23 fused: unchanged (old layout, static smem) ----------
__global__ void __launch_bounds__(128, 2)
out23(const float* __restrict__ W2, const float* __restrict__ b2,
      const float* __restrict__ W3, const float* __restrict__ b3,
      float* __restrict__ out) {
    __shared__ float As[2 * ASZ], Bs[2 * BSZ1];
    __shared__ float red[128 * 8];
    __shared__ float b2S[128], w3S[128];
    int tid = threadIdx.x, lane = tid & 31, warp = tid >> 5;
    int wy = warp >> 1, wx = warp & 1;
    int m0 = blockIdx.x * 128;

    b2S[tid] = b2[tid]; w3S[tid] = W3[tid];

    int e = m0 + tid;
    bool valid = (e < EN);
    float areg[16], breg[16];
    auto loadA = [&](int k0) {
        if (valid) {
            const float* p = &g_h1[(size_t)e * H + k0];
#pragma unroll
            for (int j = 0; j < 4; j++) {
                float4 v = *(const float4*)(p + 4 * j);
                areg[4 * j] = v.x; areg[4 * j + 1] = v.y;
                areg[4 * j + 2] = v.z; areg[4 * j + 3] = v.w;
            }
        } else {
#pragma unroll
            for (int i = 0; i < 16; i++) areg[i] = 0.f;
        }
    };

    loadA(0);
    load_w128(breg, W2, 128, 0, 0, tid);
    store_a16(As, tid, areg);
    store_w128(Bs, breg, tid);
    __syncthreads();

    float acc[4][8][4] = {};
    for (int s = 0; s < 16; s++) {
        int cur = s & 1, nxt = cur ^ 1;
        if (s < 15) { loadA((s + 1) * 16); load_w128(breg, W2, 128, (s + 1) * 16, 0, tid); }
        mma_k8w<PB1>(acc, As + cur * ASZ, Bs + cur * BSZ1, 0, wy, wx, lane);
        mma_k8w<PB1>(acc, As + cur * ASZ, Bs + cur * BSZ1, 8, wy, wx, lane);
        if (s < 15) {
            store_a16(As + nxt * ASZ, tid, areg);
            store_w128(Bs + nxt * BSZ1, breg, tid);
            __syncthreads();
        }
    }

    int g = lane >> 2, t4 = lane & 3;
#pragma unroll
    for (int mt = 0; mt < 4; mt++)
#pragma unroll
        for (int half = 0; half < 2; half++) {
            int rl = wy * 64 + mt * 16 + g + half * 8;
            float partial = 0.f;
#pragma unroll
            for (int nt = 0; nt < 8; nt++) {
                int col = wx * 64 + nt * 8 + 2 * t4;
                float h0 = fmaxf(acc[mt][nt][half * 2 + 0] + b2S[col], 0.f);
                float h1 = fmaxf(acc[mt][nt][half * 2 + 1] + b2S[col + 1], 0.f);
                partial += h0 * w3S[col] + h1 * w3S[col + 1];
            }
            red[rl * 8 + wx * 4 + t4] = partial;
        }
    __syncthreads();

    if (valid) {
        float s = 0.f;
#pragma unroll
        for (int i = 0; i < 8; i++) s += red[tid * 8 + i];
        out[e] = (s + b3[0]) * g_einv[e];
    }
}

// ---------------- launch ----------------------------------------------------
extern "C" void kernel_launch(void* const* d_in, const int* in_sizes, int n_in,
                              void* d_out, int out_size) {
    const int*   node_type = (const int*)d_in[0];
    const int*   edge_type = (const int*)d_in[1];
    const int*   edge_index = (const int*)d_in[2];
    const int*   batch = (const int*)d_in[3];
    const float* elen = (const float*)d_in[4];
    const float* t = (const float*)d_in[5];
    const float* atom_emb = (const float*)d_in[6];
    const float* bond_emb = (const float*)d_in[7];
    const float* in_W1 = (const float*)d_in[8];
    const float* in_b1 = (const float*)d_in[9];
    const float* in_W2 = (const float*)d_in[10];
    const float* in_b2 = (const float*)d_in[11];
    const float* fourier_W = (const float*)d_in[12];
    const float* temb_W = (const float*)d_in[13];
    const float* temb_b = (const float*)d_in[14];
    const float* d1W = (const float*)d_in[15];
    const float* d1b = (const float*)d_in[16];
    const float* gin_W1 = (const float*)d_in[17];
    const float* gin_b1 = (const float*)d_in[18];
    const float* gin_W2 = (const float*)d_in[19];
    const float* gin_b2 = (const float*)d_in[20];
    const float* out_W1 = (const float*)d_in[21];
    const float* out_b1 = (const float*)d_in[22];
    const float* out_W2 = (const float*)d_in[23];
    const float* out_b2 = (const float*)d_in[24];
    const float* out_W3 = (const float*)d_in[25];
    const float* out_b3 = (const float*)d_in[26];
    const int* src = edge_index;
    const int* dst = edge_index + EN;
    float* out = (float*)d_out;

    const int EB = (EN + 127) / 128;      // 2344
    const int EB64 = (EN + 63) / 64;      // 4688
    const int NB64 = (NN + 63) / 64;      // 782

    static int attr_done = 0;
    if (!attr_done) {
        cudaFuncSetAttribute(edge_bond, cudaFuncAttributeMaxDynamicSharedMemorySize, EB_SMEM);
        cudaFuncSetAttribute(gin_mma<0>, cudaFuncAttributeMaxDynamicSharedMemorySize, GIN_SMEM);
        cudaFuncSetAttribute(gin_mma<1>, cudaFuncAttributeMaxDynamicSharedMemorySize, GIN_SMEM);
        cudaFuncSetAttribute(out1, cudaFuncAttributeMaxDynamicSharedMemorySize, OUT1_SMEM);
        attr_done = 1;
    }

    // launch order chosen so ncu (launch index 3) profiles edge_bond
    temb_fused<<<GN, 128>>>(t, fourier_W, temb_W, temb_b, d1W, d1b);      // 0
    hist<<<(EN + 255) / 256, 256>>>(dst);                                 // 1
    scan_kernel<<<1, 1024>>>();                                           // 2
    edge_bond<<<dim3(2, EB), 128, EB_SMEM>>>(elen, src, batch, edge_type, // 3
                                             in_W1, in_b1, in_W2, in_b2, bond_emb);
    place<<<(EN + 255) / 256, 256>>>(src, dst);                           // 4
    init_h<<<(NN * 64 + 255) / 256, 256>>>(node_type, atom_emb);          // 5

    for (int c = 0; c < NCONV; c++) {
        gather<<<(NN + 7) / 8, 256>>>();
        gin_mma<0><<<NB64, 128, GIN_SMEM>>>(gin_W1 + c * H * H, gin_b1 + c * H, 1);
        gin_mma<1><<<NB64, 128, GIN_SMEM>>>(gin_W2 + c * H * H, gin_b2 + c * H,
                                            (c < NCONV - 1) ? 1 : 0);
    }

    out1<<<EB64, 128, OUT1_SMEM>>>(src, dst, out_W1, out_b1);
    out23<<<EB, 128>>>(out_W2, out_b2, out_W3, out_b3, out);
}

// round 15
// speedup vs baseline: 1.1313x; 1.0185x over previous
#include <cuda_runtime.h>
#include <math.h>
#include <stdint.h>

#define EN 300000
#define NN 50000
#define GN 1024
#define H  256
#define NCONV 4
// old-style strides (out23)
#define PA 136
#define PB1 136
#define ASZ (16 * PA)
#define BSZ1 (16 * PB1)
// paired-fragment layout constants
#define A64P 136            // A 64-row paired: k*136 + rpos   (136 mod 32 == 8)
#define A64SZ (16 * A64P)
#define B256P 520           // B 256-wide paired: slot*520 + n*2 + half
#define B256SZ (8 * B256P)
#define B128P 264           // B 128-wide paired
#define B128SZ (8 * B128P)

// ---------------- scratch (device globals) ---------------------------------
static __device__ float g_bond[(size_t)EN * H];   // DST-SORTED rows
static __device__ float g_h1[(size_t)EN * H];
static __device__ float g_h[NN * H];
static __device__ float g_aggr[NN * H];
static __device__ float g_tmp[NN * H];
static __device__ float g_temb[GN];
static __device__ float g_invstd[GN];
static __device__ float g_einv[EN];
static __device__ int g_cnt[NN];
static __device__ int g_rp[NN + 1];
static __device__ int g_woff[NN];
static __device__ int g_srcp[EN];     // sorted pos -> src node
static __device__ int g_pos[EN];      // edge -> sorted pos

// ---------------- helpers ---------------------------------------------------
__device__ __forceinline__ float totf(float x) {
    uint32_t u; asm("cvt.rna.tf32.f32 %0, %1;" : "=r"(u) : "f"(x));
    return __uint_as_float(u);
}

__device__ __forceinline__ void mma1(float acc[4],
                                     float a0, float a1, float a2, float a3,
                                     float b0, float b1) {
    asm volatile(
        "mma.sync.aligned.m16n8k8.row.col.f32.tf32.tf32.f32 "
        "{%0,%1,%2,%3}, {%4,%5,%6,%7}, {%8,%9}, {%0,%1,%2,%3};\n"
        : "+f"(acc[0]), "+f"(acc[1]), "+f"(acc[2]), "+f"(acc[3])
        : "r"(__float_as_uint(a0)), "r"(__float_as_uint(a1)),
          "r"(__float_as_uint(a2)), "r"(__float_as_uint(a3)),
          "r"(__float_as_uint(b0)), "r"(__float_as_uint(b1)));
}

// old-style warp 64x64 (out23)
template <int BS>
__device__ __forceinline__ void mma_k8w(float acc[4][8][4],
                                        const float* As, const float* Bs,
                                        int kk, int wy, int wx, int lane) {
    int g = lane >> 2, t4 = lane & 3;
    float a[4][4];
#pragma unroll
    for (int mt = 0; mt < 4; mt++) {
        int rm = wy * 64 + mt * 16 + g;
        a[mt][0] = As[(kk + t4) * PA + rm];
        a[mt][1] = As[(kk + t4) * PA + rm + 8];
        a[mt][2] = As[(kk + t4 + 4) * PA + rm];
        a[mt][3] = As[(kk + t4 + 4) * PA + rm + 8];
    }
#pragma unroll
    for (int nt = 0; nt < 8; nt++) {
        int cn = wx * 64 + nt * 8 + g;
        float b0 = Bs[(kk + t4) * BS + cn];
        float b1 = Bs[(kk + t4 + 4) * BS + cn];
#pragma unroll
        for (int mt = 0; mt < 4; mt++)
            mma1(acc[mt][nt], a[mt][0], a[mt][1], a[mt][2], a[mt][3], b0, b1);
    }
}

// paired-fragment warp 64x64: A 64-row paired, B 256-wide paired
__device__ __forceinline__ void mma_k8p64(float acc[4][8][4],
                                          const float* As, const float* Bs,
                                          int kk, int wx, int lane) {
    int g = lane >> 2, t4 = lane & 3;
    int ks = (kk >> 3) * 4 + t4;
    float2 a01[4], a23[4];
#pragma unroll
    for (int mt = 0; mt < 4; mt++) {
        a01[mt] = *(const float2*)&As[(kk + t4) * A64P + (mt * 8 + g) * 2];
        a23[mt] = *(const float2*)&As[(kk + t4 + 4) * A64P + (mt * 8 + g) * 2];
    }
#pragma unroll
    for (int nt = 0; nt < 8; nt++) {
        int cn = wx * 64 + nt * 8 + g;
        float2 b = *(const float2*)&Bs[ks * B256P + cn * 2];
#pragma unroll
        for (int mt = 0; mt < 4; mt++)
            mma1(acc[mt][nt], a01[mt].x, a01[mt].y, a23[mt].x, a23[mt].y, b.x, b.y);
    }
}

// ---- loaders / storers ----
__device__ __forceinline__ void load_w256h(float v[32], const float* __restrict__ W,
                                           int ldw, int k0, int tid) {
    const float* p = &W[(size_t)k0 * ldw + tid];
#pragma unroll
    for (int k = 0; k < 16; k++) {
        v[k] = p[(size_t)k * ldw];
        v[16 + k] = p[(size_t)k * ldw + 128];
    }
}
__device__ __forceinline__ void store_w256p(float* Bs, const float v[32], int tid) {
#pragma unroll
    for (int s8 = 0; s8 < 2; s8++)
#pragma unroll
        for (int t4 = 0; t4 < 4; t4++) {
            int slot = s8 * 4 + t4;
            *(float2*)&Bs[slot * B256P + tid * 2] =
                make_float2(totf(v[s8 * 8 + t4]), totf(v[s8 * 8 + t4 + 4]));
            *(float2*)&Bs[slot * B256P + (tid + 128) * 2] =
                make_float2(totf(v[16 + s8 * 8 + t4]), totf(v[16 + s8 * 8 + t4 + 4]));
        }
}
__device__ __forceinline__ void load_w128(float v[16], const float* __restrict__ W,
                                          int ldw, int k0, int n0, int tid) {
    const float* p = &W[(size_t)k0 * ldw + n0 + tid];
#pragma unroll
    for (int k = 0; k < 16; k++) v[k] = p[(size_t)k * ldw];
}
__device__ __forceinline__ void store_w128p(float* Bs, const float v[16], int tid) {
#pragma unroll
    for (int s8 = 0; s8 < 2; s8++)
#pragma unroll
        for (int t4 = 0; t4 < 4; t4++)
            *(float2*)&Bs[(s8 * 4 + t4) * B128P + tid * 2] =
                make_float2(totf(v[s8 * 8 + t4]), totf(v[s8 * 8 + t4 + 4]));
}
__device__ __forceinline__ void store_w128(float* Bs, const float v[16], int tid) {
#pragma unroll
    for (int k = 0; k < 16; k++) Bs[k * PB1 + tid] = totf(v[k]);
}
__device__ __forceinline__ void store_a8p(float* As, int kh, int r, const float v[8]) {
    int rpos = ((r >> 4) * 8 + (r & 7)) * 2 + ((r >> 3) & 1);
#pragma unroll
    for (int i = 0; i < 8; i++) As[(kh + i) * A64P + rpos] = totf(v[i]);
}
__device__ __forceinline__ void store_a16(float* As, int r, const float v[16]) {
#pragma unroll
    for (int k = 0; k < 16; k++) As[k * PA + r] = totf(v[k]);
}

// ---------------- temb (comb fused) -----------------------------------------
__global__ void __launch_bounds__(128)
temb_fused(const float* __restrict__ t, const float* __restrict__ fw,
           const float* __restrict__ tW, const float* __restrict__ tb,
           const float* __restrict__ d1W, const float* __restrict__ d1b) {
    __shared__ float d1S[H], combS[H + 1], red[128];
    int tid = threadIdx.x, lane = tid & 31, warp = tid >> 5;
    d1S[tid] = d1W[tid]; d1S[tid + 128] = d1W[tid + 128];
    __syncthreads();
    for (int row = warp; row < H + 1; row += 4) {
        const float* p = (row < H) ? &tW[(size_t)row * H] : tb;
        float s = 0.f;
        for (int k = lane; k < H; k += 32) s += p[k] * d1S[k];
#pragma unroll
        for (int o = 16; o; o >>= 1) s += __shfl_down_sync(0xffffffffu, s, o);
        if (lane == 0) combS[row] = (row == H) ? s + d1b[0] : s;
    }
    __syncthreads();
    int g = blockIdx.x;
    float tt = t[g];
    float xp = tt * fw[tid] * 6.283185307179586f;
    red[tid] = sinf(xp) * combS[tid] + cosf(xp) * combS[128 + tid];
    __syncthreads();
    for (int s = 64; s > 0; s >>= 1) {
        if (tid < s) red[tid] += red[tid + s];
        __syncthreads();
    }
    if (tid == 0) {
        g_temb[g] = red[0] + combS[H];
        const float LS = 3.2188758248682006f;   // ln(25)
        float var = (expf(2.f * tt * LS) - 1.f) / (2.f * LS);
        g_invstd[g] = rsqrtf(var);
    }
}

// ---------------- sort machinery ---------------------------------------------
__global__ void __launch_bounds__(256) hist(const int* __restrict__ dst) {
    int e = blockIdx.x * blockDim.x + threadIdx.x;
    if (e < EN) atomicAdd(&g_cnt[dst[e]], 1);
}

__global__ void __launch_bounds__(1024) scan_kernel() {
    __shared__ int part[1024];
    const int CH = 49;
    int t = threadIdx.x;
    int beg = t * CH, end = min(beg + CH, NN);
    int s = 0;
    for (int i = beg; i < end; i++) s += g_cnt[i];
    part[t] = s;
    __syncthreads();
    for (int off = 1; off < 1024; off <<= 1) {
        int v = (t >= off) ? part[t - off] : 0;
        __syncthreads();
        part[t] += v;
        __syncthreads();
    }
    int run = (t == 0) ? 0 : part[t - 1];
    for (int i = beg; i < end; i++) {
        g_rp[i] = run; g_woff[i] = run; run += g_cnt[i];
        g_cnt[i] = 0;
    }
    if (t == 1023) g_rp[NN] = part[1023];
}

__global__ void __launch_bounds__(256) place(const int* __restrict__ src,
                                             const int* __restrict__ dst) {
    int e = blockIdx.x * blockDim.x + threadIdx.x;
    if (e >= EN) return;
    int p = atomicAdd(&g_woff[dst[e]], 1);
    g_pos[e] = p;
    g_srcp[p] = src[e];
}

__global__ void __launch_bounds__(256) init_h(const int* __restrict__ nt,
                                              const float* __restrict__ atom_emb) {
    int idx = blockIdx.x * blockDim.x + threadIdx.x;
    if (idx >= NN * 64) return;
    int n = idx >> 6, q = idx & 63;
    ((float4*)g_h)[idx] = ((const float4*)atom_emb)[nt[n] * 64 + q];
}

// ---------------- gather: aggr[n] = h[n] + sum relu(h[src]+bond) ------------
// bond rows are dst-sorted -> sequential streaming over g_bond
__global__ void __launch_bounds__(256) gather() {
    int warp = threadIdx.x >> 5, lane = threadIdx.x & 31;
    int n = blockIdx.x * 8 + warp;
    if (n >= NN) return;
    int q = lane * 8;
    float4 a0 = make_float4(0.f, 0.f, 0.f, 0.f), a1 = a0;
    int beg = g_rp[n], end = g_rp[n + 1];
    for (int p = beg; p < end; p++) {
        int s = g_srcp[p];
        const float4* hp = (const float4*)&g_h[s * H + q];
        const float4* bp = (const float4*)&g_bond[(size_t)p * H + q];
        float4 h0 = hp[0], h1v = hp[1], b0 = bp[0], b1v = bp[1];
        a0.x += fmaxf(h0.x + b0.x, 0.f);  a0.y += fmaxf(h0.y + b0.y, 0.f);
        a0.z += fmaxf(h0.z + b0.z, 0.f);  a0.w += fmaxf(h0.w + b0.w, 0.f);
        a1.x += fmaxf(h1v.x + b1v.x, 0.f); a1.y += fmaxf(h1v.y + b1v.y, 0.f);
        a1.z += fmaxf(h1v.z + b1v.z, 0.f); a1.w += fmaxf(h1v.w + b1v.w, 0.f);
    }
    // fold residual input: aggr = h[n] + sum
    const float4* hn = (const float4*)&g_h[n * H + q];
    float4 n0v = hn[0], n1v = hn[1];
    a0.x += n0v.x; a0.y += n0v.y; a0.z += n0v.z; a0.w += n0v.w;
    a1.x += n1v.x; a1.y += n1v.y; a1.z += n1v.z; a1.w += n1v.w;
    float4* ap = (float4*)&g_aggr[n * H + q];
    ap[0] = a0; ap[1] = a1;
}

// ---------------- edge_bond: reg-A + paired B, writes SORTED rows -----------
#define EB_SMEM ((2 * B128SZ + 128 + 128 + 128 + 128 + 2 * H) * 4)

__global__ void __launch_bounds__(128, 2)
edge_bond(const float* __restrict__ elen, const int* __restrict__ src,
          const int* __restrict__ batch, const int* __restrict__ etype,
          const float* __restrict__ W1, const float* __restrict__ b1,
          const float* __restrict__ W2, const float* __restrict__ b2,
          const float* __restrict__ bond_emb) {
    extern __shared__ float sm[];
    float* Bs = sm;                       // 2*B128SZ
    float* xS = Bs + 2 * B128SZ;
    float* tS = xS + 128;
    int*   eS = (int*)(tS + 128);
    int*   pS = eS + 128;
    float* w1S = (float*)(pS + 128);
    float* b1S = w1S + H;

    int tid = threadIdx.x, lane = tid & 31, warp = tid >> 5;
    int wy = warp >> 1, wx = warp & 1;
    int g = lane >> 2, t4 = lane & 3;
    int m0 = blockIdx.y * 128, n0 = blockIdx.x * 128;

    {
        int e = m0 + tid;
        float x = 0.f, tb = 0.f; int et = 0, ps = 0;
        if (e < EN) {
            x = elen[e];
            int gph = batch[src[e]];
            tb = g_temb[gph];
            if (n0 == 0) g_einv[e] = g_invstd[gph];
            et = etype[e];
            ps = g_pos[e];
        }
        xS[tid] = x; tS[tid] = tb; eS[tid] = et; pS[tid] = ps;
    }
    w1S[tid] = W1[tid];         w1S[tid + 128] = W1[tid + 128];
    b1S[tid] = b1[tid];         b1S[tid + 128] = b1[tid + 128];
    __syncthreads();

    float xr[4][2];
#pragma unroll
    for (int mt = 0; mt < 4; mt++) {
        xr[mt][0] = xS[wy * 64 + mt * 16 + g];
        xr[mt][1] = xS[wy * 64 + mt * 16 + g + 8];
    }

    float breg[16];
    load_w128(breg, W2, H, 0, n0, tid);
    store_w128p(Bs, breg, tid);
    __syncthreads();

    float acc[4][8][4] = {};
    for (int s = 0; s < 16; s++) {
        int cur = s & 1, nxt = cur ^ 1;
        if (s < 15) load_w128(breg, W2, H, (s + 1) * 16, n0, tid);
        const float* B = Bs + cur * B128SZ;
#pragma unroll
        for (int kh = 0; kh < 16; kh += 8) {
            int kA = s * 16 + kh;
            float w0 = w1S[kA + t4], w4 = w1S[kA + t4 + 4];
            float c0 = b1S[kA + t4], c4 = b1S[kA + t4 + 4];
            float a[4][4];
#pragma unroll
            for (int mt = 0; mt < 4; mt++) {
                a[mt][0] = totf(fmaxf(fmaf(xr[mt][0], w0, c0), 0.f));
                a[mt][1] = totf(fmaxf(fmaf(xr[mt][1], w0, c0), 0.f));
                a[mt][2] = totf(fmaxf(fmaf(xr[mt][0], w4, c4), 0.f));
                a[mt][3] = totf(fmaxf(fmaf(xr[mt][1], w4, c4), 0.f));
            }
            int ks = (kh >> 3) * 4 + t4;
#pragma unroll
            for (int nt = 0; nt < 8; nt++) {
                int cn = wx * 64 + nt * 8 + g;
                float2 b = *(const float2*)&B[ks * B128P + cn * 2];
#pragma unroll
                for (int mt = 0; mt < 4; mt++)
                    mma1(acc[mt][nt], a[mt][0], a[mt][1], a[mt][2], a[mt][3], b.x, b.y);
            }
        }
        if (s < 15) {
            store_w128p(Bs + nxt * B128SZ, breg, tid);
            __syncthreads();
        }
    }

#pragma unroll
    for (int mt = 0; mt < 4; mt++)
#pragma unroll
        for (int half = 0; half < 2; half++) {
            int rl = wy * 64 + mt * 16 + g + half * 8;
            int row = m0 + rl;
            if (row >= EN) continue;
            float tb = tS[rl];
            const float* bep = &bond_emb[eS[rl] * H];
            size_t obase = (size_t)pS[rl] * H;          // sorted position
#pragma unroll
            for (int nt = 0; nt < 8; nt++) {
                int col = n0 + wx * 64 + nt * 8 + 2 * t4;
                float v0 = (acc[mt][nt][half * 2 + 0] + b2[col] + tb) * bep[col];
                float v1 = (acc[mt][nt][half * 2 + 1] + b2[col + 1] + tb) * bep[col + 1];
                *(float2*)&g_bond[obase + col] = make_float2(v0, v1);
            }
        }
}

// ---------------- GIN GEMMs: 64x256 paired; A = g_aggr only -----------------
#define GIN_SMEM ((2 * A64SZ + 2 * B256SZ) * 4)
template <int MODE>
__global__ void __launch_bounds__(128, 2)
gin_mma(const float* __restrict__ W, const float* __restrict__ bias, int reluOut) {
    extern __shared__ float sm[];
    float* As = sm;
    float* Bs = sm + 2 * A64SZ;
    int tid = threadIdx.x, lane = tid & 31, warp = tid >> 5;
    int wx = warp;
    int m0 = blockIdx.x * 64;
    int r = tid & 63, kh = (tid >> 6) * 8;
    int arow = m0 + r;
    bool valid = (arow < NN);
    const float* A1 = (MODE == 0) ? g_aggr : g_tmp;

    float areg[8], breg[32];
    auto loadA = [&](int k0) {
        if (valid) {
            const float* p = &A1[arow * H + k0 + kh];
            float4 v0 = *(const float4*)p, v1 = *(const float4*)(p + 4);
            areg[0] = v0.x; areg[1] = v0.y; areg[2] = v0.z; areg[3] = v0.w;
            areg[4] = v1.x; areg[5] = v1.y; areg[6] = v1.z; areg[7] = v1.w;
        } else {
#pragma unroll
            for (int i = 0; i < 8; i++) areg[i] = 0.f;
        }
    };

    loadA(0);
    load_w256h(breg, W, H, 0, tid);
    store_a8p(As, kh, r, areg);
    store_w256p(Bs, breg, tid);
    __syncthreads();

    float acc[4][8][4] = {};
    for (int s = 0; s < 16; s++) {
        int cur = s & 1, nxt = cur ^ 1;
        if (s < 15) { loadA((s + 1) * 16); load_w256h(breg, W, H, (s + 1) * 16, tid); }
        mma_k8p64(acc, As + cur * A64SZ, Bs + cur * B256SZ, 0, wx, lane);
        mma_k8p64(acc, As + cur * A64SZ, Bs + cur * B256SZ, 8, wx, lane);
        if (s < 15) {
            store_a8p(As + nxt * A64SZ, kh, r, areg);
            store_w256p(Bs + nxt * B256SZ, breg, tid);
            __syncthreads();
        }
    }

    int g = lane >> 2, t4 = lane & 3;
#pragma unroll
    for (int mt = 0; mt < 4; mt++)
#pragma unroll
        for (int half = 0; half < 2; half++) {
            int row = m0 + mt * 16 + g + half * 8;
            if (row >= NN) continue;
#pragma unroll
            for (int nt = 0; nt < 8; nt++) {
                int col = wx * 64 + nt * 8 + 2 * t4;
                float v0 = acc[mt][nt][half * 2 + 0] + bias[col];
                float v1 = acc[mt][nt][half * 2 + 1] + bias[col + 1];
                if (reluOut) { v0 = fmaxf(v0, 0.f); v1 = fmaxf(v1, 0.f); }
                if (MODE == 0) {
                    *(float2*)&g_tmp[row * H + col] = make_float2(v0, v1);
                } else {
                    float2 rh = *(const float2*)&g_h[row * H + col];
                    *(float2*)&g_h[row * H + col] = make_float2(v0 + rh.x, v1 + rh.y);
                }
            }
        }
}

// ---------------- out1: K=512, 64x256 paired; bond via g_pos ----------------
#define OUT1_SMEM ((2 * A64SZ + 2 * B256SZ + 192) * 4)
__global__ void __launch_bounds__(128, 2)
out1(const int* __restrict__ src, const int* __restrict__ dst,
     const float* __restrict__ W1, const float* __restrict__ b1) {
    extern __shared__ float sm[];
    float* As = sm;
    float* Bs = sm + 2 * A64SZ;
    int* srcS = (int*)(Bs + 2 * B256SZ);  // 64
    int* dstS = srcS + 64;                // 64
    int* pS   = dstS + 64;                // 64
    int tid = threadIdx.x, lane = tid & 31, warp = tid >> 5;
    int wx = warp;
    int m0 = blockIdx.x * 64;

    if (tid < 64) {
        int e = m0 + tid;
        int s = 0, d = 0, ps = 0;
        if (e < EN) { s = src[e]; d = dst[e]; ps = g_pos[e]; }
        srcS[tid] = s; dstS[tid] = d; pS[tid] = ps;
    }
    __syncthreads();

    int r = tid & 63, kh = (tid >> 6) * 8;
    int e = m0 + r;
    bool valid = (e < EN);
    float areg[8], breg[32];

    auto loadA = [&](int k0) {
        if (k0 < 256) {
            const float* hs = &g_h[srcS[r] * H + k0 + kh];
            const float* hd = &g_h[dstS[r] * H + k0 + kh];
            float4 a0 = *(const float4*)hs, a1 = *(const float4*)(hs + 4);
            float4 c0 = *(const float4*)hd, c1 = *(const float4*)(hd + 4);
            areg[0] = a0.x * c0.x; areg[1] = a0.y * c0.y;
            areg[2] = a0.z * c0.z; areg[3] = a0.w * c0.w;
            areg[4] = a1.x * c1.x; areg[5] = a1.y * c1.y;
            areg[6] = a1.z * c1.z; areg[7] = a1.w * c1.w;
        } else if (valid) {
            const float* bp = &g_bond[(size_t)pS[r] * H + (k0 - 256) + kh];
            float4 v0 = *(const float4*)bp, v1 = *(const float4*)(bp + 4);
            areg[0] = v0.x; areg[1] = v0.y; areg[2] = v0.z; areg[3] = v0.w;
            areg[4] = v1.x; areg[5] = v1.y; areg[6] = v1.z; areg[7] = v1.w;
        } else {
#pragma unroll
            for (int i = 0; i < 8; i++) areg[i] = 0.f;
        }
    };

    loadA(0);
    load_w256h(breg, W1, H, 0, tid);
    store_a8p(As, kh, r, areg);
    store_w256p(Bs, breg, tid);
    __syncthreads();

    float acc[4][8][4] = {};
    for (int s = 0; s < 32; s++) {
        int cur = s & 1, nxt = cur ^ 1;
        if (s < 31) { loadA((s + 1) * 16); load_w256h(breg, W1, H, (s + 1) * 16, tid); }
        mma_k8p64(acc, As + cur * A64SZ, Bs + cur * B256SZ, 0, wx, lane);
        mma_k8p64(acc, As + cur * A64SZ, Bs + cur * B256SZ, 8, wx, lane);
        if (s < 31) {
            store_a8p(As + nxt * A64SZ, kh, r, areg);
            store_w256p(Bs + nxt * B256SZ, breg, tid);
            __syncthreads();
        }
    }

    int g = lane >> 2, t4 = lane & 3;
#pragma unroll
    for (int mt = 0; mt < 4; mt++)
#pragma unroll
        for (int half = 0; half < 2; half++) {
            int row = m0 + mt * 16 + g + half * 8;
            if (row >= EN) continue;
#pragma unroll
            for (int nt = 0; nt < 8; nt++) {
                int col = wx * 64 + nt * 8 + 2 * t4;
                float v0 = fmaxf(acc[mt][nt][half * 2 + 0] + b1[col], 0.f);
                float v1 = fmaxf(acc[mt][nt][half * 2 + 1] + b1[col + 1], 0.f);
                *(float2*)&g_h1[(size_t)row * H + col] = make_float2(v0, v1);
            }
        }
}

// ---------------- out23 fused: unchanged ------------------------------------
__global__ void __launch_bounds__(128, 2)
out23(const float* __restrict__ W2, const float* __restrict__ b2,
      const float* __restrict__ W3, const float* __restrict__ b3,
      float* __restrict__ out) {
    __shared__ float As[2 * ASZ], Bs[2 * BSZ1];
    __shared__ float red[128 * 8];
    __shared__ float b2S[128], w3S[128];
    int tid = threadIdx.x, lane = tid & 31, warp = tid >> 5;
    int wy = warp >> 1, wx = warp & 1;
    int m0 = blockIdx.x * 128;

    b2S[tid] = b2[tid]; w3S[tid] = W3[tid];

    int e = m0 + tid;
    bool valid = (e < EN);
    float areg[16], breg[16];
    auto loadA = [&](int k0) {
        if (valid) {
            const float* p = &g_h1[(size_t)e * H + k0];
#pragma unroll
            for (int j = 0; j < 4; j++) {
                float4 v = *(const float4*)(p + 4 * j);
                areg[4 * j] = v.x; areg[4 * j + 1] = v.y;
                areg[4 * j + 2] = v.z; areg[4 * j + 3] = v.w;
            }
        } else {
#pragma unroll
            for (int i = 0; i < 16; i++) areg[i] = 0.f;
        }
    };

    loadA(0);
    load_w128(breg, W2, 128, 0, 0, tid);
    store_a16(As, tid, areg);
    store_w128(Bs, breg, tid);
    __syncthreads();

    float acc[4][8][4] = {};
    for (int s = 0; s < 16; s++) {
        int cur = s & 1, nxt = cur ^ 1;
        if (s < 15) { loadA((s + 1) * 16); load_w128(breg, W2, 128, (s + 1) * 16, 0, tid); }
        mma_k8w<PB1>(acc, As + cur * ASZ, Bs + cur * BSZ1, 0, wy, wx, lane);
        mma_k8w<PB1>(acc, As + cur * ASZ, Bs + cur * BSZ1, 8, wy, wx, lane);
        if (s < 15) {
            store_a16(As + nxt * ASZ, tid, areg);
            store_w128(Bs + nxt * BSZ1, breg, tid);
            __syncthreads();
        }
    }

    int g = lane >> 2, t4 = lane & 3;
#pragma unroll
    for (int mt = 0; mt < 4; mt++)
#pragma unroll
        for (int half = 0; half < 2; half++) {
            int rl = wy * 64 + mt * 16 + g + half * 8;
            float partial = 0.f;
#pragma unroll
            for (int nt = 0; nt < 8; nt++) {
                int col = wx * 64 + nt * 8 + 2 * t4;
                float h0 = fmaxf(acc[mt][nt][half * 2 + 0] + b2S[col], 0.f);
                float h1 = fmaxf(acc[mt][nt][half * 2 + 1] + b2S[col + 1], 0.f);
                partial += h0 * w3S[col] + h1 * w3S[col + 1];
            }
            red[rl * 8 + wx * 4 + t4] = partial;
        }
    __syncthreads();

    if (valid) {
        float s = 0.f;
#pragma unroll
        for (int i = 0; i < 8; i++) s += red[tid * 8 + i];
        out[e] = (s + b3[0]) * g_einv[e];
    }
}

// ---------------- launch ----------------------------------------------------
extern "C" void kernel_launch(void* const* d_in, const int* in_sizes, int n_in,
                              void* d_out, int out_size) {
    const int*   node_type = (const int*)d_in[0];
    const int*   edge_type = (const int*)d_in[1];
    const int*   edge_index = (const int*)d_in[2];
    const int*   batch = (const int*)d_in[3];
    const float* elen = (const float*)d_in[4];
    const float* t = (const float*)d_in[5];
    const float* atom_emb = (const float*)d_in[6];
    const float* bond_emb = (const float*)d_in[7];
    const float* in_W1 = (const float*)d_in[8];
    const float* in_b1 = (const float*)d_in[9];
    const float* in_W2 = (const float*)d_in[10];
    const float* in_b2 = (const float*)d_in[11];
    const float* fourier_W = (const float*)d_in[12];
    const float* temb_W = (const float*)d_in[13];
    const float* temb_b = (const float*)d_in[14];
    const float* d1W = (const float*)d_in[15];
    const float* d1b = (const float*)d_in[16];
    const float* gin_W1 = (const float*)d_in[17];
    const float* gin_b1 = (const float*)d_in[18];
    const float* gin_W2 = (const float*)d_in[19];
    const float* gin_b2 = (const float*)d_in[20];
    const float* out_W1 = (const float*)d_in[21];
    const float* out_b1 = (const float*)d_in[22];
    const float* out_W2 = (const float*)d_in[23];
    const float* out_b2 = (const float*)d_in[24];
    const float* out_W3 = (const float*)d_in[25];
    const float* out_b3 = (const float*)d_in[26];
    const int* src = edge_index;
    const int* dst = edge_index + EN;
    float* out = (float*)d_out;

    const int EB = (EN + 127) / 128;      // 2344
    const int EB64 = (EN + 63) / 64;      // 4688
    const int NB64 = (NN + 63) / 64;      // 782

    static int attr_done = 0;
    if (!attr_done) {
        cudaFuncSetAttribute(edge_bond, cudaFuncAttributeMaxDynamicSharedMemorySize, EB_SMEM);
        cudaFuncSetAttribute(gin_mma<0>, cudaFuncAttributeMaxDynamicSharedMemorySize, GIN_SMEM);
        cudaFuncSetAttribute(gin_mma<1>, cudaFuncAttributeMaxDynamicSharedMemorySize, GIN_SMEM);
        cudaFuncSetAttribute(out1, cudaFuncAttributeMaxDynamicSharedMemorySize, OUT1_SMEM);
        attr_done = 1;
    }

    // sort must precede edge_bond (sorted bond writes)
    temb_fused<<<GN, 128>>>(t, fourier_W, temb_W, temb_b, d1W, d1b);      // 0
    hist<<<(EN + 255) / 256, 256>>>(dst);                                 // 1
    scan_kernel<<<1, 1024>>>();                                           // 2
    place<<<(EN + 255) / 256, 256>>>(src, dst);                           // 3
    edge_bond<<<dim3(2, EB), 128, EB_SMEM>>>(elen, src, batch, edge_type, // 4
                                             in_W1, in_b1, in_W2, in_b2, bond_emb);
    init_h<<<(NN * 64 + 255) / 256, 256>>>(node_type, atom_emb);          // 5

    for (int c = 0; c < NCONV; c++) {
        gather<<<(NN + 7) / 8, 256>>>();
        gin_mma<0><<<NB64, 128, GIN_SMEM>>>(gin_W1 + c * H * H, gin_b1 + c * H, 1);
        gin_mma<1><<<NB64, 128, GIN_SMEM>>>(gin_W2 + c * H * H, gin_b2 + c * H,
                                            (c < NCONV - 1) ? 1 : 0);
    }

    out1<<<EB64, 128, OUT1_SMEM>>>(src, dst, out_W1, out_b1);
    out23<<<EB, 128>>>(out_W2, out_b2, out_W3, out_b3, out);
}

// round 16
// speedup vs baseline: 1.1832x; 1.0458x over previous
#include <cuda_runtime.h>
#include <cuda_fp16.h>
#include <math.h>
#include <stdint.h>

#define EN 300000
#define NN 50000
#define GN 1024
#define H  256
#define NCONV 4
// old-style strides (out23)
#define PA 136
#define PB1 136
#define ASZ (16 * PA)
#define BSZ1 (16 * PB1)
// paired-fragment layout constants
#define A64P 136
#define A64SZ (16 * A64P)
#define B256P 520
#define B256SZ (8 * B256P)
#define B128P 264
#define B128SZ (8 * B128P)

// ---------------- scratch (device globals) ---------------------------------
static __device__ __half g_bond[(size_t)EN * H];   // fp16, DST-SORTED rows
static __device__ __half g_h1[(size_t)EN * H];     // fp16
static __device__ float g_h[NN * H];
static __device__ float g_aggr[NN * H];
static __device__ float g_tmp[NN * H];
static __device__ float g_temb[GN];
static __device__ float g_invstd[GN];
static __device__ float g_einv[EN];
static __device__ int g_cnt[NN];
static __device__ int g_rp[NN + 1];
static __device__ int g_woff[NN];
static __device__ int g_srcp[EN];     // sorted pos -> src node
static __device__ int g_pos[EN];      // edge -> sorted pos

// ---------------- helpers ---------------------------------------------------
__device__ __forceinline__ float totf(float x) {
    uint32_t u; asm("cvt.rna.tf32.f32 %0, %1;" : "=r"(u) : "f"(x));
    return __uint_as_float(u);
}

__device__ __forceinline__ void mma1(float acc[4],
                                     float a0, float a1, float a2, float a3,
                                     float b0, float b1) {
    asm volatile(
        "mma.sync.aligned.m16n8k8.row.col.f32.tf32.tf32.f32 "
        "{%0,%1,%2,%3}, {%4,%5,%6,%7}, {%8,%9}, {%0,%1,%2,%3};\n"
        : "+f"(acc[0]), "+f"(acc[1]), "+f"(acc[2]), "+f"(acc[3])
        : "r"(__float_as_uint(a0)), "r"(__float_as_uint(a1)),
          "r"(__float_as_uint(a2)), "r"(__float_as_uint(a3)),
          "r"(__float_as_uint(b0)), "r"(__float_as_uint(b1)));
}

// old-style warp 64x64 (out23)
template <int BS>
__device__ __forceinline__ void mma_k8w(float acc[4][8][4],
                                        const float* As, const float* Bs,
                                        int kk, int wy, int wx, int lane) {
    int g = lane >> 2, t4 = lane & 3;
    float a[4][4];
#pragma unroll
    for (int mt = 0; mt < 4; mt++) {
        int rm = wy * 64 + mt * 16 + g;
        a[mt][0] = As[(kk + t4) * PA + rm];
        a[mt][1] = As[(kk + t4) * PA + rm + 8];
        a[mt][2] = As[(kk + t4 + 4) * PA + rm];
        a[mt][3] = As[(kk + t4 + 4) * PA + rm + 8];
    }
#pragma unroll
    for (int nt = 0; nt < 8; nt++) {
        int cn = wx * 64 + nt * 8 + g;
        float b0 = Bs[(kk + t4) * BS + cn];
        float b1 = Bs[(kk + t4 + 4) * BS + cn];
#pragma unroll
        for (int mt = 0; mt < 4; mt++)
            mma1(acc[mt][nt], a[mt][0], a[mt][1], a[mt][2], a[mt][3], b0, b1);
    }
}

// paired-fragment warp 64x64
__device__ __forceinline__ void mma_k8p64(float acc[4][8][4],
                                          const float* As, const float* Bs,
                                          int kk, int wx, int lane) {
    int g = lane >> 2, t4 = lane & 3;
    int ks = (kk >> 3) * 4 + t4;
    float2 a01[4], a23[4];
#pragma unroll
    for (int mt = 0; mt < 4; mt++) {
        a01[mt] = *(const float2*)&As[(kk + t4) * A64P + (mt * 8 + g) * 2];
        a23[mt] = *(const float2*)&As[(kk + t4 + 4) * A64P + (mt * 8 + g) * 2];
    }
#pragma unroll
    for (int nt = 0; nt < 8; nt++) {
        int cn = wx * 64 + nt * 8 + g;
        float2 b = *(const float2*)&Bs[ks * B256P + cn * 2];
#pragma unroll
        for (int mt = 0; mt < 4; mt++)
            mma1(acc[mt][nt], a01[mt].x, a01[mt].y, a23[mt].x, a23[mt].y, b.x, b.y);
    }
}

// ---- loaders / storers ----
__device__ __forceinline__ void load_w256h(float v[32], const float* __restrict__ W,
                                           int ldw, int k0, int tid) {
    const float* p = &W[(size_t)k0 * ldw + tid];
#pragma unroll
    for (int k = 0; k < 16; k++) {
        v[k] = p[(size_t)k * ldw];
        v[16 + k] = p[(size_t)k * ldw + 128];
    }
}
__device__ __forceinline__ void store_w256p(float* Bs, const float v[32], int tid) {
#pragma unroll
    for (int s8 = 0; s8 < 2; s8++)
#pragma unroll
        for (int t4 = 0; t4 < 4; t4++) {
            int slot = s8 * 4 + t4;
            *(float2*)&Bs[slot * B256P + tid * 2] =
                make_float2(totf(v[s8 * 8 + t4]), totf(v[s8 * 8 + t4 + 4]));
            *(float2*)&Bs[slot * B256P + (tid + 128) * 2] =
                make_float2(totf(v[16 + s8 * 8 + t4]), totf(v[16 + s8 * 8 + t4 + 4]));
        }
}
__device__ __forceinline__ void load_w128(float v[16], const float* __restrict__ W,
                                          int ldw, int k0, int n0, int tid) {
    const float* p = &W[(size_t)k0 * ldw + n0 + tid];
#pragma unroll
    for (int k = 0; k < 16; k++) v[k] = p[(size_t)k * ldw];
}
__device__ __forceinline__ void store_w128p(float* Bs, const float v[16], int tid) {
#pragma unroll
    for (int s8 = 0; s8 < 2; s8++)
#pragma unroll
        for (int t4 = 0; t4 < 4; t4++)
            *(float2*)&Bs[(s8 * 4 + t4) * B128P + tid * 2] =
                make_float2(totf(v[s8 * 8 + t4]), totf(v[s8 * 8 + t4 + 4]));
}
__device__ __forceinline__ void store_w128(float* Bs, const float v[16], int tid) {
#pragma unroll
    for (int k = 0; k < 16; k++) Bs[k * PB1 + tid] = totf(v[k]);
}
__device__ __forceinline__ void store_a8p(float* As, int kh, int r, const float v[8]) {
    int rpos = ((r >> 4) * 8 + (r & 7)) * 2 + ((r >> 3) & 1);
#pragma unroll
    for (int i = 0; i < 8; i++) As[(kh + i) * A64P + rpos] = totf(v[i]);
}
__device__ __forceinline__ void store_a16(float* As, int r, const float v[16]) {
#pragma unroll
    for (int k = 0; k < 16; k++) As[k * PA + r] = totf(v[k]);
}
// load 8 halves -> 8 floats (one 16B load)
__device__ __forceinline__ void ldh8(float v[8], const __half* p) {
    float4 raw = *(const float4*)p;
    const __half2* h2 = (const __half2*)&raw;
#pragma unroll
    for (int i = 0; i < 4; i++) {
        float2 f = __half22float2(h2[i]);
        v[2 * i] = f.x; v[2 * i + 1] = f.y;
    }
}

// ---------------- temb (comb fused) -----------------------------------------
__global__ void __launch_bounds__(128)
temb_fused(const float* __restrict__ t, const float* __restrict__ fw,
           const float* __restrict__ tW, const float* __restrict__ tb,
           const float* __restrict__ d1W, const float* __restrict__ d1b) {
    __shared__ float d1S[H], combS[H + 1], red[128];
    int tid = threadIdx.x, lane = tid & 31, warp = tid >> 5;
    d1S[tid] = d1W[tid]; d1S[tid + 128] = d1W[tid + 128];
    __syncthreads();
    for (int row = warp; row < H + 1; row += 4) {
        const float* p = (row < H) ? &tW[(size_t)row * H] : tb;
        float s = 0.f;
        for (int k = lane; k < H; k += 32) s += p[k] * d1S[k];
#pragma unroll
        for (int o = 16; o; o >>= 1) s += __shfl_down_sync(0xffffffffu, s, o);
        if (lane == 0) combS[row] = (row == H) ? s + d1b[0] : s;
    }
    __syncthreads();
    int g = blockIdx.x;
    float tt = t[g];
    float xp = tt * fw[tid] * 6.283185307179586f;
    red[tid] = sinf(xp) * combS[tid] + cosf(xp) * combS[128 + tid];
    __syncthreads();
    for (int s = 64; s > 0; s >>= 1) {
        if (tid < s) red[tid] += red[tid + s];
        __syncthreads();
    }
    if (tid == 0) {
        g_temb[g] = red[0] + combS[H];
        const float LS = 3.2188758248682006f;   // ln(25)
        float var = (expf(2.f * tt * LS) - 1.f) / (2.f * LS);
        g_invstd[g] = rsqrtf(var);
    }
}

// ---------------- sort machinery ---------------------------------------------
__global__ void __launch_bounds__(256) hist(const int* __restrict__ dst) {
    int e = blockIdx.x * blockDim.x + threadIdx.x;
    if (e < EN) atomicAdd(&g_cnt[dst[e]], 1);
}

__global__ void __launch_bounds__(1024) scan_kernel() {
    __shared__ int part[1024];
    const int CH = 49;
    int t = threadIdx.x;
    int beg = t * CH, end = min(beg + CH, NN);
    int s = 0;
    for (int i = beg; i < end; i++) s += g_cnt[i];
    part[t] = s;
    __syncthreads();
    for (int off = 1; off < 1024; off <<= 1) {
        int v = (t >= off) ? part[t - off] : 0;
        __syncthreads();
        part[t] += v;
        __syncthreads();
    }
    int run = (t == 0) ? 0 : part[t - 1];
    for (int i = beg; i < end; i++) {
        g_rp[i] = run; g_woff[i] = run; run += g_cnt[i];
        g_cnt[i] = 0;
    }
    if (t == 1023) g_rp[NN] = part[1023];
}

__global__ void __launch_bounds__(256) place(const int* __restrict__ src,
                                             const int* __restrict__ dst) {
    int e = blockIdx.x * blockDim.x + threadIdx.x;
    if (e >= EN) return;
    int p = atomicAdd(&g_woff[dst[e]], 1);
    g_pos[e] = p;
    g_srcp[p] = src[e];
}

__global__ void __launch_bounds__(256) init_h(const int* __restrict__ nt,
                                              const float* __restrict__ atom_emb) {
    int idx = blockIdx.x * blockDim.x + threadIdx.x;
    if (idx >= NN * 64) return;
    int n = idx >> 6, q = idx & 63;
    ((float4*)g_h)[idx] = ((const float4*)atom_emb)[nt[n] * 64 + q];
}

// ---------------- gather: aggr[n] = h[n] + sum relu(h[src]+bond) ------------
__global__ void __launch_bounds__(256) gather() {
    int warp = threadIdx.x >> 5, lane = threadIdx.x & 31;
    int n = blockIdx.x * 8 + warp;
    if (n >= NN) return;
    int q = lane * 8;
    float4 a0 = make_float4(0.f, 0.f, 0.f, 0.f), a1 = a0;
    int beg = g_rp[n], end = g_rp[n + 1];
    for (int p = beg; p < end; p++) {
        int s = g_srcp[p];
        const float4* hp = (const float4*)&g_h[s * H + q];
        float bv[8];
        ldh8(bv, &g_bond[(size_t)p * H + q]);
        float4 h0 = hp[0], h1v = hp[1];
        a0.x += fmaxf(h0.x + bv[0], 0.f);  a0.y += fmaxf(h0.y + bv[1], 0.f);
        a0.z += fmaxf(h0.z + bv[2], 0.f);  a0.w += fmaxf(h0.w + bv[3], 0.f);
        a1.x += fmaxf(h1v.x + bv[4], 0.f); a1.y += fmaxf(h1v.y + bv[5], 0.f);
        a1.z += fmaxf(h1v.z + bv[6], 0.f); a1.w += fmaxf(h1v.w + bv[7], 0.f);
    }
    const float4* hn = (const float4*)&g_h[n * H + q];
    float4 n0v = hn[0], n1v = hn[1];
    a0.x += n0v.x; a0.y += n0v.y; a0.z += n0v.z; a0.w += n0v.w;
    a1.x += n1v.x; a1.y += n1v.y; a1.z += n1v.z; a1.w += n1v.w;
    float4* ap = (float4*)&g_aggr[n * H + q];
    ap[0] = a0; ap[1] = a1;
}

// ---------------- edge_bond: reg-A + paired B, writes SORTED fp16 rows ------
#define EB_SMEM ((2 * B128SZ + 128 + 128 + 128 + 128 + 2 * H) * 4)

__global__ void __launch_bounds__(128, 2)
edge_bond(const float* __restrict__ elen, const int* __restrict__ src,
          const int* __restrict__ batch, const int* __restrict__ etype,
          const float* __restrict__ W1, const float* __restrict__ b1,
          const float* __restrict__ W2, const float* __restrict__ b2,
          const float* __restrict__ bond_emb) {
    extern __shared__ float sm[];
    float* Bs = sm;                       // 2*B128SZ
    float* xS = Bs + 2 * B128SZ;
    float* tS = xS + 128;
    int*   eS = (int*)(tS + 128);
    int*   pS = eS + 128;
    float* w1S = (float*)(pS + 128);
    float* b1S = w1S + H;

    int tid = threadIdx.x, lane = tid & 31, warp = tid >> 5;
    int wy = warp >> 1, wx = warp & 1;
    int g = lane >> 2, t4 = lane & 3;
    int m0 = blockIdx.y * 128, n0 = blockIdx.x * 128;

    {
        int e = m0 + tid;
        float x = 0.f, tb = 0.f; int et = 0, ps = 0;
        if (e < EN) {
            x = elen[e];
            int gph = batch[src[e]];
            tb = g_temb[gph];
            if (n0 == 0) g_einv[e] = g_invstd[gph];
            et = etype[e];
            ps = g_pos[e];
        }
        xS[tid] = x; tS[tid] = tb; eS[tid] = et; pS[tid] = ps;
    }
    w1S[tid] = W1[tid];         w1S[tid + 128] = W1[tid + 128];
    b1S[tid] = b1[tid];         b1S[tid + 128] = b1[tid + 128];
    __syncthreads();

    float xr[4][2];
#pragma unroll
    for (int mt = 0; mt < 4; mt++) {
        xr[mt][0] = xS[wy * 64 + mt * 16 + g];
        xr[mt][1] = xS[wy * 64 + mt * 16 + g + 8];
    }

    float breg[16];
    load_w128(breg, W2, H, 0, n0, tid);
    store_w128p(Bs, breg, tid);
    __syncthreads();

    float acc[4][8][4] = {};
    for (int s = 0; s < 16; s++) {
        int cur = s & 1, nxt = cur ^ 1;
        if (s < 15) load_w128(breg, W2, H, (s + 1) * 16, n0, tid);
        const float* B = Bs + cur * B128SZ;
#pragma unroll
        for (int kh = 0; kh < 16; kh += 8) {
            int kA = s * 16 + kh;
            float w0 = w1S[kA + t4], w4 = w1S[kA + t4 + 4];
            float c0 = b1S[kA + t4], c4 = b1S[kA + t4 + 4];
            float a[4][4];
#pragma unroll
            for (int mt = 0; mt < 4; mt++) {
                a[mt][0] = totf(fmaxf(fmaf(xr[mt][0], w0, c0), 0.f));
                a[mt][1] = totf(fmaxf(fmaf(xr[mt][1], w0, c0), 0.f));
                a[mt][2] = totf(fmaxf(fmaf(xr[mt][0], w4, c4), 0.f));
                a[mt][3] = totf(fmaxf(fmaf(xr[mt][1], w4, c4), 0.f));
            }
            int ks = (kh >> 3) * 4 + t4;
#pragma unroll
            for (int nt = 0; nt < 8; nt++) {
                int cn = wx * 64 + nt * 8 + g;
                float2 b = *(const float2*)&B[ks * B128P + cn * 2];
#pragma unroll
                for (int mt = 0; mt < 4; mt++)
                    mma1(acc[mt][nt], a[mt][0], a[mt][1], a[mt][2], a[mt][3], b.x, b.y);
            }
        }
        if (s < 15) {
            store_w128p(Bs + nxt * B128SZ, breg, tid);
            __syncthreads();
        }
    }

#pragma unroll
    for (int mt = 0; mt < 4; mt++)
#pragma unroll
        for (int half = 0; half < 2; half++) {
            int rl = wy * 64 + mt * 16 + g + half * 8;
            int row = m0 + rl;
            if (row >= EN) continue;
            float tb = tS[rl];
            const float* bep = &bond_emb[eS[rl] * H];
            size_t obase = (size_t)pS[rl] * H;          // sorted position
#pragma unroll
            for (int nt = 0; nt < 8; nt++) {
                int col = n0 + wx * 64 + nt * 8 + 2 * t4;
                float v0 = (acc[mt][nt][half * 2 + 0] + b2[col] + tb) * bep[col];
                float v1 = (acc[mt][nt][half * 2 + 1] + b2[col + 1] + tb) * bep[col + 1];
                *(__half2*)&g_bond[obase + col] = __floats2half2_rn(v0, v1);
            }
        }
}

// ---------------- GIN GEMMs: 64x256 paired; A = g_aggr only -----------------
#define GIN_SMEM ((2 * A64SZ + 2 * B256SZ) * 4)
template <int MODE>
__global__ void __launch_bounds__(128, 2)
gin_mma(const float* __restrict__ W, const float* __restrict__ bias, int reluOut) {
    extern __shared__ float sm[];
    float* As = sm;
    float* Bs = sm + 2 * A64SZ;
    int tid = threadIdx.x, lane = tid & 31, warp = tid >> 5;
    int wx = warp;
    int m0 = blockIdx.x * 64;
    int r = tid & 63, kh = (tid >> 6) * 8;
    int arow = m0 + r;
    bool valid = (arow < NN);
    const float* A1 = (MODE == 0) ? g_aggr : g_tmp;

    float areg[8], breg[32];
    auto loadA = [&](int k0) {
        if (valid) {
            const float* p = &A1[arow * H + k0 + kh];
            float4 v0 = *(const float4*)p, v1 = *(const float4*)(p + 4);
            areg[0] = v0.x; areg[1] = v0.y; areg[2] = v0.z; areg[3] = v0.w;
            areg[4] = v1.x; areg[5] = v1.y; areg[6] = v1.z; areg[7] = v1.w;
        } else {
#pragma unroll
            for (int i = 0; i < 8; i++) areg[i] = 0.f;
        }
    };

    loadA(0);
    load_w256h(breg, W, H, 0, tid);
    store_a8p(As, kh, r, areg);
    store_w256p(Bs, breg, tid);
    __syncthreads();

    float acc[4][8][4] = {};
    for (int s = 0; s < 16; s++) {
        int cur = s & 1, nxt = cur ^ 1;
        if (s < 15) { loadA((s + 1) * 16); load_w256h(breg, W, H, (s + 1) * 16, tid); }
        mma_k8p64(acc, As + cur * A64SZ, Bs + cur * B256SZ, 0, wx, lane);
        mma_k8p64(acc, As + cur * A64SZ, Bs + cur * B256SZ, 8, wx, lane);
        if (s < 15) {
            store_a8p(As + nxt * A64SZ, kh, r, areg);
            store_w256p(Bs + nxt * B256SZ, breg, tid);
            __syncthreads();
        }
    }

    int g = lane >> 2, t4 = lane & 3;
#pragma unroll
    for (int mt = 0; mt < 4; mt++)
#pragma unroll
        for (int half = 0; half < 2; half++) {
            int row = m0 + mt * 16 + g + half * 8;
            if (row >= NN) continue;
#pragma unroll
            for (int nt = 0; nt < 8; nt++) {
                int col = wx * 64 + nt * 8 + 2 * t4;
                float v0 = acc[mt][nt][half * 2 + 0] + bias[col];
                float v1 = acc[mt][nt][half * 2 + 1] + bias[col + 1];
                if (reluOut) { v0 = fmaxf(v0, 0.f); v1 = fmaxf(v1, 0.f); }
                if (MODE == 0) {
                    *(float2*)&g_tmp[row * H + col] = make_float2(v0, v1);
                } else {
                    float2 rh = *(const float2*)&g_h[row * H + col];
                    *(float2*)&g_h[row * H + col] = make_float2(v0 + rh.x, v1 + rh.y);
                }
            }
        }
}

// ---------------- out1: K=512, 64x256 paired; fp16 bond/h1 ------------------
#define OUT1_SMEM ((2 * A64SZ + 2 * B256SZ + 192) * 4)
__global__ void __launch_bounds__(128, 2)
out1(const int* __restrict__ src, const int* __restrict__ dst,
     const float* __restrict__ W1, const float* __restrict__ b1) {
    extern __shared__ float sm[];
    float* As = sm;
    float* Bs = sm + 2 * A64SZ;
    int* srcS = (int*)(Bs + 2 * B256SZ);  // 64
    int* dstS = srcS + 64;                // 64
    int* pS   = dstS + 64;                // 64
    int tid = threadIdx.x, lane = tid & 31, warp = tid >> 5;
    int wx = warp;
    int m0 = blockIdx.x * 64;

    if (tid < 64) {
        int e = m0 + tid;
        int s = 0, d = 0, ps = 0;
        if (e < EN) { s = src[e]; d = dst[e]; ps = g_pos[e]; }
        srcS[tid] = s; dstS[tid] = d; pS[tid] = ps;
    }
    __syncthreads();

    int r = tid & 63, kh = (tid >> 6) * 8;
    int e = m0 + r;
    bool valid = (e < EN);
    float areg[8], breg[32];

    auto loadA = [&](int k0) {
        if (k0 < 256) {
            const float* hs = &g_h[srcS[r] * H + k0 + kh];
            const float* hd = &g_h[dstS[r] * H + k0 + kh];
            float4 a0 = *(const float4*)hs, a1 = *(const float4*)(hs + 4);
            float4 c0 = *(const float4*)hd, c1 = *(const float4*)(hd + 4);
            areg[0] = a0.x * c0.x; areg[1] = a0.y * c0.y;
            areg[2] = a0.z * c0.z; areg[3] = a0.w * c0.w;
            areg[4] = a1.x * c1.x; areg[5] = a1.y * c1.y;
            areg[6] = a1.z * c1.z; areg[7] = a1.w * c1.w;
        } else if (valid) {
            ldh8(areg, &g_bond[(size_t)pS[r] * H + (k0 - 256) + kh]);
        } else {
#pragma unroll
            for (int i = 0; i < 8; i++) areg[i] = 0.f;
        }
    };

    loadA(0);
    load_w256h(breg, W1, H, 0, tid);
    store_a8p(As, kh, r, areg);
    store_w256p(Bs, breg, tid);
    __syncthreads();

    float acc[4][8][4] = {};
    for (int s = 0; s < 32; s++) {
        int cur = s & 1, nxt = cur ^ 1;
        if (s < 31) { loadA((s + 1) * 16); load_w256h(breg, W1, H, (s + 1) * 16, tid); }
        mma_k8p64(acc, As + cur * A64SZ, Bs + cur * B256SZ, 0, wx, lane);
        mma_k8p64(acc, As + cur * A64SZ, Bs + cur * B256SZ, 8, wx, lane);
        if (s < 31) {
            store_a8p(As + nxt * A64SZ, kh, r, areg);
            store_w256p(Bs + nxt * B256SZ, breg, tid);
            __syncthreads();
        }
    }

    int g = lane >> 2, t4 = lane & 3;
#pragma unroll
    for (int mt = 0; mt < 4; mt++)
#pragma unroll
        for (int half = 0; half < 2; half++) {
            int row = m0 + mt * 16 + g + half * 8;
            if (row >= EN) continue;
#pragma unroll
            for (int nt = 0; nt < 8; nt++) {
                int col = wx * 64 + nt * 8 + 2 * t4;
                float v0 = fmaxf(acc[mt][nt][half * 2 + 0] + b1[col], 0.f);
                float v1 = fmaxf(acc[mt][nt][half * 2 + 1] + b1[col + 1], 0.f);
                *(__half2*)&g_h1[(size_t)row * H + col] = __floats2half2_rn(v0, v1);
            }
        }
}

// ---------------- out23 fused: fp16 h1 in ------------------------------------
__global__ void __launch_bounds__(128, 2)
out23(const float* __restrict__ W2, const float* __restrict__ b2,
      const float* __restrict__ W3, const float* __restrict__ b3,
      float* __restrict__ out) {
    __shared__ float As[2 * ASZ], Bs[2 * BSZ1];
    __shared__ float red[128 * 8];
    __shared__ float b2S[128], w3S[128];
    int tid = threadIdx.x, lane = tid & 31, warp = tid >> 5;
    int wy = warp >> 1, wx = warp & 1;
    int m0 = blockIdx.x * 128;

    b2S[tid] = b2[tid]; w3S[tid] = W3[tid];

    int e = m0 + tid;
    bool valid = (e < EN);
    float areg[16], breg[16];
    auto loadA = [&](int k0) {
        if (valid) {
            const __half* p = &g_h1[(size_t)e * H + k0];
            ldh8(areg, p);
            ldh8(areg + 8, p + 8);
        } else {
#pragma unroll
            for (int i = 0; i < 16; i++) areg[i] = 0.f;
        }
    };

    loadA(0);
    load_w128(breg, W2, 128, 0, 0, tid);
    store_a16(As, tid, areg);
    store_w128(Bs, breg, tid);
    __syncthreads();

    float acc[4][8][4] = {};
    for (int s = 0; s < 16; s++) {
        int cur = s & 1, nxt = cur ^ 1;
        if (s < 15) { loadA((s + 1) * 16); load_w128(breg, W2, 128, (s + 1) * 16, 0, tid); }
        mma_k8w<PB1>(acc, As + cur * ASZ, Bs + cur * BSZ1, 0, wy, wx, lane);
        mma_k8w<PB1>(acc, As + cur * ASZ, Bs + cur * BSZ1, 8, wy, wx, lane);
        if (s < 15) {
            store_a16(As + nxt * ASZ, tid, areg);
            store_w128(Bs + nxt * BSZ1, breg, tid);
            __syncthreads();
        }
    }

    int g = lane >> 2, t4 = lane & 3;
#pragma unroll
    for (int mt = 0; mt < 4; mt++)
#pragma unroll
        for (int half = 0; half < 2; half++) {
            int rl = wy * 64 + mt * 16 + g + half * 8;
            float partial = 0.f;
#pragma unroll
            for (int nt = 0; nt < 8; nt++) {
                int col = wx * 64 + nt * 8 + 2 * t4;
                float h0 = fmaxf(acc[mt][nt][half * 2 + 0] + b2S[col], 0.f);
                float h1 = fmaxf(acc[mt][nt][half * 2 + 1] + b2S[col + 1], 0.f);
                partial += h0 * w3S[col] + h1 * w3S[col + 1];
            }
            red[rl * 8 + wx * 4 + t4] = partial;
        }
    __syncthreads();

    if (valid) {
        float s = 0.f;
#pragma unroll
        for (int i = 0; i < 8; i++) s += red[tid * 8 + i];
        out[e] = (s + b3[0]) * g_einv[e];
    }
}

// ---------------- launch ----------------------------------------------------
extern "C" void kernel_launch(void* const* d_in, const int* in_sizes, int n_in,
                              void* d_out, int out_size) {
    const int*   node_type = (const int*)d_in[0];
    const int*   edge_type = (const int*)d_in[1];
    const int*   edge_index = (const int*)d_in[2];
    const int*   batch = (const int*)d_in[3];
    const float* elen = (const float*)d_in[4];
    const float* t = (const float*)d_in[5];
    const float* atom_emb = (const float*)d_in[6];
    const float* bond_emb = (const float*)d_in[7];
    const float* in_W1 = (const float*)d_in[8];
    const float* in_b1 = (const float*)d_in[9];
    const float* in_W2 = (const float*)d_in[10];
    const float* in_b2 = (const float*)d_in[11];
    const float* fourier_W = (const float*)d_in[12];
    const float* temb_W = (const float*)d_in[13];
    const float* temb_b = (const float*)d_in[14];
    const float* d1W = (const float*)d_in[15];
    const float* d1b = (const float*)d_in[16];
    const float* gin_W1 = (const float*)d_in[17];
    const float* gin_b1 = (const float*)d_in[18];
    const float* gin_W2 = (const float*)d_in[19];
    const float* gin_b2 = (const float*)d_in[20];
    const float* out_W1 = (const float*)d_in[21];
    const float* out_b1 = (const float*)d_in[22];
    const float* out_W2 = (const float*)d_in[23];
    const float* out_b2 = (const float*)d_in[24];
    const float* out_W3 = (const float*)d_in[25];
    const float* out_b3 = (const float*)d_in[26];
    const int* src = edge_index;
    const int* dst = edge_index + EN;
    float* out = (float*)d_out;

    const int EB = (EN + 127) / 128;      // 2344
    const int EB64 = (EN + 63) / 64;      // 4688
    const int NB64 = (NN + 63) / 64;      // 782

    static int attr_done = 0;
    if (!attr_done) {
        cudaFuncSetAttribute(edge_bond, cudaFuncAttributeMaxDynamicSharedMemorySize, EB_SMEM);
        cudaFuncSetAttribute(gin_mma<0>, cudaFuncAttributeMaxDynamicSharedMemorySize, GIN_SMEM);
        cudaFuncSetAttribute(gin_mma<1>, cudaFuncAttributeMaxDynamicSharedMemorySize, GIN_SMEM);
        cudaFuncSetAttribute(out1, cudaFuncAttributeMaxDynamicSharedMemorySize, OUT1_SMEM);
        attr_done = 1;
    }

    temb_fused<<<GN, 128>>>(t, fourier_W, temb_W, temb_b, d1W, d1b);      // 0
    hist<<<(EN + 255) / 256, 256>>>(dst);                                 // 1
    scan_kernel<<<1, 1024>>>();                                           // 2
    place<<<(EN + 255) / 256, 256>>>(src, dst);                           // 3
    edge_bond<<<dim3(2, EB), 128, EB_SMEM>>>(elen, src, batch, edge_type, // 4
                                             in_W1, in_b1, in_W2, in_b2, bond_emb);
    init_h<<<(NN * 64 + 255) / 256, 256>>>(node_type, atom_emb);          // 5

    for (int c = 0; c < NCONV; c++) {
        gather<<<(NN + 7) / 8, 256>>>();
        gin_mma<0><<<NB64, 128, GIN_SMEM>>>(gin_W1 + c * H * H, gin_b1 + c * H, 1);
        gin_mma<1><<<NB64, 128, GIN_SMEM>>>(gin_W2 + c * H * H, gin_b2 + c * H,
                                            (c < NCONV - 1) ? 1 : 0);
    }

    out1<<<EB64, 128, OUT1_SMEM>>>(src, dst, out_W1, out_b1);
    out23<<<EB, 128>>>(out_W2, out_b2, out_W3, out_b3, out);
}

// round 17
// speedup vs baseline: 1.2035x; 1.0172x over previous
#include <cuda_runtime.h>
#include <cuda_fp16.h>
#include <math.h>
#include <stdint.h>

#define EN 300000
#define NN 50000
#define GN 1024
#define H  256
#define NCONV 4
// old-style strides (out23)
#define PA 136
#define PB1 136
#define ASZ (16 * PA)
#define BSZ1 (16 * PB1)
// paired-fragment layout constants
#define A64P 136
#define A64SZ (16 * A64P)
#define B256P 520
#define B256SZ (8 * B256P)
#define B128P 264
#define B128SZ (8 * B128P)

// ---------------- scratch (device globals) ---------------------------------
static __device__ __half g_bond[(size_t)EN * H];   // fp16, DST-SORTED rows
static __device__ __half g_h1[(size_t)EN * H];     // fp16
static __device__ __half g_aggr[NN * H];           // fp16 (MMA A operand)
static __device__ __half g_tmp[NN * H];            // fp16 (MMA A operand)
static __device__ float g_h[NN * H];               // fp32 (residual chain)
static __device__ float g_temb[GN];
static __device__ float g_invstd[GN];
static __device__ float g_einv[EN];
static __device__ int g_cnt[NN];
static __device__ int g_rp[NN + 1];
static __device__ int g_woff[NN];
static __device__ int g_srcp[EN];     // sorted pos -> src node
static __device__ int g_pos[EN];      // edge -> sorted pos

// ---------------- helpers ---------------------------------------------------
__device__ __forceinline__ float totf(float x) {
    uint32_t u; asm("cvt.rna.tf32.f32 %0, %1;" : "=r"(u) : "f"(x));
    return __uint_as_float(u);
}

__device__ __forceinline__ void mma1(float acc[4],
                                     float a0, float a1, float a2, float a3,
                                     float b0, float b1) {
    asm volatile(
        "mma.sync.aligned.m16n8k8.row.col.f32.tf32.tf32.f32 "
        "{%0,%1,%2,%3}, {%4,%5,%6,%7}, {%8,%9}, {%0,%1,%2,%3};\n"
        : "+f"(acc[0]), "+f"(acc[1]), "+f"(acc[2]), "+f"(acc[3])
        : "r"(__float_as_uint(a0)), "r"(__float_as_uint(a1)),
          "r"(__float_as_uint(a2)), "r"(__float_as_uint(a3)),
          "r"(__float_as_uint(b0)), "r"(__float_as_uint(b1)));
}

// old-style warp 64x64 (out23)
template <int BS>
__device__ __forceinline__ void mma_k8w(float acc[4][8][4],
                                        const float* As, const float* Bs,
                                        int kk, int wy, int wx, int lane) {
    int g = lane >> 2, t4 = lane & 3;
    float a[4][4];
#pragma unroll
    for (int mt = 0; mt < 4; mt++) {
        int rm = wy * 64 + mt * 16 + g;
        a[mt][0] = As[(kk + t4) * PA + rm];
        a[mt][1] = As[(kk + t4) * PA + rm + 8];
        a[mt][2] = As[(kk + t4 + 4) * PA + rm];
        a[mt][3] = As[(kk + t4 + 4) * PA + rm + 8];
    }
#pragma unroll
    for (int nt = 0; nt < 8; nt++) {
        int cn = wx * 64 + nt * 8 + g;
        float b0 = Bs[(kk + t4) * BS + cn];
        float b1 = Bs[(kk + t4 + 4) * BS + cn];
#pragma unroll
        for (int mt = 0; mt < 4; mt++)
            mma1(acc[mt][nt], a[mt][0], a[mt][1], a[mt][2], a[mt][3], b0, b1);
    }
}

// paired-fragment warp 64x64
__device__ __forceinline__ void mma_k8p64(float acc[4][8][4],
                                          const float* As, const float* Bs,
                                          int kk, int wx, int lane) {
    int g = lane >> 2, t4 = lane & 3;
    int ks = (kk >> 3) * 4 + t4;
    float2 a01[4], a23[4];
#pragma unroll
    for (int mt = 0; mt < 4; mt++) {
        a01[mt] = *(const float2*)&As[(kk + t4) * A64P + (mt * 8 + g) * 2];
        a23[mt] = *(const float2*)&As[(kk + t4 + 4) * A64P + (mt * 8 + g) * 2];
    }
#pragma unroll
    for (int nt = 0; nt < 8; nt++) {
        int cn = wx * 64 + nt * 8 + g;
        float2 b = *(const float2*)&Bs[ks * B256P + cn * 2];
#pragma unroll
        for (int mt = 0; mt < 4; mt++)
            mma1(acc[mt][nt], a01[mt].x, a01[mt].y, a23[mt].x, a23[mt].y, b.x, b.y);
    }
}

// ---- loaders / storers ----
__device__ __forceinline__ void load_w256h(float v[32], const float* __restrict__ W,
                                           int ldw, int k0, int tid) {
    const float* p = &W[(size_t)k0 * ldw + tid];
#pragma unroll
    for (int k = 0; k < 16; k++) {
        v[k] = p[(size_t)k * ldw];
        v[16 + k] = p[(size_t)k * ldw + 128];
    }
}
__device__ __forceinline__ void store_w256p(float* Bs, const float v[32], int tid) {
#pragma unroll
    for (int s8 = 0; s8 < 2; s8++)
#pragma unroll
        for (int t4 = 0; t4 < 4; t4++) {
            int slot = s8 * 4 + t4;
            *(float2*)&Bs[slot * B256P + tid * 2] =
                make_float2(totf(v[s8 * 8 + t4]), totf(v[s8 * 8 + t4 + 4]));
            *(float2*)&Bs[slot * B256P + (tid + 128) * 2] =
                make_float2(totf(v[16 + s8 * 8 + t4]), totf(v[16 + s8 * 8 + t4 + 4]));
        }
}
__device__ __forceinline__ void load_w128(float v[16], const float* __restrict__ W,
                                          int ldw, int k0, int n0, int tid) {
    const float* p = &W[(size_t)k0 * ldw + n0 + tid];
#pragma unroll
    for (int k = 0; k < 16; k++) v[k] = p[(size_t)k * ldw];
}
__device__ __forceinline__ void store_w128p(float* Bs, const float v[16], int tid) {
#pragma unroll
    for (int s8 = 0; s8 < 2; s8++)
#pragma unroll
        for (int t4 = 0; t4 < 4; t4++)
            *(float2*)&Bs[(s8 * 4 + t4) * B128P + tid * 2] =
                make_float2(totf(v[s8 * 8 + t4]), totf(v[s8 * 8 + t4 + 4]));
}
__device__ __forceinline__ void store_w128(float* Bs, const float v[16], int tid) {
#pragma unroll
    for (int k = 0; k < 16; k++) Bs[k * PB1 + tid] = totf(v[k]);
}
__device__ __forceinline__ void store_a8p(float* As, int kh, int r, const float v[8]) {
    int rpos = ((r >> 4) * 8 + (r & 7)) * 2 + ((r >> 3) & 1);
#pragma unroll
    for (int i = 0; i < 8; i++) As[(kh + i) * A64P + rpos] = totf(v[i]);
}
__device__ __forceinline__ void store_a16(float* As, int r, const float v[16]) {
#pragma unroll
    for (int k = 0; k < 16; k++) As[k * PA + r] = totf(v[k]);
}
// load 8 halves -> 8 floats (one 16B load)
__device__ __forceinline__ void ldh8(float v[8], const __half* p) {
    float4 raw = *(const float4*)p;
    const __half2* h2 = (const __half2*)&raw;
#pragma unroll
    for (int i = 0; i < 4; i++) {
        float2 f = __half22float2(h2[i]);
        v[2 * i] = f.x; v[2 * i + 1] = f.y;
    }
}

// ---------------- temb (comb fused) -----------------------------------------
__global__ void __launch_bounds__(128)
temb_fused(const float* __restrict__ t, const float* __restrict__ fw,
           const float* __restrict__ tW, const float* __restrict__ tb,
           const float* __restrict__ d1W, const float* __restrict__ d1b) {
    __shared__ float d1S[H], combS[H + 1], red[128];
    int tid = threadIdx.x, lane = tid & 31, warp = tid >> 5;
    d1S[tid] = d1W[tid]; d1S[tid + 128] = d1W[tid + 128];
    __syncthreads();
    for (int row = warp; row < H + 1; row += 4) {
        const float* p = (row < H) ? &tW[(size_t)row * H] : tb;
        float s = 0.f;
        for (int k = lane; k < H; k += 32) s += p[k] * d1S[k];
#pragma unroll
        for (int o = 16; o; o >>= 1) s += __shfl_down_sync(0xffffffffu, s, o);
        if (lane == 0) combS[row] = (row == H) ? s + d1b[0] : s;
    }
    __syncthreads();
    int g = blockIdx.x;
    float tt = t[g];
    float xp = tt * fw[tid] * 6.283185307179586f;
    red[tid] = sinf(xp) * combS[tid] + cosf(xp) * combS[128 + tid];
    __syncthreads();
    for (int s = 64; s > 0; s >>= 1) {
        if (tid < s) red[tid] += red[tid + s];
        __syncthreads();
    }
    if (tid == 0) {
        g_temb[g] = red[0] + combS[H];
        const float LS = 3.2188758248682006f;   // ln(25)
        float var = (expf(2.f * tt * LS) - 1.f) / (2.f * LS);
        g_invstd[g] = rsqrtf(var);
    }
}

// ---------------- sort machinery ---------------------------------------------
__global__ void __launch_bounds__(256) hist(const int* __restrict__ dst) {
    int e = blockIdx.x * blockDim.x + threadIdx.x;
    if (e < EN) atomicAdd(&g_cnt[dst[e]], 1);
}

__global__ void __launch_bounds__(1024) scan_kernel() {
    __shared__ int part[1024];
    const int CH = 49;
    int t = threadIdx.x;
    int beg = t * CH, end = min(beg + CH, NN);
    int s = 0;
    for (int i = beg; i < end; i++) s += g_cnt[i];
    part[t] = s;
    __syncthreads();
    for (int off = 1; off < 1024; off <<= 1) {
        int v = (t >= off) ? part[t - off] : 0;
        __syncthreads();
        part[t] += v;
        __syncthreads();
    }
    int run = (t == 0) ? 0 : part[t - 1];
    for (int i = beg; i < end; i++) {
        g_rp[i] = run; g_woff[i] = run; run += g_cnt[i];
        g_cnt[i] = 0;
    }
    if (t == 1023) g_rp[NN] = part[1023];
}

__global__ void __launch_bounds__(256) place(const int* __restrict__ src,
                                             const int* __restrict__ dst) {
    int e = blockIdx.x * blockDim.x + threadIdx.x;
    if (e >= EN) return;
    int p = atomicAdd(&g_woff[dst[e]], 1);
    g_pos[e] = p;
    g_srcp[p] = src[e];
}

__global__ void __launch_bounds__(256) init_h(const int* __restrict__ nt,
                                              const float* __restrict__ atom_emb) {
    int idx = blockIdx.x * blockDim.x + threadIdx.x;
    if (idx >= NN * 64) return;
    int n = idx >> 6, q = idx & 63;
    ((float4*)g_h)[idx] = ((const float4*)atom_emb)[nt[n] * 64 + q];
}

// ---------------- gather: aggr[n] = h[n] + sum relu(h[src]+bond), fp16 out --
__global__ void __launch_bounds__(256) gather() {
    int warp = threadIdx.x >> 5, lane = threadIdx.x & 31;
    int n = blockIdx.x * 8 + warp;
    if (n >= NN) return;
    int q = lane * 8;
    float a[8] = {};
    int beg = g_rp[n], end = g_rp[n + 1];
    int p = beg;
    for (; p + 1 < end; p += 2) {
        int s0 = g_srcp[p], s1 = g_srcp[p + 1];
        const float4* hp0 = (const float4*)&g_h[s0 * H + q];
        const float4* hp1 = (const float4*)&g_h[s1 * H + q];
        float bv0[8], bv1[8];
        ldh8(bv0, &g_bond[(size_t)p * H + q]);
        ldh8(bv1, &g_bond[(size_t)(p + 1) * H + q]);
        float4 h00 = hp0[0], h01 = hp0[1];
        float4 h10 = hp1[0], h11 = hp1[1];
        a[0] += fmaxf(h00.x + bv0[0], 0.f) + fmaxf(h10.x + bv1[0], 0.f);
        a[1] += fmaxf(h00.y + bv0[1], 0.f) + fmaxf(h10.y + bv1[1], 0.f);
        a[2] += fmaxf(h00.z + bv0[2], 0.f) + fmaxf(h10.z + bv1[2], 0.f);
        a[3] += fmaxf(h00.w + bv0[3], 0.f) + fmaxf(h10.w + bv1[3], 0.f);
        a[4] += fmaxf(h01.x + bv0[4], 0.f) + fmaxf(h11.x + bv1[4], 0.f);
        a[5] += fmaxf(h01.y + bv0[5], 0.f) + fmaxf(h11.y + bv1[5], 0.f);
        a[6] += fmaxf(h01.z + bv0[6], 0.f) + fmaxf(h11.z + bv1[6], 0.f);
        a[7] += fmaxf(h01.w + bv0[7], 0.f) + fmaxf(h11.w + bv1[7], 0.f);
    }
    if (p < end) {
        int s0 = g_srcp[p];
        const float4* hp0 = (const float4*)&g_h[s0 * H + q];
        float bv0[8];
        ldh8(bv0, &g_bond[(size_t)p * H + q]);
        float4 h00 = hp0[0], h01 = hp0[1];
        a[0] += fmaxf(h00.x + bv0[0], 0.f);
        a[1] += fmaxf(h00.y + bv0[1], 0.f);
        a[2] += fmaxf(h00.z + bv0[2], 0.f);
        a[3] += fmaxf(h00.w + bv0[3], 0.f);
        a[4] += fmaxf(h01.x + bv0[4], 0.f);
        a[5] += fmaxf(h01.y + bv0[5], 0.f);
        a[6] += fmaxf(h01.z + bv0[6], 0.f);
        a[7] += fmaxf(h01.w + bv0[7], 0.f);
    }
    const float4* hn = (const float4*)&g_h[n * H + q];
    float4 n0v = hn[0], n1v = hn[1];
    a[0] += n0v.x; a[1] += n0v.y; a[2] += n0v.z; a[3] += n0v.w;
    a[4] += n1v.x; a[5] += n1v.y; a[6] += n1v.z; a[7] += n1v.w;
    __half2 hv[4];
#pragma unroll
    for (int i = 0; i < 4; i++) hv[i] = __floats2half2_rn(a[2 * i], a[2 * i + 1]);
    *(float4*)&g_aggr[n * H + q] = *(float4*)hv;
}

// ---------------- edge_bond: reg-A + paired B, writes SORTED fp16 rows ------
#define EB_SMEM ((2 * B128SZ + 128 + 128 + 128 + 128 + 2 * H) * 4)

__global__ void __launch_bounds__(128, 2)
edge_bond(const float* __restrict__ elen, const int* __restrict__ src,
          const int* __restrict__ batch, const int* __restrict__ etype,
          const float* __restrict__ W1, const float* __restrict__ b1,
          const float* __restrict__ W2, const float* __restrict__ b2,
          const float* __restrict__ bond_emb) {
    extern __shared__ float sm[];
    float* Bs = sm;                       // 2*B128SZ
    float* xS = Bs + 2 * B128SZ;
    float* tS = xS + 128;
    int*   eS = (int*)(tS + 128);
    int*   pS = eS + 128;
    float* w1S = (float*)(pS + 128);
    float* b1S = w1S + H;

    int tid = threadIdx.x, lane = tid & 31, warp = tid >> 5;
    int wy = warp >> 1, wx = warp & 1;
    int g = lane >> 2, t4 = lane & 3;
    int m0 = blockIdx.y * 128, n0 = blockIdx.x * 128;

    {
        int e = m0 + tid;
        float x = 0.f, tb = 0.f; int et = 0, ps = 0;
        if (e < EN) {
            x = elen[e];
            int gph = batch[src[e]];
            tb = g_temb[gph];
            if (n0 == 0) g_einv[e] = g_invstd[gph];
            et = etype[e];
            ps = g_pos[e];
        }
        xS[tid] = x; tS[tid] = tb; eS[tid] = et; pS[tid] = ps;
    }
    w1S[tid] = W1[tid];         w1S[tid + 128] = W1[tid + 128];
    b1S[tid] = b1[tid];         b1S[tid + 128] = b1[tid + 128];
    __syncthreads();

    float xr[4][2];
#pragma unroll
    for (int mt = 0; mt < 4; mt++) {
        xr[mt][0] = xS[wy * 64 + mt * 16 + g];
        xr[mt][1] = xS[wy * 64 + mt * 16 + g + 8];
    }

    float breg[16];
    load_w128(breg, W2, H, 0, n0, tid);
    store_w128p(Bs, breg, tid);
    __syncthreads();

    float acc[4][8][4] = {};
    for (int s = 0; s < 16; s++) {
        int cur = s & 1, nxt = cur ^ 1;
        if (s < 15) load_w128(breg, W2, H, (s + 1) * 16, n0, tid);
        const float* B = Bs + cur * B128SZ;
#pragma unroll
        for (int kh = 0; kh < 16; kh += 8) {
            int kA = s * 16 + kh;
            float w0 = w1S[kA + t4], w4 = w1S[kA + t4 + 4];
            float c0 = b1S[kA + t4], c4 = b1S[kA + t4 + 4];
            float a[4][4];
#pragma unroll
            for (int mt = 0; mt < 4; mt++) {
                a[mt][0] = totf(fmaxf(fmaf(xr[mt][0], w0, c0), 0.f));
                a[mt][1] = totf(fmaxf(fmaf(xr[mt][1], w0, c0), 0.f));
                a[mt][2] = totf(fmaxf(fmaf(xr[mt][0], w4, c4), 0.f));
                a[mt][3] = totf(fmaxf(fmaf(xr[mt][1], w4, c4), 0.f));
            }
            int ks = (kh >> 3) * 4 + t4;
#pragma unroll
            for (int nt = 0; nt < 8; nt++) {
                int cn = wx * 64 + nt * 8 + g;
                float2 b = *(const float2*)&B[ks * B128P + cn * 2];
#pragma unroll
                for (int mt = 0; mt < 4; mt++)
                    mma1(acc[mt][nt], a[mt][0], a[mt][1], a[mt][2], a[mt][3], b.x, b.y);
            }
        }
        if (s < 15) {
            store_w128p(Bs + nxt * B128SZ, breg, tid);
            __syncthreads();
        }
    }

#pragma unroll
    for (int mt = 0; mt < 4; mt++)
#pragma unroll
        for (int half = 0; half < 2; half++) {
            int rl = wy * 64 + mt * 16 + g + half * 8;
            int row = m0 + rl;
            if (row >= EN) continue;
            float tb = tS[rl];
            const float* bep = &bond_emb[eS[rl] * H];
            size_t obase = (size_t)pS[rl] * H;
#pragma unroll
            for (int nt = 0; nt < 8; nt++) {
                int col = n0 + wx * 64 + nt * 8 + 2 * t4;
                float v0 = (acc[mt][nt][half * 2 + 0] + b2[col] + tb) * bep[col];
                float v1 = (acc[mt][nt][half * 2 + 1] + b2[col + 1] + tb) * bep[col + 1];
                *(__half2*)&g_bond[obase + col] = __floats2half2_rn(v0, v1);
            }
        }
}

// ---------------- GIN GEMMs: 64x256 paired; fp16 A --------------------------
#define GIN_SMEM ((2 * A64SZ + 2 * B256SZ) * 4)
template <int MODE>
__global__ void __launch_bounds__(128, 2)
gin_mma(const float* __restrict__ W, const float* __restrict__ bias, int reluOut) {
    extern __shared__ float sm[];
    float* As = sm;
    float* Bs = sm + 2 * A64SZ;
    int tid = threadIdx.x, lane = tid & 31, warp = tid >> 5;
    int wx = warp;
    int m0 = blockIdx.x * 64;
    int r = tid & 63, kh = (tid >> 6) * 8;
    int arow = m0 + r;
    bool valid = (arow < NN);
    const __half* A1 = (MODE == 0) ? g_aggr : g_tmp;

    float areg[8], breg[32];
    auto loadA = [&](int k0) {
        if (valid) {
            ldh8(areg, &A1[arow * H + k0 + kh]);
        } else {
#pragma unroll
            for (int i = 0; i < 8; i++) areg[i] = 0.f;
        }
    };

    loadA(0);
    load_w256h(breg, W, H, 0, tid);
    store_a8p(As, kh, r, areg);
    store_w256p(Bs, breg, tid);
    __syncthreads();

    float acc[4][8][4] = {};
    for (int s = 0; s < 16; s++) {
        int cur = s & 1, nxt = cur ^ 1;
        if (s < 15) { loadA((s + 1) * 16); load_w256h(breg, W, H, (s + 1) * 16, tid); }
        mma_k8p64(acc, As + cur * A64SZ, Bs + cur * B256SZ, 0, wx, lane);
        mma_k8p64(acc, As + cur * A64SZ, Bs + cur * B256SZ, 8, wx, lane);
        if (s < 15) {
            store_a8p(As + nxt * A64SZ, kh, r, areg);
            store_w256p(Bs + nxt * B256SZ, breg, tid);
            __syncthreads();
        }
    }

    int g = lane >> 2, t4 = lane & 3;
#pragma unroll
    for (int mt = 0; mt < 4; mt++)
#pragma unroll
        for (int half = 0; half < 2; half++) {
            int row = m0 + mt * 16 + g + half * 8;
            if (row >= NN) continue;
#pragma unroll
            for (int nt = 0; nt < 8; nt++) {
                int col = wx * 64 + nt * 8 + 2 * t4;
                float v0 = acc[mt][nt][half * 2 + 0] + bias[col];
                float v1 = acc[mt][nt][half * 2 + 1] + bias[col + 1];
                if (reluOut) { v0 = fmaxf(v0, 0.f); v1 = fmaxf(v1, 0.f); }
                if (MODE == 0) {
                    *(__half2*)&g_tmp[row * H + col] = __floats2half2_rn(v0, v1);
                } else {
                    float2 rh = *(const float2*)&g_h[row * H + col];
                    *(float2*)&g_h[row * H + col] = make_float2(v0 + rh.x, v1 + rh.y);
                }
            }
        }
}

// ---------------- out1: K=512, 64x256 paired; fp16 bond/h1 ------------------
#define OUT1_SMEM ((2 * A64SZ + 2 * B256SZ + 192) * 4)
__global__ void __launch_bounds__(128, 2)
out1(const int* __restrict__ src, const int* __restrict__ dst,
     const float* __restrict__ W1, const float* __restrict__ b1) {
    extern __shared__ float sm[];
    float* As = sm;
    float* Bs = sm + 2 * A64SZ;
    int* srcS = (int*)(Bs + 2 * B256SZ);  // 64
    int* dstS = srcS + 64;                // 64
    int* pS   = dstS + 64;                // 64
    int tid = threadIdx.x, lane = tid & 31, warp = tid >> 5;
    int wx = warp;
    int m0 = blockIdx.x * 64;

    if (tid < 64) {
        int e = m0 + tid;
        int s = 0, d = 0, ps = 0;
        if (e < EN) { s = src[e]; d = dst[e]; ps = g_pos[e]; }
        srcS[tid] = s; dstS[tid] = d; pS[tid] = ps;
    }
    __syncthreads();

    int r = tid & 63, kh = (tid >> 6) * 8;
    int e = m0 + r;
    bool valid = (e < EN);
    float areg[8], breg[32];

    auto loadA = [&](int k0) {
        if (k0 < 256) {
            const float* hs = &g_h[srcS[r] * H + k0 + kh];
            const float* hd = &g_h[dstS[r] * H + k0 + kh];
            float4 a0 = *(const float4*)hs, a1 = *(const float4*)(hs + 4);
            float4 c0 = *(const float4*)hd, c1 = *(const float4*)(hd + 4);
            areg[0] = a0.x * c0.x; areg[1] = a0.y * c0.y;
            areg[2] = a0.z * c0.z; areg[3] = a0.w * c0.w;
            areg[4] = a1.x * c1.x; areg[5] = a1.y * c1.y;
            areg[6] = a1.z * c1.z; areg[7] = a1.w * c1.w;
        } else if (valid) {
            ldh8(areg, &g_bond[(size_t)pS[r] * H + (k0 - 256) + kh]);
        } else {
#pragma unroll
            for (int i = 0; i < 8; i++) areg[i] = 0.f;
        }
    };

    loadA(0);
    load_w256h(breg, W1, H, 0, tid);
    store_a8p(As, kh, r, areg);
    store_w256p(Bs, breg, tid);
    __syncthreads();

    float acc[4][8][4] = {};
    for (int s = 0; s < 32; s++) {
        int cur = s & 1, nxt = cur ^ 1;
        if (s < 31) { loadA((s + 1) * 16); load_w256h(breg, W1, H, (s + 1) * 16, tid); }
        mma_k8p64(acc, As + cur * A64SZ, Bs + cur * B256SZ, 0, wx, lane);
        mma_k8p64(acc, As + cur * A64SZ, Bs + cur * B256SZ, 8, wx, lane);
        if (s < 31) {
            store_a8p(As + nxt * A64SZ, kh, r, areg);
            store_w256p(Bs + nxt * B256SZ, breg, tid);
            __syncthreads();
        }
    }

    int g = lane >> 2, t4 = lane & 3;
#pragma unroll
    for (int mt = 0; mt < 4; mt++)
#pragma unroll
        for (int half = 0; half < 2; half++) {
            int row = m0 + mt * 16 + g + half * 8;
            if (row >= EN) continue;
#pragma unroll
            for (int nt = 0; nt < 8; nt++) {
                int col = wx * 64 + nt * 8 + 2 * t4;
                float v0 = fmaxf(acc[mt][nt][half * 2 + 0] + b1[col], 0.f);
                float v1 = fmaxf(acc[mt][nt][half * 2 + 1] + b1[col + 1], 0.f);
                *(__half2*)&g_h1[(size_t)row * H + col] = __floats2half2_rn(v0, v1);
            }
        }
}

// ---------------- out23 fused: fp16 h1 in ------------------------------------
__global__ void __launch_bounds__(128, 2)
out23(const float* __restrict__ W2, const float* __restrict__ b2,
      const float* __restrict__ W3, const float* __restrict__ b3,
      float* __restrict__ out) {
    __shared__ float As[2 * ASZ], Bs[2 * BSZ1];
    __shared__ float red[128 * 8];
    __shared__ float b2S[128], w3S[128];
    int tid = threadIdx.x, lane = tid & 31, warp = tid >> 5;
    int wy = warp >> 1, wx = warp & 1;
    int m0 = blockIdx.x * 128;

    b2S[tid] = b2[tid]; w3S[tid] = W3[tid];

    int e = m0 + tid;
    bool valid = (e < EN);
    float areg[16], breg[16];
    auto loadA = [&](int k0) {
        if (valid) {
            const __half* p = &g_h1[(size_t)e * H + k0];
            ldh8(areg, p);
            ldh8(areg + 8, p + 8);
        } else {
#pragma unroll
            for (int i = 0; i < 16; i++) areg[i] = 0.f;
        }
    };

    loadA(0);
    load_w128(breg, W2, 128, 0, 0, tid);
    store_a16(As, tid, areg);
    store_w128(Bs, breg, tid);
    __syncthreads();

    float acc[4][8][4] = {};
    for (int s = 0; s < 16; s++) {
        int cur = s & 1, nxt = cur ^ 1;
        if (s < 15) { loadA((s + 1) * 16); load_w128(breg, W2, 128, (s + 1) * 16, 0, tid); }
        mma_k8w<PB1>(acc, As + cur * ASZ, Bs + cur * BSZ1, 0, wy, wx, lane);
        mma_k8w<PB1>(acc, As + cur * ASZ, Bs + cur * BSZ1, 8, wy, wx, lane);
        if (s < 15) {
            store_a16(As + nxt * ASZ, tid, areg);
            store_w128(Bs + nxt * BSZ1, breg, tid);
            __syncthreads();
        }
    }

    int g = lane >> 2, t4 = lane & 3;
#pragma unroll
    for (int mt = 0; mt < 4; mt++)
#pragma unroll
        for (int half = 0; half < 2; half++) {
            int rl = wy * 64 + mt * 16 + g + half * 8;
            float partial = 0.f;
#pragma unroll
            for (int nt = 0; nt < 8; nt++) {
                int col = wx * 64 + nt * 8 + 2 * t4;
                float h0 = fmaxf(acc[mt][nt][half * 2 + 0] + b2S[col], 0.f);
                float h1 = fmaxf(acc[mt][nt][half * 2 + 1] + b2S[col + 1], 0.f);
                partial += h0 * w3S[col] + h1 * w3S[col + 1];
            }
            red[rl * 8 + wx * 4 + t4] = partial;
        }
    __syncthreads();

    if (valid) {
        float s = 0.f;
#pragma unroll
        for (int i = 0; i < 8; i++) s += red[tid * 8 + i];
        out[e] = (s + b3[0]) * g_einv[e];
    }
}

// ---------------- launch ----------------------------------------------------
extern "C" void kernel_launch(void* const* d_in, const int* in_sizes, int n_in,
                              void* d_out, int out_size) {
    const int*   node_type = (const int*)d_in[0];
    const int*   edge_type = (const int*)d_in[1];
    const int*   edge_index = (const int*)d_in[2];
    const int*   batch = (const int*)d_in[3];
    const float* elen = (const float*)d_in[4];
    const float* t = (const float*)d_in[5];
    const float* atom_emb = (const float*)d_in[6];
    const float* bond_emb = (const float*)d_in[7];
    const float* in_W1 = (const float*)d_in[8];
    const float* in_b1 = (const float*)d_in[9];
    const float* in_W2 = (const float*)d_in[10];
    const float* in_b2 = (const float*)d_in[11];
    const float* fourier_W = (const float*)d_in[12];
    const float* temb_W = (const float*)d_in[13];
    const float* temb_b = (const float*)d_in[14];
    const float* d1W = (const float*)d_in[15];
    const float* d1b = (const float*)d_in[16];
    const float* gin_W1 = (const float*)d_in[17];
    const float* gin_b1 = (const float*)d_in[18];
    const float* gin_W2 = (const float*)d_in[19];
    const float* gin_b2 = (const float*)d_in[20];
    const float* out_W1 = (const float*)d_in[21];
    const float* out_b1 = (const float*)d_in[22];
    const float* out_W2 = (const float*)d_in[23];
    const float* out_b2 = (const float*)d_in[24];
    const float* out_W3 = (const float*)d_in[25];
    const float* out_b3 = (const float*)d_in[26];
    const int* src = edge_index;
    const int* dst = edge_index + EN;
    float* out = (float*)d_out;

    const int EB = (EN + 127) / 128;      // 2344
    const int EB64 = (EN + 63) / 64;      // 4688
    const int NB64 = (NN + 63) / 64;      // 782

    static int attr_done = 0;
    if (!attr_done) {
        cudaFuncSetAttribute(edge_bond, cudaFuncAttributeMaxDynamicSharedMemorySize, EB_SMEM);
        cudaFuncSetAttribute(gin_mma<0>, cudaFuncAttributeMaxDynamicSharedMemorySize, GIN_SMEM);
        cudaFuncSetAttribute(gin_mma<1>, cudaFuncAttributeMaxDynamicSharedMemorySize, GIN_SMEM);
        cudaFuncSetAttribute(out1, cudaFuncAttributeMaxDynamicSharedMemorySize, OUT1_SMEM);
        attr_done = 1;
    }

    temb_fused<<<GN, 128>>>(t, fourier_W, temb_W, temb_b, d1W, d1b);      // 0
    hist<<<(EN + 255) / 256, 256>>>(dst);                                 // 1
    scan_kernel<<<1, 1024>>>();                                           // 2
    place<<<(EN + 255) / 256, 256>>>(src, dst);                           // 3
    edge_bond<<<dim3(2, EB), 128, EB_SMEM>>>(elen, src, batch, edge_type, // 4
                                             in_W1, in_b1, in_W2, in_b2, bond_emb);
    init_h<<<(NN * 64 + 255) / 256, 256>>>(node_type, atom_emb);          // 5

    for (int c = 0; c < NCONV; c++) {
        gather<<<(NN + 7) / 8, 256>>>();
        gin_mma<0><<<NB64, 128, GIN_SMEM>>>(gin_W1 + c * H * H, gin_b1 + c * H, 1);
        gin_mma<1><<<NB64, 128, GIN_SMEM>>>(gin_W2 + c * H * H, gin_b2 + c * H,
                                            (c < NCONV - 1) ? 1 : 0);
    }

    out1<<<EB64, 128, OUT1_SMEM>>>(src, dst, out_W1, out_b1);
    out23<<<EB, 128>>>(out_W2, out_b2, out_W3, out_b3, out);
}